// round 11
// baseline (speedup 1.0000x reference)
#include <cuda_runtime.h>
#include <cuda_fp16.h>
#include <math.h>

#define N_ATOMS 10000
#define N_EDGES 150000
#define NB 128
#define NI 3
#define NF (NI * 3 * NB)     // 1152 filter cols
#define N_RBF 20
#define CUTOFF 5.0f
#define EPSV 1e-8f
#define BATCH 64
#define EB 32                // edges per filter-precompute block
#define TX 16                // atoms per block, k_atoms_x
#define PX 20                // padded row for TX
#define TU 8                 // atoms per block, k_atoms_update
#define PU 12                // padded row for TU
#define TH 8                 // atoms per block, k_head

typedef unsigned long long u64;

// ---------------- device scratch (static, no allocation) ----------------
__device__ float  g_q   [N_ATOMS * NB];
__device__ __align__(16) float g_mu [N_ATOMS * 3 * NB];
__device__ __align__(16) float g_x  [N_ATOMS * 3 * NB];
__device__ float  g_dq  [N_ATOMS * NB];
__device__ float  g_dmu [N_ATOMS * 3 * NB];
__device__ float  g_phif[N_EDGES * N_RBF];
__device__ float  g_fc  [N_EDGES];
__device__ float4 g_dir4[N_EDGES];
// filters fp16, layout [it][slot][384] (it-major for contiguous per-iter reads)
__device__ __align__(16) __half g_filt[(size_t)NI * N_EDGES * 384];
// CSR by destination atom (idx_i)
__device__ int    g_cnt [N_ATOMS];
__device__ int    g_ofs [N_ATOMS + 1];
__device__ int    g_cur [N_ATOMS];
__device__ int    g_slot[N_EDGES];
__device__ int    g_pj  [N_EDGES];
__device__ float4 g_pdir[N_EDGES];

// ---------------- packed f32x2 helpers (FFMA2 path, sm_103a) ----------------
__device__ __forceinline__ u64 pk2(float lo, float hi) {
    u64 r; asm("mov.b64 %0, {%1, %2};" : "=l"(r) : "f"(lo), "f"(hi)); return r;
}
__device__ __forceinline__ float2 upk2(u64 v) {
    float2 f; asm("mov.b64 {%0, %1}, %2;" : "=f"(f.x), "=f"(f.y) : "l"(v)); return f;
}
__device__ __forceinline__ u64 fma2v(u64 a, u64 b, u64 c) {
    u64 d; asm("fma.rn.f32x2 %0, %1, %2, %3;" : "=l"(d) : "l"(a), "l"(b), "l"(c)); return d;
}
__device__ __forceinline__ u64 mul2v(u64 a, u64 b) {
    u64 d; asm("mul.rn.f32x2 %0, %1, %2;" : "=l"(d) : "l"(a), "l"(b)); return d;
}
// half2 (as uint) -> packed f32x2
__device__ __forceinline__ u64 h2f2(unsigned h) {
    float2 f = __half22float2(*reinterpret_cast<__half2*>(&h));
    return pk2(f.x, f.y);
}

__device__ __forceinline__ float silu_f(float v) {
    return v / (1.0f + expf(-v));
}

// ---------------- edge geometry precompute ----------------
__global__ void k_init_edges(const float* __restrict__ pos,
                             const int* __restrict__ idx_i,
                             const int* __restrict__ idx_j) {
    int e = blockIdx.x * blockDim.x + threadIdx.x;
    if (e >= N_EDGES) return;
    int i = idx_i[e], j = idx_j[e];
    float rx = pos[j * 3 + 0] - pos[i * 3 + 0];
    float ry = pos[j * 3 + 1] - pos[i * 3 + 1];
    float rz = pos[j * 3 + 2] - pos[i * 3 + 2];
    float d  = sqrtf(rx * rx + ry * ry + rz * rz);
    float inv = 1.0f / d;
    g_dir4[e] = make_float4(rx * inv, ry * inv, rz * inv, 0.0f);
    float fc = (d < CUTOFF) ? 0.5f * (cosf(d * (float)M_PI / CUTOFF) + 1.0f) : 0.0f;
    g_fc[e] = fc;
    const float width = CUTOFF / (float)(N_RBF - 1);
    const float coeff = -0.5f / (width * width);
    #pragma unroll
    for (int r = 0; r < N_RBF; r++) {
        float dd = d - (float)r * width;
        g_phif[e * N_RBF + r] = expf(coeff * dd * dd) * fc;
    }
}

// ---------------- CSR build ----------------
__global__ void k_zero_cnt() {
    int a = blockIdx.x * blockDim.x + threadIdx.x;
    if (a < N_ATOMS) g_cnt[a] = 0;
}
__global__ void k_hist(const int* __restrict__ idx_i) {
    int e = blockIdx.x * blockDim.x + threadIdx.x;
    if (e < N_EDGES) atomicAdd(&g_cnt[idx_i[e]], 1);
}
__global__ void __launch_bounds__(1024) k_scan() {
    __shared__ int partial[1024];
    int t = threadIdx.x;
    int base = t * 10;
    int local[10];
    int s = 0;
    #pragma unroll
    for (int k = 0; k < 10; k++) {
        int idx = base + k;
        int c = (idx < N_ATOMS) ? g_cnt[idx] : 0;
        local[k] = s;
        s += c;
    }
    partial[t] = s;
    __syncthreads();
    for (int off = 1; off < 1024; off <<= 1) {
        int v = partial[t];
        int u = (t >= off) ? partial[t - off] : 0;
        __syncthreads();
        partial[t] = v + u;
        __syncthreads();
    }
    int pre = (t > 0) ? partial[t - 1] : 0;
    #pragma unroll
    for (int k = 0; k < 10; k++) {
        int idx = base + k;
        if (idx < N_ATOMS) {
            int o = pre + local[k];
            g_ofs[idx] = o;
            g_cur[idx] = o;
        }
    }
    if (t == 1023) g_ofs[N_ATOMS] = partial[1023];
}
__global__ void k_fill(const int* __restrict__ idx_i,
                       const int* __restrict__ idx_j) {
    int e = blockIdx.x * blockDim.x + threadIdx.x;
    if (e < N_EDGES) {
        int pos = atomicAdd(&g_cur[idx_i[e]], 1);
        g_slot[e] = pos;
        g_pj[pos] = idx_j[e];
        g_pdir[pos] = g_dir4[e];
    }
}

// ---------------- dense filter precompute into [it][slot][384] (fp16) --------
// EB=32 edges per 128-thread block amortizes the fW L2 reads 4x vs EB=8.
// Grid is ceil(N_EDGES/EB); tail edges are guarded.
__global__ void __launch_bounds__(128) k_filters(const float* __restrict__ fW,
                                                 const float* __restrict__ fb) {
    __shared__ __align__(16) float ps[N_RBF][EB];   // [r][edge]
    __shared__ float fcs[EB];
    __shared__ int   slots[EB];
    int e0 = blockIdx.x * EB;
    int t  = threadIdx.x;
    for (int idx = t; idx < EB * N_RBF; idx += 128) {
        int a = idx / N_RBF, r = idx % N_RBF;
        int e = e0 + a;
        ps[r][a] = (e < N_EDGES) ? g_phif[(size_t)e * N_RBF + r] : 0.0f;
    }
    for (int idx = t; idx < EB; idx += 128) {
        int e = e0 + idx;
        fcs[idx]   = (e < N_EDGES) ? g_fc[e] : 0.0f;
        slots[idx] = (e < N_EDGES) ? g_slot[e] : 0;
    }
    __syncthreads();

    int nval = N_EDGES - e0;            // edges valid in this block
    if (nval > EB) nval = EB;

    #pragma unroll 1
    for (int grp = 0; grp < NF / 128; grp++) {
        int c = grp * 128 + t;            // column in [0, 1152)
        int it = grp / 3;                 // iteration this column belongs to
        int cit = (grp % 3) * 128 + t;    // column within iteration [0, 384)
        float wc[N_RBF];
        #pragma unroll
        for (int r = 0; r < N_RBF; r++) wc[r] = fW[r * NF + c];
        float bias = fb[c];
        u64 bp = pk2(bias, bias);
        u64 acc[EB / 2];
        #pragma unroll
        for (int p = 0; p < EB / 2; p++)
            acc[p] = mul2v(pk2(fcs[2 * p], fcs[2 * p + 1]), bp);
        #pragma unroll
        for (int r = 0; r < N_RBF; r++) {
            u64 wp = pk2(wc[r], wc[r]);
            const u64* pr = (const u64*)&ps[r][0];
            #pragma unroll
            for (int p = 0; p < EB / 2; p++) acc[p] = fma2v(pr[p], wp, acc[p]);
        }
        size_t itbase = (size_t)it * N_EDGES * 384;
        #pragma unroll
        for (int p = 0; p < EB / 2; p++) {
            float2 f = upk2(acc[p]);
            if (2 * p < nval)
                g_filt[itbase + (size_t)slots[2 * p] * 384 + cit]     = __float2half_rn(f.x);
            if (2 * p + 1 < nval)
                g_filt[itbase + (size_t)slots[2 * p + 1] * 384 + cit] = __float2half_rn(f.y);
        }
    }
}

// ---------------- atom init ----------------
__global__ void k_init_atoms(const float* __restrict__ emb,
                             const int* __restrict__ z,
                             float* __restrict__ y_out) {
    int a = blockIdx.x;
    int t = threadIdx.x;
    g_q[a * NB + t] = emb[z[a] * NB + t];
    #pragma unroll
    for (int d = 0; d < 3; d++)
        g_mu[a * 3 * NB + d * NB + t] = 0.0f;
    if (a == 0 && t < BATCH) y_out[t] = 0.0f;
}

// ---------------- per-atom input MLP (f32x2 packed atom pairs) ---------------
__global__ void __launch_bounds__(128) k_atoms_x(
        const float* __restrict__ ic1W, const float* __restrict__ ic1b,
        const float* __restrict__ ic2W, const float* __restrict__ ic2b,
        int it) {
    __shared__ __align__(16) float qs[NB][PX];
    __shared__ __align__(16) float hs[NB][PX];
    int t  = threadIdx.x;
    int a0 = blockIdx.x * TX;

    #pragma unroll
    for (int a = 0; a < TX; a++)
        qs[t][a] = g_q[(size_t)(a0 + a) * NB + t];
    __syncthreads();

    const float* W1 = ic1W + (size_t)it * NB * NB;
    float b1 = ic1b[it * NB + t];
    u64 acc[TX / 2];
    u64 b1p = pk2(b1, b1);
    #pragma unroll
    for (int p = 0; p < TX / 2; p++) acc[p] = b1p;
    for (int k = 0; k < NB; k++) {
        float w = W1[k * NB + t];
        u64 wp = pk2(w, w);
        const ulonglong2* q2 = (const ulonglong2*)&qs[k][0];
        #pragma unroll
        for (int p4 = 0; p4 < TX / 4; p4++) {
            ulonglong2 u = q2[p4];
            acc[2 * p4]     = fma2v(u.x, wp, acc[2 * p4]);
            acc[2 * p4 + 1] = fma2v(u.y, wp, acc[2 * p4 + 1]);
        }
    }
    #pragma unroll
    for (int p = 0; p < TX / 2; p++) {
        float2 f = upk2(acc[p]);
        hs[t][2 * p]     = silu_f(f.x);
        hs[t][2 * p + 1] = silu_f(f.y);
    }
    __syncthreads();

    const float* W2 = ic2W + (size_t)it * NB * 3 * NB;
    float b20 = ic2b[it * 3 * NB + t];
    float b21 = ic2b[it * 3 * NB + NB + t];
    float b22 = ic2b[it * 3 * NB + 2 * NB + t];
    u64 c0[TX / 2], c1[TX / 2], c2[TX / 2];
    u64 b20p = pk2(b20, b20), b21p = pk2(b21, b21), b22p = pk2(b22, b22);
    #pragma unroll
    for (int p = 0; p < TX / 2; p++) { c0[p] = b20p; c1[p] = b21p; c2[p] = b22p; }
    for (int k = 0; k < NB; k++) {
        float w0 = W2[k * 384 + t];
        float w1 = W2[k * 384 + NB + t];
        float w2 = W2[k * 384 + 2 * NB + t];
        u64 w0p = pk2(w0, w0), w1p = pk2(w1, w1), w2p = pk2(w2, w2);
        const ulonglong2* h2 = (const ulonglong2*)&hs[k][0];
        #pragma unroll
        for (int p4 = 0; p4 < TX / 4; p4++) {
            ulonglong2 u = h2[p4];
            c0[2 * p4]     = fma2v(u.x, w0p, c0[2 * p4]);
            c0[2 * p4 + 1] = fma2v(u.y, w0p, c0[2 * p4 + 1]);
            c1[2 * p4]     = fma2v(u.x, w1p, c1[2 * p4]);
            c1[2 * p4 + 1] = fma2v(u.y, w1p, c1[2 * p4 + 1]);
            c2[2 * p4]     = fma2v(u.x, w2p, c2[2 * p4]);
            c2[2 * p4 + 1] = fma2v(u.y, w2p, c2[2 * p4 + 1]);
        }
    }
    #pragma unroll
    for (int p = 0; p < TX / 2; p++) {
        float2 f0 = upk2(c0[p]);
        float2 f1 = upk2(c1[p]);
        float2 f2 = upk2(c2[p]);
        size_t ga = (size_t)(a0 + 2 * p) * 384;
        size_t gb = (size_t)(a0 + 2 * p + 1) * 384;
        g_x[ga + t] = f0.x;           g_x[gb + t] = f0.y;
        g_x[ga + NB + t] = f1.x;      g_x[gb + NB + t] = f1.y;
        g_x[ga + 2 * NB + t] = f2.x;  g_x[gb + 2 * NB + t] = f2.y;
    }
}

// ---------------- edge gather: warp per atom (R6 best-measured form) ---------
template <int HAS_MU>
__global__ void __launch_bounds__(256) k_gather(int it) {
    int warp = threadIdx.x >> 5;
    int lane = threadIdx.x & 31;
    int i = blockIdx.x * 8 + warp;
    int beg = g_ofs[i], end = g_ofs[i + 1];

    u64 mq0 = 0, mq1 = 0;
    u64 m0a = 0, m0b = 0, m1a = 0, m1b = 0, m2a = 0, m2b = 0;

    const __half* filt_it = g_filt + (size_t)it * N_EDGES * 384;
    int j = 0; float4 d4 = make_float4(0,0,0,0);
    if (beg < end) { j = __ldg(g_pj + beg); d4 = g_pdir[beg]; }

    for (int k = beg; k < end; k++) {
        int jn = 0; float4 dn = d4;
        if (k + 1 < end) { jn = __ldg(g_pj + k + 1); dn = g_pdir[k + 1]; }

        const uint2* fe = (const uint2*)(filt_it + (size_t)k * 384);
        uint2 f0 = fe[lane];
        uint2 f1 = fe[32 + lane];
        uint2 f2 = fe[64 + lane];
        const ulonglong2* xr = (const ulonglong2*)(g_x + (size_t)j * 384);
        ulonglong2 x0 = xr[lane];
        ulonglong2 x1 = xr[32 + lane];
        ulonglong2 x2 = xr[64 + lane];
        ulonglong2 u0, u1, u2;
        if (HAS_MU) {
            const ulonglong2* mr = (const ulonglong2*)(g_mu + (size_t)j * 384);
            u0 = mr[lane];
            u1 = mr[32 + lane];
            u2 = mr[64 + lane];
        }

        u64 w0x = h2f2(f0.x), w0y = h2f2(f0.y);
        u64 w1x = h2f2(f1.x), w1y = h2f2(f1.y);
        u64 w2x = h2f2(f2.x), w2y = h2f2(f2.y);

        mq0 = fma2v(w0x, x0.x, mq0);
        mq1 = fma2v(w0y, x0.y, mq1);
        u64 vR0 = mul2v(w1x, x1.x), vR1 = mul2v(w1y, x1.y);
        u64 vM0 = mul2v(w2x, x2.x), vM1 = mul2v(w2y, x2.y);
        u64 dxp = pk2(d4.x, d4.x), dyp = pk2(d4.y, d4.y), dzp = pk2(d4.z, d4.z);
        if (HAS_MU) {
            m0a = fma2v(vR0, dxp, fma2v(vM0, u0.x, m0a));
            m0b = fma2v(vR1, dxp, fma2v(vM1, u0.y, m0b));
            m1a = fma2v(vR0, dyp, fma2v(vM0, u1.x, m1a));
            m1b = fma2v(vR1, dyp, fma2v(vM1, u1.y, m1b));
            m2a = fma2v(vR0, dzp, fma2v(vM0, u2.x, m2a));
            m2b = fma2v(vR1, dzp, fma2v(vM1, u2.y, m2b));
        } else {
            m0a = fma2v(vR0, dxp, m0a);
            m0b = fma2v(vR1, dxp, m0b);
            m1a = fma2v(vR0, dyp, m1a);
            m1b = fma2v(vR1, dyp, m1b);
            m2a = fma2v(vR0, dzp, m2a);
            m2b = fma2v(vR1, dzp, m2b);
        }
        j = jn; d4 = dn;
    }
    ulonglong2 o;
    o.x = mq0; o.y = mq1;
    ((ulonglong2*)(g_dq + (size_t)i * NB))[lane] = o;
    ulonglong2* dmu = (ulonglong2*)(g_dmu + (size_t)i * 3 * NB);
    o.x = m0a; o.y = m0b; dmu[lane]      = o;
    o.x = m1a; o.y = m1b; dmu[32 + lane] = o;
    o.x = m2a; o.y = m2b; dmu[64 + lane] = o;
}

// ---------------- per-atom update (f32x2 packed atom pairs) ------------------
__global__ void __launch_bounds__(128) k_atoms_update(
        const float* __restrict__ mixW,
        const float* __restrict__ c1W, const float* __restrict__ c1b,
        const float* __restrict__ c2W, const float* __restrict__ c2b,
        int it, int last, float* __restrict__ mu_out) {
    __shared__ __align__(16) float mus[NB][3][PU];     // [k][d][a]
    __shared__ __align__(16) float ctxs[2 * NB][PU];   // [k][a]
    __shared__ __align__(16) float hs[NB][PU];         // [k][a]
    int t  = threadIdx.x;
    int a0 = blockIdx.x * TU;

    float qreg[TU];
    #pragma unroll
    for (int a = 0; a < TU; a++) {
        size_t g = (size_t)(a0 + a);
        qreg[a] = g_q[g * NB + t] + g_dq[g * NB + t];
        ctxs[t][a] = qreg[a];
        #pragma unroll
        for (int d = 0; d < 3; d++)
            mus[t][d][a] = g_mu[g * 3 * NB + d * NB + t] + g_dmu[g * 3 * NB + d * NB + t];
    }
    __syncthreads();

    const float* MW = mixW + (size_t)it * NB * 2 * NB;
    u64 v2[TU / 2][3], w2[TU / 2][3];
    #pragma unroll
    for (int p = 0; p < TU / 2; p++)
        #pragma unroll
        for (int d = 0; d < 3; d++) { v2[p][d] = 0; w2[p][d] = 0; }
    for (int k = 0; k < NB; k++) {
        float wv = MW[k * 256 + t];
        float ww = MW[k * 256 + NB + t];
        u64 wvp = pk2(wv, wv), wwp = pk2(ww, ww);
        #pragma unroll
        for (int d = 0; d < 3; d++) {
            const ulonglong2* m2 = (const ulonglong2*)&mus[k][d][0];
            ulonglong2 ua = m2[0];
            ulonglong2 ub = m2[1];
            v2[0][d] = fma2v(ua.x, wvp, v2[0][d]);
            v2[1][d] = fma2v(ua.y, wvp, v2[1][d]);
            v2[2][d] = fma2v(ub.x, wvp, v2[2][d]);
            v2[3][d] = fma2v(ub.y, wvp, v2[3][d]);
            w2[0][d] = fma2v(ua.x, wwp, w2[0][d]);
            w2[1][d] = fma2v(ua.y, wwp, w2[1][d]);
            w2[2][d] = fma2v(ub.x, wwp, w2[2][d]);
            w2[3][d] = fma2v(ub.y, wwp, w2[3][d]);
        }
    }
    float v[TU][3], w[TU][3];
    #pragma unroll
    for (int p = 0; p < TU / 2; p++)
        #pragma unroll
        for (int d = 0; d < 3; d++) {
            float2 fv = upk2(v2[p][d]);
            float2 fw = upk2(w2[p][d]);
            v[2 * p][d] = fv.x; v[2 * p + 1][d] = fv.y;
            w[2 * p][d] = fw.x; w[2 * p + 1][d] = fw.y;
        }
    float s[TU];
    #pragma unroll
    for (int a = 0; a < TU; a++) {
        float n2 = v[a][0]*v[a][0] + v[a][1]*v[a][1] + v[a][2]*v[a][2];
        float vn = sqrtf(n2 + EPSV);
        s[a] = v[a][0]*w[a][0] + v[a][1]*w[a][1] + v[a][2]*w[a][2];
        ctxs[NB + t][a] = vn;
    }
    __syncthreads();

    const float* W1 = c1W + (size_t)it * 2 * NB * NB;
    float b1 = c1b[it * NB + t];
    u64 acc[TU / 2];
    u64 b1p = pk2(b1, b1);
    #pragma unroll
    for (int p = 0; p < TU / 2; p++) acc[p] = b1p;
    for (int k = 0; k < 2 * NB; k++) {
        float ww1 = W1[k * NB + t];
        u64 wp = pk2(ww1, ww1);
        const ulonglong2* c2p = (const ulonglong2*)&ctxs[k][0];
        ulonglong2 ca = c2p[0], cb = c2p[1];
        acc[0] = fma2v(ca.x, wp, acc[0]);
        acc[1] = fma2v(ca.y, wp, acc[1]);
        acc[2] = fma2v(cb.x, wp, acc[2]);
        acc[3] = fma2v(cb.y, wp, acc[3]);
    }
    #pragma unroll
    for (int p = 0; p < TU / 2; p++) {
        float2 f = upk2(acc[p]);
        hs[t][2 * p]     = silu_f(f.x);
        hs[t][2 * p + 1] = silu_f(f.y);
    }
    __syncthreads();

    const float* W2 = c2W + (size_t)it * NB * 3 * NB;
    float b20 = c2b[it * 3 * NB + t];
    float b21 = c2b[it * 3 * NB + NB + t];
    float b22 = c2b[it * 3 * NB + 2 * NB + t];
    u64 aq2[TU / 2], am2[TU / 2], aqm2[TU / 2];
    u64 b20p = pk2(b20, b20), b21p = pk2(b21, b21), b22p = pk2(b22, b22);
    #pragma unroll
    for (int p = 0; p < TU / 2; p++) { aq2[p] = b20p; am2[p] = b21p; aqm2[p] = b22p; }
    for (int k = 0; k < NB; k++) {
        float w0 = W2[k * 384 + t];
        float w1 = W2[k * 384 + NB + t];
        float w2w = W2[k * 384 + 2 * NB + t];
        u64 w0p = pk2(w0, w0), w1p = pk2(w1, w1), w2p = pk2(w2w, w2w);
        const ulonglong2* h2 = (const ulonglong2*)&hs[k][0];
        ulonglong2 ha = h2[0], hb = h2[1];
        aq2[0]  = fma2v(ha.x, w0p, aq2[0]);
        aq2[1]  = fma2v(ha.y, w0p, aq2[1]);
        aq2[2]  = fma2v(hb.x, w0p, aq2[2]);
        aq2[3]  = fma2v(hb.y, w0p, aq2[3]);
        am2[0]  = fma2v(ha.x, w1p, am2[0]);
        am2[1]  = fma2v(ha.y, w1p, am2[1]);
        am2[2]  = fma2v(hb.x, w1p, am2[2]);
        am2[3]  = fma2v(hb.y, w1p, am2[3]);
        aqm2[0] = fma2v(ha.x, w2p, aqm2[0]);
        aqm2[1] = fma2v(ha.y, w2p, aqm2[1]);
        aqm2[2] = fma2v(hb.x, w2p, aqm2[2]);
        aqm2[3] = fma2v(hb.y, w2p, aqm2[3]);
    }
    float aq[TU], am[TU], aqm[TU];
    #pragma unroll
    for (int p = 0; p < TU / 2; p++) {
        float2 f0 = upk2(aq2[p]);
        float2 f1 = upk2(am2[p]);
        float2 f2 = upk2(aqm2[p]);
        aq[2 * p] = f0.x;  aq[2 * p + 1] = f0.y;
        am[2 * p] = f1.x;  am[2 * p + 1] = f1.y;
        aqm[2 * p] = f2.x; aqm[2 * p + 1] = f2.y;
    }
    #pragma unroll
    for (int a = 0; a < TU; a++) {
        size_t g = (size_t)(a0 + a);
        g_q[g * NB + t] = qreg[a] + aq[a] + aqm[a] * s[a];
        #pragma unroll
        for (int d = 0; d < 3; d++) {
            float val = mus[t][d][a] + am[a] * w[a][d];
            g_mu[g * 3 * NB + d * NB + t] = val;
            if (last) mu_out[g * 3 * NB + d * NB + t] = val;
        }
    }
}

// ---------------- output head ----------------
__global__ void __launch_bounds__(128) k_head(
        const float* __restrict__ o1W, const float* __restrict__ o1b,
        const float* __restrict__ o2W, const float* __restrict__ o2b,
        const float* __restrict__ o3W, const float* __restrict__ o3b,
        const int* __restrict__ idx_m, float* __restrict__ y) {
    __shared__ float qs[TH][NB];
    __shared__ float h1[TH][NB];
    __shared__ float h2[TH][NB];
    int t  = threadIdx.x;
    int a0 = blockIdx.x * TH;
    #pragma unroll
    for (int a = 0; a < TH; a++) qs[a][t] = g_q[(size_t)(a0 + a) * NB + t];
    __syncthreads();

    float acc[TH];
    float b = o1b[t];
    #pragma unroll
    for (int a = 0; a < TH; a++) acc[a] = b;
    for (int k = 0; k < NB; k++) {
        float w = o1W[k * NB + t];
        #pragma unroll
        for (int a = 0; a < TH; a++) acc[a] += qs[a][k] * w;
    }
    #pragma unroll
    for (int a = 0; a < TH; a++) h1[a][t] = silu_f(acc[a]);
    __syncthreads();

    b = o2b[t];
    #pragma unroll
    for (int a = 0; a < TH; a++) acc[a] = b;
    for (int k = 0; k < NB; k++) {
        float w = o2W[k * NB + t];
        #pragma unroll
        for (int a = 0; a < TH; a++) acc[a] += h1[a][k] * w;
    }
    #pragma unroll
    for (int a = 0; a < TH; a++) h2[a][t] = silu_f(acc[a]);
    __syncthreads();

    if (t < TH) {
        float sum = o3b[0];
        for (int k = 0; k < NB; k++) sum += h2[t][k] * o3W[k];
        atomicAdd(&y[idx_m[a0 + t]], sum);
    }
}

// ---------------- launch ----------------
extern "C" void kernel_launch(void* const* d_in, const int* in_sizes, int n_in,
                              void* d_out, int out_size) {
    const float* positions = (const float*)d_in[0];
    const float* emb  = (const float*)d_in[1];
    const float* fW   = (const float*)d_in[2];
    const float* fb   = (const float*)d_in[3];
    const float* ic1W = (const float*)d_in[4];
    const float* ic1b = (const float*)d_in[5];
    const float* ic2W = (const float*)d_in[6];
    const float* ic2b = (const float*)d_in[7];
    const float* mixW = (const float*)d_in[8];
    const float* c1W  = (const float*)d_in[9];
    const float* c1b  = (const float*)d_in[10];
    const float* c2W  = (const float*)d_in[11];
    const float* c2b  = (const float*)d_in[12];
    const float* o1W  = (const float*)d_in[13];
    const float* o1b  = (const float*)d_in[14];
    const float* o2W  = (const float*)d_in[15];
    const float* o2b  = (const float*)d_in[16];
    const float* o3W  = (const float*)d_in[17];
    const float* o3b  = (const float*)d_in[18];
    const int* z      = (const int*)d_in[19];
    const int* idx_i  = (const int*)d_in[20];
    const int* idx_j  = (const int*)d_in[21];
    const int* idx_m  = (const int*)d_in[22];
    float* out = (float*)d_out;   // layout: y[64], then mu[10000*3*128]

    k_init_edges<<<(N_EDGES + 255) / 256, 256>>>(positions, idx_i, idx_j);
    k_zero_cnt<<<(N_ATOMS + 255) / 256, 256>>>();
    k_hist<<<(N_EDGES + 255) / 256, 256>>>(idx_i);
    k_scan<<<1, 1024>>>();
    k_fill<<<(N_EDGES + 255) / 256, 256>>>(idx_i, idx_j);
    k_filters<<<(N_EDGES + EB - 1) / EB, 128>>>(fW, fb);
    k_init_atoms<<<N_ATOMS, 128>>>(emb, z, out);

    for (int it = 0; it < NI; it++) {
        k_atoms_x<<<N_ATOMS / TX, 128>>>(ic1W, ic1b, ic2W, ic2b, it);
        if (it == 0) k_gather<0><<<N_ATOMS / 8, 256>>>(it);
        else         k_gather<1><<<N_ATOMS / 8, 256>>>(it);
        k_atoms_update<<<N_ATOMS / TU, 128>>>(mixW, c1W, c1b, c2W, c2b,
                                              it, it == NI - 1, out + BATCH);
    }

    k_head<<<N_ATOMS / TH, 128>>>(o1W, o1b, o2W, o2b, o3W, o3b, idx_m, out);
}

// round 12
// speedup vs baseline: 1.0174x; 1.0174x over previous
#include <cuda_runtime.h>
#include <cuda_fp16.h>
#include <math.h>

#define N_ATOMS 10000
#define N_EDGES 150000
#define NB 128
#define NI 3
#define NF (NI * 3 * NB)     // 1152 filter cols
#define N_RBF 20
#define CUTOFF 5.0f
#define EPSV 1e-8f
#define BATCH 64
#define EB 32                // edges per filter-precompute block
#define TX 16                // atoms per block, k_atoms_x
#define PX 20                // padded row for TX
#define TU 8                 // atoms per block, k_atoms_update
#define PU 12                // padded row for TU
#define TH 8                 // atoms per block, k_head

typedef unsigned long long u64;

// ---------------- device scratch (static, no allocation) ----------------
__device__ float  g_q   [N_ATOMS * NB];
__device__ __align__(16) float g_mu [N_ATOMS * 3 * NB];
__device__ __align__(16) float g_x  [N_ATOMS * 3 * NB];
__device__ float  g_dq  [N_ATOMS * NB];
__device__ float  g_dmu [N_ATOMS * 3 * NB];
__device__ float  g_phif[N_EDGES * N_RBF];
__device__ float  g_fc  [N_EDGES];
__device__ float4 g_dir4[N_EDGES];
__device__ __align__(16) __half g_filt[(size_t)N_EDGES * NF]; // filters fp16, CSR-slot-major
// CSR by destination atom (idx_i)
__device__ int    g_cnt [N_ATOMS];
__device__ int    g_ofs [N_ATOMS + 1];
__device__ int    g_cur [N_ATOMS];
__device__ int    g_slot[N_EDGES];
__device__ int    g_pj  [N_EDGES];
__device__ float4 g_pdir[N_EDGES];

// ---------------- packed f32x2 helpers (FFMA2 path, sm_103a) ----------------
__device__ __forceinline__ u64 pk2(float lo, float hi) {
    u64 r; asm("mov.b64 %0, {%1, %2};" : "=l"(r) : "f"(lo), "f"(hi)); return r;
}
__device__ __forceinline__ float2 upk2(u64 v) {
    float2 f; asm("mov.b64 {%0, %1}, %2;" : "=f"(f.x), "=f"(f.y) : "l"(v)); return f;
}
__device__ __forceinline__ u64 fma2v(u64 a, u64 b, u64 c) {
    u64 d; asm("fma.rn.f32x2 %0, %1, %2, %3;" : "=l"(d) : "l"(a), "l"(b), "l"(c)); return d;
}
__device__ __forceinline__ u64 mul2v(u64 a, u64 b) {
    u64 d; asm("mul.rn.f32x2 %0, %1, %2;" : "=l"(d) : "l"(a), "l"(b)); return d;
}
// half2 (as uint) -> packed f32x2
__device__ __forceinline__ u64 h2f2(unsigned h) {
    float2 f = __half22float2(*reinterpret_cast<__half2*>(&h));
    return pk2(f.x, f.y);
}

__device__ __forceinline__ float silu_f(float v) {
    return v / (1.0f + expf(-v));
}

// ---------------- edge geometry precompute ----------------
__global__ void k_init_edges(const float* __restrict__ pos,
                             const int* __restrict__ idx_i,
                             const int* __restrict__ idx_j) {
    int e = blockIdx.x * blockDim.x + threadIdx.x;
    if (e >= N_EDGES) return;
    int i = idx_i[e], j = idx_j[e];
    float rx = pos[j * 3 + 0] - pos[i * 3 + 0];
    float ry = pos[j * 3 + 1] - pos[i * 3 + 1];
    float rz = pos[j * 3 + 2] - pos[i * 3 + 2];
    float d  = sqrtf(rx * rx + ry * ry + rz * rz);
    float inv = 1.0f / d;
    g_dir4[e] = make_float4(rx * inv, ry * inv, rz * inv, 0.0f);
    float fc = (d < CUTOFF) ? 0.5f * (cosf(d * (float)M_PI / CUTOFF) + 1.0f) : 0.0f;
    g_fc[e] = fc;
    const float width = CUTOFF / (float)(N_RBF - 1);
    const float coeff = -0.5f / (width * width);
    #pragma unroll
    for (int r = 0; r < N_RBF; r++) {
        float dd = d - (float)r * width;
        g_phif[e * N_RBF + r] = expf(coeff * dd * dd) * fc;
    }
}

// ---------------- CSR build ----------------
__global__ void k_zero_cnt() {
    int a = blockIdx.x * blockDim.x + threadIdx.x;
    if (a < N_ATOMS) g_cnt[a] = 0;
}
__global__ void k_hist(const int* __restrict__ idx_i) {
    int e = blockIdx.x * blockDim.x + threadIdx.x;
    if (e < N_EDGES) atomicAdd(&g_cnt[idx_i[e]], 1);
}
__global__ void __launch_bounds__(1024) k_scan() {
    __shared__ int partial[1024];
    int t = threadIdx.x;
    int base = t * 10;
    int local[10];
    int s = 0;
    #pragma unroll
    for (int k = 0; k < 10; k++) {
        int idx = base + k;
        int c = (idx < N_ATOMS) ? g_cnt[idx] : 0;
        local[k] = s;
        s += c;
    }
    partial[t] = s;
    __syncthreads();
    for (int off = 1; off < 1024; off <<= 1) {
        int v = partial[t];
        int u = (t >= off) ? partial[t - off] : 0;
        __syncthreads();
        partial[t] = v + u;
        __syncthreads();
    }
    int pre = (t > 0) ? partial[t - 1] : 0;
    #pragma unroll
    for (int k = 0; k < 10; k++) {
        int idx = base + k;
        if (idx < N_ATOMS) {
            int o = pre + local[k];
            g_ofs[idx] = o;
            g_cur[idx] = o;
        }
    }
    if (t == 1023) g_ofs[N_ATOMS] = partial[1023];
}
__global__ void k_fill(const int* __restrict__ idx_i,
                       const int* __restrict__ idx_j) {
    int e = blockIdx.x * blockDim.x + threadIdx.x;
    if (e < N_EDGES) {
        int pos = atomicAdd(&g_cur[idx_i[e]], 1);
        g_slot[e] = pos;
        g_pj[pos] = idx_j[e];
        g_pdir[pos] = g_dir4[e];
    }
}

// ---------------- dense filter precompute into CSR-slot rows (fp16, f32x2) ---
// EB=32 amortizes the per-block fW L2 reads 4x vs EB=8; slot-major layout kept.
__global__ void __launch_bounds__(128) k_filters(const float* __restrict__ fW,
                                                 const float* __restrict__ fb) {
    __shared__ __align__(16) float ps[N_RBF][EB];   // [r][edge]
    __shared__ float fcs[EB];
    __shared__ int   slots[EB];
    int e0 = blockIdx.x * EB;
    int t  = threadIdx.x;
    for (int idx = t; idx < EB * N_RBF; idx += 128) {
        int a = idx / N_RBF, r = idx % N_RBF;
        int e = e0 + a;
        ps[r][a] = (e < N_EDGES) ? g_phif[(size_t)e * N_RBF + r] : 0.0f;
    }
    for (int idx = t; idx < EB; idx += 128) {
        int e = e0 + idx;
        fcs[idx]   = (e < N_EDGES) ? g_fc[e] : 0.0f;
        slots[idx] = (e < N_EDGES) ? g_slot[e] : 0;
    }
    __syncthreads();

    int nval = N_EDGES - e0;
    if (nval > EB) nval = EB;

    #pragma unroll 1
    for (int grp = 0; grp < NF / 128; grp++) {
        int c = grp * 128 + t;
        float wc[N_RBF];
        #pragma unroll
        for (int r = 0; r < N_RBF; r++) wc[r] = fW[r * NF + c];
        float bias = fb[c];
        u64 bp = pk2(bias, bias);
        u64 acc[EB / 2];
        #pragma unroll
        for (int p = 0; p < EB / 2; p++)
            acc[p] = mul2v(pk2(fcs[2 * p], fcs[2 * p + 1]), bp);
        #pragma unroll
        for (int r = 0; r < N_RBF; r++) {
            u64 wp = pk2(wc[r], wc[r]);
            const u64* pr = (const u64*)&ps[r][0];
            #pragma unroll
            for (int p = 0; p < EB / 2; p++) acc[p] = fma2v(pr[p], wp, acc[p]);
        }
        #pragma unroll
        for (int p = 0; p < EB / 2; p++) {
            float2 f = upk2(acc[p]);
            if (2 * p < nval)
                g_filt[(size_t)slots[2 * p] * NF + c]     = __float2half_rn(f.x);
            if (2 * p + 1 < nval)
                g_filt[(size_t)slots[2 * p + 1] * NF + c] = __float2half_rn(f.y);
        }
    }
}

// ---------------- atom init ----------------
__global__ void k_init_atoms(const float* __restrict__ emb,
                             const int* __restrict__ z,
                             float* __restrict__ y_out) {
    int a = blockIdx.x;
    int t = threadIdx.x;
    g_q[a * NB + t] = emb[z[a] * NB + t];
    #pragma unroll
    for (int d = 0; d < 3; d++)
        g_mu[a * 3 * NB + d * NB + t] = 0.0f;
    if (a == 0 && t < BATCH) y_out[t] = 0.0f;
}

// ---------------- per-atom input MLP (f32x2 packed atom pairs) ---------------
__global__ void __launch_bounds__(128) k_atoms_x(
        const float* __restrict__ ic1W, const float* __restrict__ ic1b,
        const float* __restrict__ ic2W, const float* __restrict__ ic2b,
        int it) {
    __shared__ __align__(16) float qs[NB][PX];
    __shared__ __align__(16) float hs[NB][PX];
    int t  = threadIdx.x;
    int a0 = blockIdx.x * TX;

    #pragma unroll
    for (int a = 0; a < TX; a++)
        qs[t][a] = g_q[(size_t)(a0 + a) * NB + t];
    __syncthreads();

    const float* W1 = ic1W + (size_t)it * NB * NB;
    float b1 = ic1b[it * NB + t];
    u64 acc[TX / 2];
    u64 b1p = pk2(b1, b1);
    #pragma unroll
    for (int p = 0; p < TX / 2; p++) acc[p] = b1p;
    for (int k = 0; k < NB; k++) {
        float w = W1[k * NB + t];
        u64 wp = pk2(w, w);
        const ulonglong2* q2 = (const ulonglong2*)&qs[k][0];
        #pragma unroll
        for (int p4 = 0; p4 < TX / 4; p4++) {
            ulonglong2 u = q2[p4];
            acc[2 * p4]     = fma2v(u.x, wp, acc[2 * p4]);
            acc[2 * p4 + 1] = fma2v(u.y, wp, acc[2 * p4 + 1]);
        }
    }
    #pragma unroll
    for (int p = 0; p < TX / 2; p++) {
        float2 f = upk2(acc[p]);
        hs[t][2 * p]     = silu_f(f.x);
        hs[t][2 * p + 1] = silu_f(f.y);
    }
    __syncthreads();

    const float* W2 = ic2W + (size_t)it * NB * 3 * NB;
    float b20 = ic2b[it * 3 * NB + t];
    float b21 = ic2b[it * 3 * NB + NB + t];
    float b22 = ic2b[it * 3 * NB + 2 * NB + t];
    u64 c0[TX / 2], c1[TX / 2], c2[TX / 2];
    u64 b20p = pk2(b20, b20), b21p = pk2(b21, b21), b22p = pk2(b22, b22);
    #pragma unroll
    for (int p = 0; p < TX / 2; p++) { c0[p] = b20p; c1[p] = b21p; c2[p] = b22p; }
    for (int k = 0; k < NB; k++) {
        float w0 = W2[k * 384 + t];
        float w1 = W2[k * 384 + NB + t];
        float w2 = W2[k * 384 + 2 * NB + t];
        u64 w0p = pk2(w0, w0), w1p = pk2(w1, w1), w2p = pk2(w2, w2);
        const ulonglong2* h2 = (const ulonglong2*)&hs[k][0];
        #pragma unroll
        for (int p4 = 0; p4 < TX / 4; p4++) {
            ulonglong2 u = h2[p4];
            c0[2 * p4]     = fma2v(u.x, w0p, c0[2 * p4]);
            c0[2 * p4 + 1] = fma2v(u.y, w0p, c0[2 * p4 + 1]);
            c1[2 * p4]     = fma2v(u.x, w1p, c1[2 * p4]);
            c1[2 * p4 + 1] = fma2v(u.y, w1p, c1[2 * p4 + 1]);
            c2[2 * p4]     = fma2v(u.x, w2p, c2[2 * p4]);
            c2[2 * p4 + 1] = fma2v(u.y, w2p, c2[2 * p4 + 1]);
        }
    }
    #pragma unroll
    for (int p = 0; p < TX / 2; p++) {
        float2 f0 = upk2(c0[p]);
        float2 f1 = upk2(c1[p]);
        float2 f2 = upk2(c2[p]);
        size_t ga = (size_t)(a0 + 2 * p) * 384;
        size_t gb = (size_t)(a0 + 2 * p + 1) * 384;
        g_x[ga + t] = f0.x;           g_x[gb + t] = f0.y;
        g_x[ga + NB + t] = f1.x;      g_x[gb + NB + t] = f1.y;
        g_x[ga + 2 * NB + t] = f2.x;  g_x[gb + 2 * NB + t] = f2.y;
    }
}

// ---------------- edge gather: warp per atom (R6 best-measured form) ---------
template <int HAS_MU>
__global__ void __launch_bounds__(256) k_gather(int it) {
    int warp = threadIdx.x >> 5;
    int lane = threadIdx.x & 31;
    int i = blockIdx.x * 8 + warp;
    int beg = g_ofs[i], end = g_ofs[i + 1];

    u64 mq0 = 0, mq1 = 0;
    u64 m0a = 0, m0b = 0, m1a = 0, m1b = 0, m2a = 0, m2b = 0;

    const int itofs = it * 384;   // in half units
    int j = 0; float4 d4 = make_float4(0,0,0,0);
    if (beg < end) { j = __ldg(g_pj + beg); d4 = g_pdir[beg]; }

    for (int k = beg; k < end; k++) {
        int jn = 0; float4 dn = d4;
        if (k + 1 < end) { jn = __ldg(g_pj + k + 1); dn = g_pdir[k + 1]; }

        const uint2* fe = (const uint2*)(g_filt + (size_t)k * NF + itofs);
        uint2 f0 = fe[lane];
        uint2 f1 = fe[32 + lane];
        uint2 f2 = fe[64 + lane];
        const ulonglong2* xr = (const ulonglong2*)(g_x + (size_t)j * 384);
        ulonglong2 x0 = xr[lane];
        ulonglong2 x1 = xr[32 + lane];
        ulonglong2 x2 = xr[64 + lane];
        ulonglong2 u0, u1, u2;
        if (HAS_MU) {
            const ulonglong2* mr = (const ulonglong2*)(g_mu + (size_t)j * 384);
            u0 = mr[lane];
            u1 = mr[32 + lane];
            u2 = mr[64 + lane];
        }

        u64 w0x = h2f2(f0.x), w0y = h2f2(f0.y);
        u64 w1x = h2f2(f1.x), w1y = h2f2(f1.y);
        u64 w2x = h2f2(f2.x), w2y = h2f2(f2.y);

        mq0 = fma2v(w0x, x0.x, mq0);
        mq1 = fma2v(w0y, x0.y, mq1);
        u64 vR0 = mul2v(w1x, x1.x), vR1 = mul2v(w1y, x1.y);
        u64 vM0 = mul2v(w2x, x2.x), vM1 = mul2v(w2y, x2.y);
        u64 dxp = pk2(d4.x, d4.x), dyp = pk2(d4.y, d4.y), dzp = pk2(d4.z, d4.z);
        if (HAS_MU) {
            m0a = fma2v(vR0, dxp, fma2v(vM0, u0.x, m0a));
            m0b = fma2v(vR1, dxp, fma2v(vM1, u0.y, m0b));
            m1a = fma2v(vR0, dyp, fma2v(vM0, u1.x, m1a));
            m1b = fma2v(vR1, dyp, fma2v(vM1, u1.y, m1b));
            m2a = fma2v(vR0, dzp, fma2v(vM0, u2.x, m2a));
            m2b = fma2v(vR1, dzp, fma2v(vM1, u2.y, m2b));
        } else {
            m0a = fma2v(vR0, dxp, m0a);
            m0b = fma2v(vR1, dxp, m0b);
            m1a = fma2v(vR0, dyp, m1a);
            m1b = fma2v(vR1, dyp, m1b);
            m2a = fma2v(vR0, dzp, m2a);
            m2b = fma2v(vR1, dzp, m2b);
        }
        j = jn; d4 = dn;
    }
    ulonglong2 o;
    o.x = mq0; o.y = mq1;
    ((ulonglong2*)(g_dq + (size_t)i * NB))[lane] = o;
    ulonglong2* dmu = (ulonglong2*)(g_dmu + (size_t)i * 3 * NB);
    o.x = m0a; o.y = m0b; dmu[lane]      = o;
    o.x = m1a; o.y = m1b; dmu[32 + lane] = o;
    o.x = m2a; o.y = m2b; dmu[64 + lane] = o;
}

// ---------------- per-atom update (f32x2 packed atom pairs) ------------------
__global__ void __launch_bounds__(128) k_atoms_update(
        const float* __restrict__ mixW,
        const float* __restrict__ c1W, const float* __restrict__ c1b,
        const float* __restrict__ c2W, const float* __restrict__ c2b,
        int it, int last, float* __restrict__ mu_out) {
    __shared__ __align__(16) float mus[NB][3][PU];     // [k][d][a]
    __shared__ __align__(16) float ctxs[2 * NB][PU];   // [k][a]
    __shared__ __align__(16) float hs[NB][PU];         // [k][a]
    int t  = threadIdx.x;
    int a0 = blockIdx.x * TU;

    float qreg[TU];
    #pragma unroll
    for (int a = 0; a < TU; a++) {
        size_t g = (size_t)(a0 + a);
        qreg[a] = g_q[g * NB + t] + g_dq[g * NB + t];
        ctxs[t][a] = qreg[a];
        #pragma unroll
        for (int d = 0; d < 3; d++)
            mus[t][d][a] = g_mu[g * 3 * NB + d * NB + t] + g_dmu[g * 3 * NB + d * NB + t];
    }
    __syncthreads();

    const float* MW = mixW + (size_t)it * NB * 2 * NB;
    u64 v2[TU / 2][3], w2[TU / 2][3];
    #pragma unroll
    for (int p = 0; p < TU / 2; p++)
        #pragma unroll
        for (int d = 0; d < 3; d++) { v2[p][d] = 0; w2[p][d] = 0; }
    for (int k = 0; k < NB; k++) {
        float wv = MW[k * 256 + t];
        float ww = MW[k * 256 + NB + t];
        u64 wvp = pk2(wv, wv), wwp = pk2(ww, ww);
        #pragma unroll
        for (int d = 0; d < 3; d++) {
            const ulonglong2* m2 = (const ulonglong2*)&mus[k][d][0];
            ulonglong2 ua = m2[0];
            ulonglong2 ub = m2[1];
            v2[0][d] = fma2v(ua.x, wvp, v2[0][d]);
            v2[1][d] = fma2v(ua.y, wvp, v2[1][d]);
            v2[2][d] = fma2v(ub.x, wvp, v2[2][d]);
            v2[3][d] = fma2v(ub.y, wvp, v2[3][d]);
            w2[0][d] = fma2v(ua.x, wwp, w2[0][d]);
            w2[1][d] = fma2v(ua.y, wwp, w2[1][d]);
            w2[2][d] = fma2v(ub.x, wwp, w2[2][d]);
            w2[3][d] = fma2v(ub.y, wwp, w2[3][d]);
        }
    }
    float v[TU][3], w[TU][3];
    #pragma unroll
    for (int p = 0; p < TU / 2; p++)
        #pragma unroll
        for (int d = 0; d < 3; d++) {
            float2 fv = upk2(v2[p][d]);
            float2 fw = upk2(w2[p][d]);
            v[2 * p][d] = fv.x; v[2 * p + 1][d] = fv.y;
            w[2 * p][d] = fw.x; w[2 * p + 1][d] = fw.y;
        }
    float s[TU];
    #pragma unroll
    for (int a = 0; a < TU; a++) {
        float n2 = v[a][0]*v[a][0] + v[a][1]*v[a][1] + v[a][2]*v[a][2];
        float vn = sqrtf(n2 + EPSV);
        s[a] = v[a][0]*w[a][0] + v[a][1]*w[a][1] + v[a][2]*w[a][2];
        ctxs[NB + t][a] = vn;
    }
    __syncthreads();

    const float* W1 = c1W + (size_t)it * 2 * NB * NB;
    float b1 = c1b[it * NB + t];
    u64 acc[TU / 2];
    u64 b1p = pk2(b1, b1);
    #pragma unroll
    for (int p = 0; p < TU / 2; p++) acc[p] = b1p;
    for (int k = 0; k < 2 * NB; k++) {
        float ww1 = W1[k * NB + t];
        u64 wp = pk2(ww1, ww1);
        const ulonglong2* c2p = (const ulonglong2*)&ctxs[k][0];
        ulonglong2 ca = c2p[0], cb = c2p[1];
        acc[0] = fma2v(ca.x, wp, acc[0]);
        acc[1] = fma2v(ca.y, wp, acc[1]);
        acc[2] = fma2v(cb.x, wp, acc[2]);
        acc[3] = fma2v(cb.y, wp, acc[3]);
    }
    #pragma unroll
    for (int p = 0; p < TU / 2; p++) {
        float2 f = upk2(acc[p]);
        hs[t][2 * p]     = silu_f(f.x);
        hs[t][2 * p + 1] = silu_f(f.y);
    }
    __syncthreads();

    const float* W2 = c2W + (size_t)it * NB * 3 * NB;
    float b20 = c2b[it * 3 * NB + t];
    float b21 = c2b[it * 3 * NB + NB + t];
    float b22 = c2b[it * 3 * NB + 2 * NB + t];
    u64 aq2[TU / 2], am2[TU / 2], aqm2[TU / 2];
    u64 b20p = pk2(b20, b20), b21p = pk2(b21, b21), b22p = pk2(b22, b22);
    #pragma unroll
    for (int p = 0; p < TU / 2; p++) { aq2[p] = b20p; am2[p] = b21p; aqm2[p] = b22p; }
    for (int k = 0; k < NB; k++) {
        float w0 = W2[k * 384 + t];
        float w1 = W2[k * 384 + NB + t];
        float w2w = W2[k * 384 + 2 * NB + t];
        u64 w0p = pk2(w0, w0), w1p = pk2(w1, w1), w2p = pk2(w2w, w2w);
        const ulonglong2* h2 = (const ulonglong2*)&hs[k][0];
        ulonglong2 ha = h2[0], hb = h2[1];
        aq2[0]  = fma2v(ha.x, w0p, aq2[0]);
        aq2[1]  = fma2v(ha.y, w0p, aq2[1]);
        aq2[2]  = fma2v(hb.x, w0p, aq2[2]);
        aq2[3]  = fma2v(hb.y, w0p, aq2[3]);
        am2[0]  = fma2v(ha.x, w1p, am2[0]);
        am2[1]  = fma2v(ha.y, w1p, am2[1]);
        am2[2]  = fma2v(hb.x, w1p, am2[2]);
        am2[3]  = fma2v(hb.y, w1p, am2[3]);
        aqm2[0] = fma2v(ha.x, w2p, aqm2[0]);
        aqm2[1] = fma2v(ha.y, w2p, aqm2[1]);
        aqm2[2] = fma2v(hb.x, w2p, aqm2[2]);
        aqm2[3] = fma2v(hb.y, w2p, aqm2[3]);
    }
    float aq[TU], am[TU], aqm[TU];
    #pragma unroll
    for (int p = 0; p < TU / 2; p++) {
        float2 f0 = upk2(aq2[p]);
        float2 f1 = upk2(am2[p]);
        float2 f2 = upk2(aqm2[p]);
        aq[2 * p] = f0.x;  aq[2 * p + 1] = f0.y;
        am[2 * p] = f1.x;  am[2 * p + 1] = f1.y;
        aqm[2 * p] = f2.x; aqm[2 * p + 1] = f2.y;
    }
    #pragma unroll
    for (int a = 0; a < TU; a++) {
        size_t g = (size_t)(a0 + a);
        g_q[g * NB + t] = qreg[a] + aq[a] + aqm[a] * s[a];
        #pragma unroll
        for (int d = 0; d < 3; d++) {
            float val = mus[t][d][a] + am[a] * w[a][d];
            g_mu[g * 3 * NB + d * NB + t] = val;
            if (last) mu_out[g * 3 * NB + d * NB + t] = val;
        }
    }
}

// ---------------- output head ----------------
__global__ void __launch_bounds__(128) k_head(
        const float* __restrict__ o1W, const float* __restrict__ o1b,
        const float* __restrict__ o2W, const float* __restrict__ o2b,
        const float* __restrict__ o3W, const float* __restrict__ o3b,
        const int* __restrict__ idx_m, float* __restrict__ y) {
    __shared__ float qs[TH][NB];
    __shared__ float h1[TH][NB];
    __shared__ float h2[TH][NB];
    int t  = threadIdx.x;
    int a0 = blockIdx.x * TH;
    #pragma unroll
    for (int a = 0; a < TH; a++) qs[a][t] = g_q[(size_t)(a0 + a) * NB + t];
    __syncthreads();

    float acc[TH];
    float b = o1b[t];
    #pragma unroll
    for (int a = 0; a < TH; a++) acc[a] = b;
    for (int k = 0; k < NB; k++) {
        float w = o1W[k * NB + t];
        #pragma unroll
        for (int a = 0; a < TH; a++) acc[a] += qs[a][k] * w;
    }
    #pragma unroll
    for (int a = 0; a < TH; a++) h1[a][t] = silu_f(acc[a]);
    __syncthreads();

    b = o2b[t];
    #pragma unroll
    for (int a = 0; a < TH; a++) acc[a] = b;
    for (int k = 0; k < NB; k++) {
        float w = o2W[k * NB + t];
        #pragma unroll
        for (int a = 0; a < TH; a++) acc[a] += h1[a][k] * w;
    }
    #pragma unroll
    for (int a = 0; a < TH; a++) h2[a][t] = silu_f(acc[a]);
    __syncthreads();

    if (t < TH) {
        float sum = o3b[0];
        for (int k = 0; k < NB; k++) sum += h2[t][k] * o3W[k];
        atomicAdd(&y[idx_m[a0 + t]], sum);
    }
}

// ---------------- launch ----------------
extern "C" void kernel_launch(void* const* d_in, const int* in_sizes, int n_in,
                              void* d_out, int out_size) {
    const float* positions = (const float*)d_in[0];
    const float* emb  = (const float*)d_in[1];
    const float* fW   = (const float*)d_in[2];
    const float* fb   = (const float*)d_in[3];
    const float* ic1W = (const float*)d_in[4];
    const float* ic1b = (const float*)d_in[5];
    const float* ic2W = (const float*)d_in[6];
    const float* ic2b = (const float*)d_in[7];
    const float* mixW = (const float*)d_in[8];
    const float* c1W  = (const float*)d_in[9];
    const float* c1b  = (const float*)d_in[10];
    const float* c2W  = (const float*)d_in[11];
    const float* c2b  = (const float*)d_in[12];
    const float* o1W  = (const float*)d_in[13];
    const float* o1b  = (const float*)d_in[14];
    const float* o2W  = (const float*)d_in[15];
    const float* o2b  = (const float*)d_in[16];
    const float* o3W  = (const float*)d_in[17];
    const float* o3b  = (const float*)d_in[18];
    const int* z      = (const int*)d_in[19];
    const int* idx_i  = (const int*)d_in[20];
    const int* idx_j  = (const int*)d_in[21];
    const int* idx_m  = (const int*)d_in[22];
    float* out = (float*)d_out;   // layout: y[64], then mu[10000*3*128]

    k_init_edges<<<(N_EDGES + 255) / 256, 256>>>(positions, idx_i, idx_j);
    k_zero_cnt<<<(N_ATOMS + 255) / 256, 256>>>();
    k_hist<<<(N_EDGES + 255) / 256, 256>>>(idx_i);
    k_scan<<<1, 1024>>>();
    k_fill<<<(N_EDGES + 255) / 256, 256>>>(idx_i, idx_j);
    k_filters<<<(N_EDGES + EB - 1) / EB, 128>>>(fW, fb);
    k_init_atoms<<<N_ATOMS, 128>>>(emb, z, out);

    for (int it = 0; it < NI; it++) {
        k_atoms_x<<<N_ATOMS / TX, 128>>>(ic1W, ic1b, ic2W, ic2b, it);
        if (it == 0) k_gather<0><<<N_ATOMS / 8, 256>>>(it);
        else         k_gather<1><<<N_ATOMS / 8, 256>>>(it);
        k_atoms_update<<<N_ATOMS / TU, 128>>>(mixW, c1W, c1b, c2W, c2b,
                                              it, it == NI - 1, out + BATCH);
    }

    k_head<<<N_ATOMS / TH, 128>>>(o1W, o1b, o2W, o2b, o3W, o3b, idx_m, out);
}

// round 13
// speedup vs baseline: 2.4909x; 2.4484x over previous
#include <cuda_runtime.h>
#include <cuda_fp16.h>
#include <math.h>

#define N_ATOMS 10000
#define N_EDGES 150000
#define NB 128
#define NI 3
#define NF (NI * 3 * NB)     // 1152 filter cols
#define N_RBF 20
#define CUTOFF 5.0f
#define EPSV 1e-8f
#define BATCH 64
#define EB 8                 // edges per filter-precompute block (R6 operating point)
#define TX 16                // atoms per block, k_atoms_x
#define PX 20                // padded row for TX
#define TU 8                 // atoms per block, k_atoms_update
#define PU 12                // padded row for TU
#define TH 8                 // atoms per block, k_head

typedef unsigned long long u64;

// ---------------- device scratch (static, no allocation) ----------------
__device__ float  g_q   [N_ATOMS * NB];
__device__ __align__(16) float g_mu [N_ATOMS * 3 * NB];
__device__ __align__(16) float g_x  [N_ATOMS * 3 * NB];
__device__ float  g_dq  [N_ATOMS * NB];
__device__ float  g_dmu [N_ATOMS * 3 * NB];
__device__ float  g_phif[N_EDGES * N_RBF];
__device__ float  g_fc  [N_EDGES];
__device__ float4 g_dir4[N_EDGES];
__device__ __align__(16) __half g_filt[(size_t)N_EDGES * NF]; // filters fp16, CSR-slot-major
// CSR by destination atom (idx_i)
__device__ int    g_cnt [N_ATOMS];
__device__ int    g_ofs [N_ATOMS + 1];
__device__ int    g_cur [N_ATOMS];
__device__ int    g_slot[N_EDGES];
__device__ int    g_pj  [N_EDGES];
__device__ float4 g_pdir[N_EDGES];

// ---------------- packed f32x2 helpers (FFMA2 path, sm_103a) ----------------
__device__ __forceinline__ u64 pk2(float lo, float hi) {
    u64 r; asm("mov.b64 %0, {%1, %2};" : "=l"(r) : "f"(lo), "f"(hi)); return r;
}
__device__ __forceinline__ float2 upk2(u64 v) {
    float2 f; asm("mov.b64 {%0, %1}, %2;" : "=f"(f.x), "=f"(f.y) : "l"(v)); return f;
}
__device__ __forceinline__ u64 fma2v(u64 a, u64 b, u64 c) {
    u64 d; asm("fma.rn.f32x2 %0, %1, %2, %3;" : "=l"(d) : "l"(a), "l"(b), "l"(c)); return d;
}
__device__ __forceinline__ u64 mul2v(u64 a, u64 b) {
    u64 d; asm("mul.rn.f32x2 %0, %1, %2;" : "=l"(d) : "l"(a), "l"(b)); return d;
}
// half2 (as uint) -> packed f32x2
__device__ __forceinline__ u64 h2f2(unsigned h) {
    float2 f = __half22float2(*reinterpret_cast<__half2*>(&h));
    return pk2(f.x, f.y);
}

__device__ __forceinline__ float silu_f(float v) {
    return v / (1.0f + expf(-v));
}

// ---------------- iteration-0 atom MLP + global init (launch 0) --------------
// q = emb[z], mu = 0, x = silu(q@W1+b1)@W2+b2 (it=0), plus cnt/y zeroing.
__global__ void __launch_bounds__(128) k_atoms_x0(
        const float* __restrict__ emb, const int* __restrict__ z,
        const float* __restrict__ ic1W, const float* __restrict__ ic1b,
        const float* __restrict__ ic2W, const float* __restrict__ ic2b,
        float* __restrict__ y_out) {
    __shared__ __align__(16) float qs[NB][PX];
    __shared__ __align__(16) float hs[NB][PX];
    int t  = threadIdx.x;
    int a0 = blockIdx.x * TX;

    int flat = blockIdx.x * 128 + t;
    if (flat < N_ATOMS) g_cnt[flat] = 0;
    if (flat < BATCH)   y_out[flat] = 0.0f;

    #pragma unroll
    for (int a = 0; a < TX; a++) {
        int at = a0 + a;
        float qv = emb[(size_t)z[at] * NB + t];
        qs[t][a] = qv;
        g_q[(size_t)at * NB + t] = qv;
        #pragma unroll
        for (int d = 0; d < 3; d++)
            g_mu[(size_t)at * 3 * NB + d * NB + t] = 0.0f;
    }
    __syncthreads();

    const float* W1 = ic1W;   // it = 0 slice
    float b1 = ic1b[t];
    u64 acc[TX / 2];
    u64 b1p = pk2(b1, b1);
    #pragma unroll
    for (int p = 0; p < TX / 2; p++) acc[p] = b1p;
    for (int k = 0; k < NB; k++) {
        float w = W1[k * NB + t];
        u64 wp = pk2(w, w);
        const ulonglong2* q2 = (const ulonglong2*)&qs[k][0];
        #pragma unroll
        for (int p4 = 0; p4 < TX / 4; p4++) {
            ulonglong2 u = q2[p4];
            acc[2 * p4]     = fma2v(u.x, wp, acc[2 * p4]);
            acc[2 * p4 + 1] = fma2v(u.y, wp, acc[2 * p4 + 1]);
        }
    }
    #pragma unroll
    for (int p = 0; p < TX / 2; p++) {
        float2 f = upk2(acc[p]);
        hs[t][2 * p]     = silu_f(f.x);
        hs[t][2 * p + 1] = silu_f(f.y);
    }
    __syncthreads();

    const float* W2 = ic2W;   // it = 0 slice
    float b20 = ic2b[t];
    float b21 = ic2b[NB + t];
    float b22 = ic2b[2 * NB + t];
    u64 c0[TX / 2], c1[TX / 2], c2[TX / 2];
    u64 b20p = pk2(b20, b20), b21p = pk2(b21, b21), b22p = pk2(b22, b22);
    #pragma unroll
    for (int p = 0; p < TX / 2; p++) { c0[p] = b20p; c1[p] = b21p; c2[p] = b22p; }
    for (int k = 0; k < NB; k++) {
        float w0 = W2[k * 384 + t];
        float w1 = W2[k * 384 + NB + t];
        float w2 = W2[k * 384 + 2 * NB + t];
        u64 w0p = pk2(w0, w0), w1p = pk2(w1, w1), w2p = pk2(w2, w2);
        const ulonglong2* h2 = (const ulonglong2*)&hs[k][0];
        #pragma unroll
        for (int p4 = 0; p4 < TX / 4; p4++) {
            ulonglong2 u = h2[p4];
            c0[2 * p4]     = fma2v(u.x, w0p, c0[2 * p4]);
            c0[2 * p4 + 1] = fma2v(u.y, w0p, c0[2 * p4 + 1]);
            c1[2 * p4]     = fma2v(u.x, w1p, c1[2 * p4]);
            c1[2 * p4 + 1] = fma2v(u.y, w1p, c1[2 * p4 + 1]);
            c2[2 * p4]     = fma2v(u.x, w2p, c2[2 * p4]);
            c2[2 * p4 + 1] = fma2v(u.y, w2p, c2[2 * p4 + 1]);
        }
    }
    #pragma unroll
    for (int p = 0; p < TX / 2; p++) {
        float2 f0 = upk2(c0[p]);
        float2 f1 = upk2(c1[p]);
        float2 f2 = upk2(c2[p]);
        size_t ga = (size_t)(a0 + 2 * p) * 384;
        size_t gb = (size_t)(a0 + 2 * p + 1) * 384;
        g_x[ga + t] = f0.x;           g_x[gb + t] = f0.y;
        g_x[ga + NB + t] = f1.x;      g_x[gb + NB + t] = f1.y;
        g_x[ga + 2 * NB + t] = f2.x;  g_x[gb + 2 * NB + t] = f2.y;
    }
}

// ---------------- edge geometry precompute + histogram (launch 1) ------------
__global__ void k_init_edges(const float* __restrict__ pos,
                             const int* __restrict__ idx_i,
                             const int* __restrict__ idx_j) {
    int e = blockIdx.x * blockDim.x + threadIdx.x;
    if (e >= N_EDGES) return;
    int i = idx_i[e], j = idx_j[e];
    float rx = pos[j * 3 + 0] - pos[i * 3 + 0];
    float ry = pos[j * 3 + 1] - pos[i * 3 + 1];
    float rz = pos[j * 3 + 2] - pos[i * 3 + 2];
    float d  = sqrtf(rx * rx + ry * ry + rz * rz);
    float inv = 1.0f / d;
    g_dir4[e] = make_float4(rx * inv, ry * inv, rz * inv, 0.0f);
    float fc = (d < CUTOFF) ? 0.5f * (cosf(d * (float)M_PI / CUTOFF) + 1.0f) : 0.0f;
    g_fc[e] = fc;
    const float width = CUTOFF / (float)(N_RBF - 1);
    const float coeff = -0.5f / (width * width);
    #pragma unroll
    for (int r = 0; r < N_RBF; r++) {
        float dd = d - (float)r * width;
        g_phif[e * N_RBF + r] = expf(coeff * dd * dd) * fc;
    }
    atomicAdd(&g_cnt[i], 1);   // cnt zeroed in launch 0
}

// ---------------- CSR build ----------------
__global__ void __launch_bounds__(1024) k_scan() {
    __shared__ int partial[1024];
    int t = threadIdx.x;
    int base = t * 10;
    int local[10];
    int s = 0;
    #pragma unroll
    for (int k = 0; k < 10; k++) {
        int idx = base + k;
        int c = (idx < N_ATOMS) ? g_cnt[idx] : 0;
        local[k] = s;
        s += c;
    }
    partial[t] = s;
    __syncthreads();
    for (int off = 1; off < 1024; off <<= 1) {
        int v = partial[t];
        int u = (t >= off) ? partial[t - off] : 0;
        __syncthreads();
        partial[t] = v + u;
        __syncthreads();
    }
    int pre = (t > 0) ? partial[t - 1] : 0;
    #pragma unroll
    for (int k = 0; k < 10; k++) {
        int idx = base + k;
        if (idx < N_ATOMS) {
            int o = pre + local[k];
            g_ofs[idx] = o;
            g_cur[idx] = o;
        }
    }
    if (t == 1023) g_ofs[N_ATOMS] = partial[1023];
}
__global__ void k_fill(const int* __restrict__ idx_i,
                       const int* __restrict__ idx_j) {
    int e = blockIdx.x * blockDim.x + threadIdx.x;
    if (e < N_EDGES) {
        int pos = atomicAdd(&g_cur[idx_i[e]], 1);
        g_slot[e] = pos;
        g_pj[pos] = idx_j[e];
        g_pdir[pos] = g_dir4[e];
    }
}

// ---------------- dense filter precompute into CSR-slot rows (fp16, f32x2) ---
__global__ void __launch_bounds__(128) k_filters(const float* __restrict__ fW,
                                                 const float* __restrict__ fb) {
    __shared__ __align__(16) float ps[N_RBF][EB];   // [r][edge]
    __shared__ float fcs[EB];
    __shared__ int   slots[EB];
    int e0 = blockIdx.x * EB;
    int t  = threadIdx.x;
    for (int idx = t; idx < EB * N_RBF; idx += 128) {
        int a = idx / N_RBF, r = idx % N_RBF;
        ps[r][a] = g_phif[(size_t)(e0 + a) * N_RBF + r];
    }
    if (t < EB) {
        fcs[t] = g_fc[e0 + t];
        slots[t] = g_slot[e0 + t];
    }
    __syncthreads();

    u64 fcp[EB / 2];
    int slt[EB];
    #pragma unroll
    for (int p = 0; p < EB / 2; p++) fcp[p] = pk2(fcs[2 * p], fcs[2 * p + 1]);
    #pragma unroll
    for (int a = 0; a < EB; a++) slt[a] = slots[a];

    #pragma unroll 1
    for (int grp = 0; grp < NF / 128; grp++) {
        int c = grp * 128 + t;
        float bias = fb[c];
        u64 bp = pk2(bias, bias);
        u64 acc[EB / 2];
        #pragma unroll
        for (int p = 0; p < EB / 2; p++) acc[p] = mul2v(fcp[p], bp);
        #pragma unroll
        for (int r = 0; r < N_RBF; r++) {
            float w = fW[r * NF + c];
            u64 wp = pk2(w, w);
            const u64* pr = (const u64*)&ps[r][0];
            #pragma unroll
            for (int p = 0; p < EB / 2; p++) acc[p] = fma2v(pr[p], wp, acc[p]);
        }
        #pragma unroll
        for (int p = 0; p < EB / 2; p++) {
            float2 f = upk2(acc[p]);
            g_filt[(size_t)slt[2 * p] * NF + c]     = __float2half_rn(f.x);
            g_filt[(size_t)slt[2 * p + 1] * NF + c] = __float2half_rn(f.y);
        }
    }
}

// ---------------- per-atom input MLP (iterations 1,2) ------------------------
__global__ void __launch_bounds__(128) k_atoms_x(
        const float* __restrict__ ic1W, const float* __restrict__ ic1b,
        const float* __restrict__ ic2W, const float* __restrict__ ic2b,
        int it) {
    __shared__ __align__(16) float qs[NB][PX];
    __shared__ __align__(16) float hs[NB][PX];
    int t  = threadIdx.x;
    int a0 = blockIdx.x * TX;

    #pragma unroll
    for (int a = 0; a < TX; a++)
        qs[t][a] = g_q[(size_t)(a0 + a) * NB + t];
    __syncthreads();

    const float* W1 = ic1W + (size_t)it * NB * NB;
    float b1 = ic1b[it * NB + t];
    u64 acc[TX / 2];
    u64 b1p = pk2(b1, b1);
    #pragma unroll
    for (int p = 0; p < TX / 2; p++) acc[p] = b1p;
    for (int k = 0; k < NB; k++) {
        float w = W1[k * NB + t];
        u64 wp = pk2(w, w);
        const ulonglong2* q2 = (const ulonglong2*)&qs[k][0];
        #pragma unroll
        for (int p4 = 0; p4 < TX / 4; p4++) {
            ulonglong2 u = q2[p4];
            acc[2 * p4]     = fma2v(u.x, wp, acc[2 * p4]);
            acc[2 * p4 + 1] = fma2v(u.y, wp, acc[2 * p4 + 1]);
        }
    }
    #pragma unroll
    for (int p = 0; p < TX / 2; p++) {
        float2 f = upk2(acc[p]);
        hs[t][2 * p]     = silu_f(f.x);
        hs[t][2 * p + 1] = silu_f(f.y);
    }
    __syncthreads();

    const float* W2 = ic2W + (size_t)it * NB * 3 * NB;
    float b20 = ic2b[it * 3 * NB + t];
    float b21 = ic2b[it * 3 * NB + NB + t];
    float b22 = ic2b[it * 3 * NB + 2 * NB + t];
    u64 c0[TX / 2], c1[TX / 2], c2[TX / 2];
    u64 b20p = pk2(b20, b20), b21p = pk2(b21, b21), b22p = pk2(b22, b22);
    #pragma unroll
    for (int p = 0; p < TX / 2; p++) { c0[p] = b20p; c1[p] = b21p; c2[p] = b22p; }
    for (int k = 0; k < NB; k++) {
        float w0 = W2[k * 384 + t];
        float w1 = W2[k * 384 + NB + t];
        float w2 = W2[k * 384 + 2 * NB + t];
        u64 w0p = pk2(w0, w0), w1p = pk2(w1, w1), w2p = pk2(w2, w2);
        const ulonglong2* h2 = (const ulonglong2*)&hs[k][0];
        #pragma unroll
        for (int p4 = 0; p4 < TX / 4; p4++) {
            ulonglong2 u = h2[p4];
            c0[2 * p4]     = fma2v(u.x, w0p, c0[2 * p4]);
            c0[2 * p4 + 1] = fma2v(u.y, w0p, c0[2 * p4 + 1]);
            c1[2 * p4]     = fma2v(u.x, w1p, c1[2 * p4]);
            c1[2 * p4 + 1] = fma2v(u.y, w1p, c1[2 * p4 + 1]);
            c2[2 * p4]     = fma2v(u.x, w2p, c2[2 * p4]);
            c2[2 * p4 + 1] = fma2v(u.y, w2p, c2[2 * p4 + 1]);
        }
    }
    #pragma unroll
    for (int p = 0; p < TX / 2; p++) {
        float2 f0 = upk2(c0[p]);
        float2 f1 = upk2(c1[p]);
        float2 f2 = upk2(c2[p]);
        size_t ga = (size_t)(a0 + 2 * p) * 384;
        size_t gb = (size_t)(a0 + 2 * p + 1) * 384;
        g_x[ga + t] = f0.x;           g_x[gb + t] = f0.y;
        g_x[ga + NB + t] = f1.x;      g_x[gb + NB + t] = f1.y;
        g_x[ga + 2 * NB + t] = f2.x;  g_x[gb + 2 * NB + t] = f2.y;
    }
}

// ---------------- edge gather: warp per atom (R6 best-measured form) ---------
template <int HAS_MU>
__global__ void __launch_bounds__(256) k_gather(int it) {
    int warp = threadIdx.x >> 5;
    int lane = threadIdx.x & 31;
    int i = blockIdx.x * 8 + warp;
    int beg = g_ofs[i], end = g_ofs[i + 1];

    u64 mq0 = 0, mq1 = 0;
    u64 m0a = 0, m0b = 0, m1a = 0, m1b = 0, m2a = 0, m2b = 0;

    const int itofs = it * 384;   // in half units
    int j = 0; float4 d4 = make_float4(0,0,0,0);
    if (beg < end) { j = __ldg(g_pj + beg); d4 = g_pdir[beg]; }

    for (int k = beg; k < end; k++) {
        int jn = 0; float4 dn = d4;
        if (k + 1 < end) { jn = __ldg(g_pj + k + 1); dn = g_pdir[k + 1]; }

        const uint2* fe = (const uint2*)(g_filt + (size_t)k * NF + itofs);
        uint2 f0 = fe[lane];
        uint2 f1 = fe[32 + lane];
        uint2 f2 = fe[64 + lane];
        const ulonglong2* xr = (const ulonglong2*)(g_x + (size_t)j * 384);
        ulonglong2 x0 = xr[lane];
        ulonglong2 x1 = xr[32 + lane];
        ulonglong2 x2 = xr[64 + lane];
        ulonglong2 u0, u1, u2;
        if (HAS_MU) {
            const ulonglong2* mr = (const ulonglong2*)(g_mu + (size_t)j * 384);
            u0 = mr[lane];
            u1 = mr[32 + lane];
            u2 = mr[64 + lane];
        }

        u64 w0x = h2f2(f0.x), w0y = h2f2(f0.y);
        u64 w1x = h2f2(f1.x), w1y = h2f2(f1.y);
        u64 w2x = h2f2(f2.x), w2y = h2f2(f2.y);

        mq0 = fma2v(w0x, x0.x, mq0);
        mq1 = fma2v(w0y, x0.y, mq1);
        u64 vR0 = mul2v(w1x, x1.x), vR1 = mul2v(w1y, x1.y);
        u64 vM0 = mul2v(w2x, x2.x), vM1 = mul2v(w2y, x2.y);
        u64 dxp = pk2(d4.x, d4.x), dyp = pk2(d4.y, d4.y), dzp = pk2(d4.z, d4.z);
        if (HAS_MU) {
            m0a = fma2v(vR0, dxp, fma2v(vM0, u0.x, m0a));
            m0b = fma2v(vR1, dxp, fma2v(vM1, u0.y, m0b));
            m1a = fma2v(vR0, dyp, fma2v(vM0, u1.x, m1a));
            m1b = fma2v(vR1, dyp, fma2v(vM1, u1.y, m1b));
            m2a = fma2v(vR0, dzp, fma2v(vM0, u2.x, m2a));
            m2b = fma2v(vR1, dzp, fma2v(vM1, u2.y, m2b));
        } else {
            m0a = fma2v(vR0, dxp, m0a);
            m0b = fma2v(vR1, dxp, m0b);
            m1a = fma2v(vR0, dyp, m1a);
            m1b = fma2v(vR1, dyp, m1b);
            m2a = fma2v(vR0, dzp, m2a);
            m2b = fma2v(vR1, dzp, m2b);
        }
        j = jn; d4 = dn;
    }
    ulonglong2 o;
    o.x = mq0; o.y = mq1;
    ((ulonglong2*)(g_dq + (size_t)i * NB))[lane] = o;
    ulonglong2* dmu = (ulonglong2*)(g_dmu + (size_t)i * 3 * NB);
    o.x = m0a; o.y = m0b; dmu[lane]      = o;
    o.x = m1a; o.y = m1b; dmu[32 + lane] = o;
    o.x = m2a; o.y = m2b; dmu[64 + lane] = o;
}

// ---------------- per-atom update (f32x2 packed atom pairs) ------------------
__global__ void __launch_bounds__(128) k_atoms_update(
        const float* __restrict__ mixW,
        const float* __restrict__ c1W, const float* __restrict__ c1b,
        const float* __restrict__ c2W, const float* __restrict__ c2b,
        int it, int last, float* __restrict__ mu_out) {
    __shared__ __align__(16) float mus[NB][3][PU];     // [k][d][a]
    __shared__ __align__(16) float ctxs[2 * NB][PU];   // [k][a]
    __shared__ __align__(16) float hs[NB][PU];         // [k][a]
    int t  = threadIdx.x;
    int a0 = blockIdx.x * TU;

    float qreg[TU];
    #pragma unroll
    for (int a = 0; a < TU; a++) {
        size_t g = (size_t)(a0 + a);
        qreg[a] = g_q[g * NB + t] + g_dq[g * NB + t];
        ctxs[t][a] = qreg[a];
        #pragma unroll
        for (int d = 0; d < 3; d++)
            mus[t][d][a] = g_mu[g * 3 * NB + d * NB + t] + g_dmu[g * 3 * NB + d * NB + t];
    }
    __syncthreads();

    const float* MW = mixW + (size_t)it * NB * 2 * NB;
    u64 v2[TU / 2][3], w2[TU / 2][3];
    #pragma unroll
    for (int p = 0; p < TU / 2; p++)
        #pragma unroll
        for (int d = 0; d < 3; d++) { v2[p][d] = 0; w2[p][d] = 0; }
    for (int k = 0; k < NB; k++) {
        float wv = MW[k * 256 + t];
        float ww = MW[k * 256 + NB + t];
        u64 wvp = pk2(wv, wv), wwp = pk2(ww, ww);
        #pragma unroll
        for (int d = 0; d < 3; d++) {
            const ulonglong2* m2 = (const ulonglong2*)&mus[k][d][0];
            ulonglong2 ua = m2[0];
            ulonglong2 ub = m2[1];
            v2[0][d] = fma2v(ua.x, wvp, v2[0][d]);
            v2[1][d] = fma2v(ua.y, wvp, v2[1][d]);
            v2[2][d] = fma2v(ub.x, wvp, v2[2][d]);
            v2[3][d] = fma2v(ub.y, wvp, v2[3][d]);
            w2[0][d] = fma2v(ua.x, wwp, w2[0][d]);
            w2[1][d] = fma2v(ua.y, wwp, w2[1][d]);
            w2[2][d] = fma2v(ub.x, wwp, w2[2][d]);
            w2[3][d] = fma2v(ub.y, wwp, w2[3][d]);
        }
    }
    float v[TU][3], w[TU][3];
    #pragma unroll
    for (int p = 0; p < TU / 2; p++)
        #pragma unroll
        for (int d = 0; d < 3; d++) {
            float2 fv = upk2(v2[p][d]);
            float2 fw = upk2(w2[p][d]);
            v[2 * p][d] = fv.x; v[2 * p + 1][d] = fv.y;
            w[2 * p][d] = fw.x; w[2 * p + 1][d] = fw.y;
        }
    float s[TU];
    #pragma unroll
    for (int a = 0; a < TU; a++) {
        float n2 = v[a][0]*v[a][0] + v[a][1]*v[a][1] + v[a][2]*v[a][2];
        float vn = sqrtf(n2 + EPSV);
        s[a] = v[a][0]*w[a][0] + v[a][1]*w[a][1] + v[a][2]*w[a][2];
        ctxs[NB + t][a] = vn;
    }
    __syncthreads();

    const float* W1 = c1W + (size_t)it * 2 * NB * NB;
    float b1 = c1b[it * NB + t];
    u64 acc[TU / 2];
    u64 b1p = pk2(b1, b1);
    #pragma unroll
    for (int p = 0; p < TU / 2; p++) acc[p] = b1p;
    for (int k = 0; k < 2 * NB; k++) {
        float ww1 = W1[k * NB + t];
        u64 wp = pk2(ww1, ww1);
        const ulonglong2* c2p = (const ulonglong2*)&ctxs[k][0];
        ulonglong2 ca = c2p[0], cb = c2p[1];
        acc[0] = fma2v(ca.x, wp, acc[0]);
        acc[1] = fma2v(ca.y, wp, acc[1]);
        acc[2] = fma2v(cb.x, wp, acc[2]);
        acc[3] = fma2v(cb.y, wp, acc[3]);
    }
    #pragma unroll
    for (int p = 0; p < TU / 2; p++) {
        float2 f = upk2(acc[p]);
        hs[t][2 * p]     = silu_f(f.x);
        hs[t][2 * p + 1] = silu_f(f.y);
    }
    __syncthreads();

    const float* W2 = c2W + (size_t)it * NB * 3 * NB;
    float b20 = c2b[it * 3 * NB + t];
    float b21 = c2b[it * 3 * NB + NB + t];
    float b22 = c2b[it * 3 * NB + 2 * NB + t];
    u64 aq2[TU / 2], am2[TU / 2], aqm2[TU / 2];
    u64 b20p = pk2(b20, b20), b21p = pk2(b21, b21), b22p = pk2(b22, b22);
    #pragma unroll
    for (int p = 0; p < TU / 2; p++) { aq2[p] = b20p; am2[p] = b21p; aqm2[p] = b22p; }
    for (int k = 0; k < NB; k++) {
        float w0 = W2[k * 384 + t];
        float w1 = W2[k * 384 + NB + t];
        float w2w = W2[k * 384 + 2 * NB + t];
        u64 w0p = pk2(w0, w0), w1p = pk2(w1, w1), w2p = pk2(w2w, w2w);
        const ulonglong2* h2 = (const ulonglong2*)&hs[k][0];
        ulonglong2 ha = h2[0], hb = h2[1];
        aq2[0]  = fma2v(ha.x, w0p, aq2[0]);
        aq2[1]  = fma2v(ha.y, w0p, aq2[1]);
        aq2[2]  = fma2v(hb.x, w0p, aq2[2]);
        aq2[3]  = fma2v(hb.y, w0p, aq2[3]);
        am2[0]  = fma2v(ha.x, w1p, am2[0]);
        am2[1]  = fma2v(ha.y, w1p, am2[1]);
        am2[2]  = fma2v(hb.x, w1p, am2[2]);
        am2[3]  = fma2v(hb.y, w1p, am2[3]);
        aqm2[0] = fma2v(ha.x, w2p, aqm2[0]);
        aqm2[1] = fma2v(ha.y, w2p, aqm2[1]);
        aqm2[2] = fma2v(hb.x, w2p, aqm2[2]);
        aqm2[3] = fma2v(hb.y, w2p, aqm2[3]);
    }
    float aq[TU], am[TU], aqm[TU];
    #pragma unroll
    for (int p = 0; p < TU / 2; p++) {
        float2 f0 = upk2(aq2[p]);
        float2 f1 = upk2(am2[p]);
        float2 f2 = upk2(aqm2[p]);
        aq[2 * p] = f0.x;  aq[2 * p + 1] = f0.y;
        am[2 * p] = f1.x;  am[2 * p + 1] = f1.y;
        aqm[2 * p] = f2.x; aqm[2 * p + 1] = f2.y;
    }
    #pragma unroll
    for (int a = 0; a < TU; a++) {
        size_t g = (size_t)(a0 + a);
        g_q[g * NB + t] = qreg[a] + aq[a] + aqm[a] * s[a];
        #pragma unroll
        for (int d = 0; d < 3; d++) {
            float val = mus[t][d][a] + am[a] * w[a][d];
            g_mu[g * 3 * NB + d * NB + t] = val;
            if (last) mu_out[g * 3 * NB + d * NB + t] = val;
        }
    }
}

// ---------------- output head ----------------
__global__ void __launch_bounds__(128) k_head(
        const float* __restrict__ o1W, const float* __restrict__ o1b,
        const float* __restrict__ o2W, const float* __restrict__ o2b,
        const float* __restrict__ o3W, const float* __restrict__ o3b,
        const int* __restrict__ idx_m, float* __restrict__ y) {
    __shared__ float qs[TH][NB];
    __shared__ float h1[TH][NB];
    __shared__ float h2[TH][NB];
    int t  = threadIdx.x;
    int a0 = blockIdx.x * TH;
    #pragma unroll
    for (int a = 0; a < TH; a++) qs[a][t] = g_q[(size_t)(a0 + a) * NB + t];
    __syncthreads();

    float acc[TH];
    float b = o1b[t];
    #pragma unroll
    for (int a = 0; a < TH; a++) acc[a] = b;
    for (int k = 0; k < NB; k++) {
        float w = o1W[k * NB + t];
        #pragma unroll
        for (int a = 0; a < TH; a++) acc[a] += qs[a][k] * w;
    }
    #pragma unroll
    for (int a = 0; a < TH; a++) h1[a][t] = silu_f(acc[a]);
    __syncthreads();

    b = o2b[t];
    #pragma unroll
    for (int a = 0; a < TH; a++) acc[a] = b;
    for (int k = 0; k < NB; k++) {
        float w = o2W[k * NB + t];
        #pragma unroll
        for (int a = 0; a < TH; a++) acc[a] += h1[a][k] * w;
    }
    #pragma unroll
    for (int a = 0; a < TH; a++) h2[a][t] = silu_f(acc[a]);
    __syncthreads();

    if (t < TH) {
        float sum = o3b[0];
        for (int k = 0; k < NB; k++) sum += h2[t][k] * o3W[k];
        atomicAdd(&y[idx_m[a0 + t]], sum);
    }
}

// ---------------- launch ----------------
extern "C" void kernel_launch(void* const* d_in, const int* in_sizes, int n_in,
                              void* d_out, int out_size) {
    const float* positions = (const float*)d_in[0];
    const float* emb  = (const float*)d_in[1];
    const float* fW   = (const float*)d_in[2];
    const float* fb   = (const float*)d_in[3];
    const float* ic1W = (const float*)d_in[4];
    const float* ic1b = (const float*)d_in[5];
    const float* ic2W = (const float*)d_in[6];
    const float* ic2b = (const float*)d_in[7];
    const float* mixW = (const float*)d_in[8];
    const float* c1W  = (const float*)d_in[9];
    const float* c1b  = (const float*)d_in[10];
    const float* c2W  = (const float*)d_in[11];
    const float* c2b  = (const float*)d_in[12];
    const float* o1W  = (const float*)d_in[13];
    const float* o1b  = (const float*)d_in[14];
    const float* o2W  = (const float*)d_in[15];
    const float* o2b  = (const float*)d_in[16];
    const float* o3W  = (const float*)d_in[17];
    const float* o3b  = (const float*)d_in[18];
    const int* z      = (const int*)d_in[19];
    const int* idx_i  = (const int*)d_in[20];
    const int* idx_j  = (const int*)d_in[21];
    const int* idx_m  = (const int*)d_in[22];
    float* out = (float*)d_out;   // layout: y[64], then mu[10000*3*128]

    // launch 0: it=0 atom MLP + q/mu init + cnt/y zero (independent)
    k_atoms_x0<<<N_ATOMS / TX, 128>>>(emb, z, ic1W, ic1b, ic2W, ic2b, out);
    // launch 1: edge geometry + histogram
    k_init_edges<<<(N_EDGES + 255) / 256, 256>>>(positions, idx_i, idx_j);
    // launch 2-4: CSR + filters
    k_scan<<<1, 1024>>>();
    k_fill<<<(N_EDGES + 255) / 256, 256>>>(idx_i, idx_j);
    k_filters<<<N_EDGES / EB, 128>>>(fW, fb);
    // launch 5: gather it=0  (ncu -s 5 capture target)
    k_gather<0><<<N_ATOMS / 8, 256>>>(0);
    k_atoms_update<<<N_ATOMS / TU, 128>>>(mixW, c1W, c1b, c2W, c2b, 0, 0, out + BATCH);

    for (int it = 1; it < NI; it++) {
        k_atoms_x<<<N_ATOMS / TX, 128>>>(ic1W, ic1b, ic2W, ic2b, it);
        k_gather<1><<<N_ATOMS / 8, 256>>>(it);
        k_atoms_update<<<N_ATOMS / TU, 128>>>(mixW, c1W, c1b, c2W, c2b,
                                              it, it == NI - 1, out + BATCH);
    }

    k_head<<<N_ATOMS / TH, 128>>>(o1W, o1b, o2W, o2b, o3W, o3b, idx_m, out);
}

// round 14
// speedup vs baseline: 2.5492x; 1.0234x over previous
#include <cuda_runtime.h>
#include <cuda_fp16.h>
#include <math.h>

#define N_ATOMS 10000
#define N_EDGES 150000
#define NB 128
#define NI 3
#define NF (NI * 3 * NB)     // 1152 filter cols
#define N_RBF 20
#define CUTOFF 5.0f
#define EPSV 1e-8f
#define BATCH 64
#define EB 8                 // edges per filter-precompute block
#define TX 16                // atoms per block, k_atoms_x
#define PX 20                // padded row for TX
#define TU 8                 // atoms per block, k_atoms_update
#define PU 12                // padded row for TU
#define TH 8                 // atoms per block, k_head

typedef unsigned long long u64;

// ---------------- device scratch (static, no allocation) ----------------
__device__ float  g_q   [N_ATOMS * NB];
__device__ __align__(16) float g_mu [N_ATOMS * 3 * NB];
__device__ __align__(16) float g_x  [N_ATOMS * 3 * NB];
__device__ float  g_dq  [N_ATOMS * NB];
__device__ float  g_dmu [N_ATOMS * 3 * NB];
__device__ float  g_phif[N_EDGES * N_RBF];
__device__ float  g_fc  [N_EDGES];
__device__ float4 g_dir4[N_EDGES];
__device__ __align__(16) __half g_filt[(size_t)N_EDGES * NF]; // filters fp16, CSR-slot order
// CSR by destination atom (idx_i)
__device__ int    g_cnt [N_ATOMS];
__device__ int    g_ofs [N_ATOMS + 1];
__device__ int    g_cur [N_ATOMS];
__device__ int    g_slot[N_EDGES];
__device__ int    g_pj  [N_EDGES];
__device__ float4 g_pdir[N_EDGES];

// ---------------- packed f32x2 helpers (FFMA2 path, sm_103a) ----------------
__device__ __forceinline__ u64 pk2(float lo, float hi) {
    u64 r; asm("mov.b64 %0, {%1, %2};" : "=l"(r) : "f"(lo), "f"(hi)); return r;
}
__device__ __forceinline__ float2 upk2(u64 v) {
    float2 f; asm("mov.b64 {%0, %1}, %2;" : "=f"(f.x), "=f"(f.y) : "l"(v)); return f;
}
__device__ __forceinline__ u64 fma2v(u64 a, u64 b, u64 c) {
    u64 d; asm("fma.rn.f32x2 %0, %1, %2, %3;" : "=l"(d) : "l"(a), "l"(b), "l"(c)); return d;
}
__device__ __forceinline__ u64 mul2v(u64 a, u64 b) {
    u64 d; asm("mul.rn.f32x2 %0, %1, %2;" : "=l"(d) : "l"(a), "l"(b)); return d;
}
// half2 (as uint) -> packed f32x2
__device__ __forceinline__ u64 h2f2(unsigned h) {
    float2 f = __half22float2(*reinterpret_cast<__half2*>(&h));
    return pk2(f.x, f.y);
}

__device__ __forceinline__ float silu_f(float v) {
    return v / (1.0f + expf(-v));
}

// ---------------- edge geometry precompute ----------------
__global__ void k_init_edges(const float* __restrict__ pos,
                             const int* __restrict__ idx_i,
                             const int* __restrict__ idx_j) {
    int e = blockIdx.x * blockDim.x + threadIdx.x;
    if (e >= N_EDGES) return;
    int i = idx_i[e], j = idx_j[e];
    float rx = pos[j * 3 + 0] - pos[i * 3 + 0];
    float ry = pos[j * 3 + 1] - pos[i * 3 + 1];
    float rz = pos[j * 3 + 2] - pos[i * 3 + 2];
    float d  = sqrtf(rx * rx + ry * ry + rz * rz);
    float inv = 1.0f / d;
    g_dir4[e] = make_float4(rx * inv, ry * inv, rz * inv, 0.0f);
    float fc = (d < CUTOFF) ? 0.5f * (cosf(d * (float)M_PI / CUTOFF) + 1.0f) : 0.0f;
    g_fc[e] = fc;
    const float width = CUTOFF / (float)(N_RBF - 1);
    const float coeff = -0.5f / (width * width);
    #pragma unroll
    for (int r = 0; r < N_RBF; r++) {
        float dd = d - (float)r * width;
        g_phif[e * N_RBF + r] = expf(coeff * dd * dd) * fc;
    }
}

// ---------------- CSR build ----------------
__global__ void k_zero_cnt() {
    int a = blockIdx.x * blockDim.x + threadIdx.x;
    if (a < N_ATOMS) g_cnt[a] = 0;
}
__global__ void k_hist(const int* __restrict__ idx_i) {
    int e = blockIdx.x * blockDim.x + threadIdx.x;
    if (e < N_EDGES) atomicAdd(&g_cnt[idx_i[e]], 1);
}
__global__ void __launch_bounds__(1024) k_scan() {
    __shared__ int partial[1024];
    int t = threadIdx.x;
    int base = t * 10;
    int local[10];
    int s = 0;
    #pragma unroll
    for (int k = 0; k < 10; k++) {
        int idx = base + k;
        int c = (idx < N_ATOMS) ? g_cnt[idx] : 0;
        local[k] = s;
        s += c;
    }
    partial[t] = s;
    __syncthreads();
    for (int off = 1; off < 1024; off <<= 1) {
        int v = partial[t];
        int u = (t >= off) ? partial[t - off] : 0;
        __syncthreads();
        partial[t] = v + u;
        __syncthreads();
    }
    int pre = (t > 0) ? partial[t - 1] : 0;
    #pragma unroll
    for (int k = 0; k < 10; k++) {
        int idx = base + k;
        if (idx < N_ATOMS) {
            int o = pre + local[k];
            g_ofs[idx] = o;
            g_cur[idx] = o;
        }
    }
    if (t == 1023) g_ofs[N_ATOMS] = partial[1023];
}
__global__ void k_fill(const int* __restrict__ idx_i,
                       const int* __restrict__ idx_j) {
    int e = blockIdx.x * blockDim.x + threadIdx.x;
    if (e < N_EDGES) {
        int pos = atomicAdd(&g_cur[idx_i[e]], 1);
        g_slot[e] = pos;
        g_pj[pos] = idx_j[e];
        g_pdir[pos] = g_dir4[e];
    }
}

// ---------------- dense filter precompute into CSR-slot rows (fp16, f32x2) ---
__global__ void __launch_bounds__(128) k_filters(const float* __restrict__ fW,
                                                 const float* __restrict__ fb) {
    __shared__ __align__(16) float ps[N_RBF][EB];   // [r][edge]
    __shared__ float fcs[EB];
    __shared__ int   slots[EB];
    int e0 = blockIdx.x * EB;
    int t  = threadIdx.x;
    for (int idx = t; idx < EB * N_RBF; idx += 128) {
        int a = idx / N_RBF, r = idx % N_RBF;
        ps[r][a] = g_phif[(size_t)(e0 + a) * N_RBF + r];
    }
    if (t < EB) {
        fcs[t] = g_fc[e0 + t];
        slots[t] = g_slot[e0 + t];
    }
    __syncthreads();

    u64 fcp[EB / 2];
    int slt[EB];
    #pragma unroll
    for (int p = 0; p < EB / 2; p++) fcp[p] = pk2(fcs[2 * p], fcs[2 * p + 1]);
    #pragma unroll
    for (int a = 0; a < EB; a++) slt[a] = slots[a];

    #pragma unroll 1
    for (int grp = 0; grp < NF / 128; grp++) {
        int c = grp * 128 + t;
        float bias = fb[c];
        u64 bp = pk2(bias, bias);
        u64 acc[EB / 2];
        #pragma unroll
        for (int p = 0; p < EB / 2; p++) acc[p] = mul2v(fcp[p], bp);
        #pragma unroll
        for (int r = 0; r < N_RBF; r++) {
            float w = fW[r * NF + c];
            u64 wp = pk2(w, w);
            const u64* pr = (const u64*)&ps[r][0];
            #pragma unroll
            for (int p = 0; p < EB / 2; p++) acc[p] = fma2v(pr[p], wp, acc[p]);
        }
        #pragma unroll
        for (int p = 0; p < EB / 2; p++) {
            float2 f = upk2(acc[p]);
            g_filt[(size_t)slt[2 * p] * NF + c]     = __float2half_rn(f.x);
            g_filt[(size_t)slt[2 * p + 1] * NF + c] = __float2half_rn(f.y);
        }
    }
}

// ---------------- atom init ----------------
__global__ void k_init_atoms(const float* __restrict__ emb,
                             const int* __restrict__ z,
                             float* __restrict__ y_out) {
    int a = blockIdx.x;
    int t = threadIdx.x;
    g_q[a * NB + t] = emb[z[a] * NB + t];
    #pragma unroll
    for (int d = 0; d < 3; d++)
        g_mu[a * 3 * NB + d * NB + t] = 0.0f;
    if (a == 0 && t < BATCH) y_out[t] = 0.0f;
}

// ---------------- per-atom input MLP (f32x2 packed atom pairs) ---------------
__global__ void __launch_bounds__(128) k_atoms_x(
        const float* __restrict__ ic1W, const float* __restrict__ ic1b,
        const float* __restrict__ ic2W, const float* __restrict__ ic2b,
        int it) {
    __shared__ __align__(16) float qs[NB][PX];
    __shared__ __align__(16) float hs[NB][PX];
    int t  = threadIdx.x;
    int a0 = blockIdx.x * TX;

    #pragma unroll
    for (int a = 0; a < TX; a++)
        qs[t][a] = g_q[(size_t)(a0 + a) * NB + t];
    __syncthreads();

    const float* W1 = ic1W + (size_t)it * NB * NB;
    float b1 = ic1b[it * NB + t];
    u64 acc[TX / 2];
    u64 b1p = pk2(b1, b1);
    #pragma unroll
    for (int p = 0; p < TX / 2; p++) acc[p] = b1p;
    for (int k = 0; k < NB; k++) {
        float w = W1[k * NB + t];
        u64 wp = pk2(w, w);
        const ulonglong2* q2 = (const ulonglong2*)&qs[k][0];
        #pragma unroll
        for (int p4 = 0; p4 < TX / 4; p4++) {
            ulonglong2 u = q2[p4];
            acc[2 * p4]     = fma2v(u.x, wp, acc[2 * p4]);
            acc[2 * p4 + 1] = fma2v(u.y, wp, acc[2 * p4 + 1]);
        }
    }
    #pragma unroll
    for (int p = 0; p < TX / 2; p++) {
        float2 f = upk2(acc[p]);
        hs[t][2 * p]     = silu_f(f.x);
        hs[t][2 * p + 1] = silu_f(f.y);
    }
    __syncthreads();

    const float* W2 = ic2W + (size_t)it * NB * 3 * NB;
    float b20 = ic2b[it * 3 * NB + t];
    float b21 = ic2b[it * 3 * NB + NB + t];
    float b22 = ic2b[it * 3 * NB + 2 * NB + t];
    u64 c0[TX / 2], c1[TX / 2], c2[TX / 2];
    u64 b20p = pk2(b20, b20), b21p = pk2(b21, b21), b22p = pk2(b22, b22);
    #pragma unroll
    for (int p = 0; p < TX / 2; p++) { c0[p] = b20p; c1[p] = b21p; c2[p] = b22p; }
    for (int k = 0; k < NB; k++) {
        float w0 = W2[k * 384 + t];
        float w1 = W2[k * 384 + NB + t];
        float w2 = W2[k * 384 + 2 * NB + t];
        u64 w0p = pk2(w0, w0), w1p = pk2(w1, w1), w2p = pk2(w2, w2);
        const ulonglong2* h2 = (const ulonglong2*)&hs[k][0];
        #pragma unroll
        for (int p4 = 0; p4 < TX / 4; p4++) {
            ulonglong2 u = h2[p4];
            c0[2 * p4]     = fma2v(u.x, w0p, c0[2 * p4]);
            c0[2 * p4 + 1] = fma2v(u.y, w0p, c0[2 * p4 + 1]);
            c1[2 * p4]     = fma2v(u.x, w1p, c1[2 * p4]);
            c1[2 * p4 + 1] = fma2v(u.y, w1p, c1[2 * p4 + 1]);
            c2[2 * p4]     = fma2v(u.x, w2p, c2[2 * p4]);
            c2[2 * p4 + 1] = fma2v(u.y, w2p, c2[2 * p4 + 1]);
        }
    }
    #pragma unroll
    for (int p = 0; p < TX / 2; p++) {
        float2 f0 = upk2(c0[p]);
        float2 f1 = upk2(c1[p]);
        float2 f2 = upk2(c2[p]);
        size_t ga = (size_t)(a0 + 2 * p) * 384;
        size_t gb = (size_t)(a0 + 2 * p + 1) * 384;
        g_x[ga + t] = f0.x;           g_x[gb + t] = f0.y;
        g_x[ga + NB + t] = f1.x;      g_x[gb + NB + t] = f1.y;
        g_x[ga + 2 * NB + t] = f2.x;  g_x[gb + 2 * NB + t] = f2.y;
    }
}

// ---------------- edge gather: TWO warps per destination atom ----------------
// Each warp accumulates half of the atom's edge range (halving the serial
// per-warp edge chain); partial sums are combined through shared memory.
template <int HAS_MU>
__global__ void __launch_bounds__(256) k_gather(int it) {
    __shared__ __align__(16) float sm[4][4 * NB];   // 4 atoms x (dq,m0,m1,m2) x 128
    int warp = threadIdx.x >> 5;
    int lane = threadIdx.x & 31;
    int a    = warp >> 1;          // atom slot 0..3
    int half = warp & 1;
    int i = blockIdx.x * 4 + a;
    int beg0 = g_ofs[i], end0 = g_ofs[i + 1];
    int len  = end0 - beg0;
    int mid  = beg0 + ((len + 1) >> 1);
    int beg  = half ? mid : beg0;
    int end  = half ? end0 : mid;

    u64 mq0 = 0, mq1 = 0;
    u64 m0a = 0, m0b = 0, m1a = 0, m1b = 0, m2a = 0, m2b = 0;

    const int itofs = it * 384;   // in half units
    int j = 0; float4 d4 = make_float4(0,0,0,0);
    if (beg < end) { j = __ldg(g_pj + beg); d4 = g_pdir[beg]; }

    for (int k = beg; k < end; k++) {
        int jn = 0; float4 dn = d4;
        if (k + 1 < end) { jn = __ldg(g_pj + k + 1); dn = g_pdir[k + 1]; }

        const uint2* fe = (const uint2*)(g_filt + (size_t)k * NF + itofs);
        uint2 f0 = fe[lane];
        uint2 f1 = fe[32 + lane];
        uint2 f2 = fe[64 + lane];
        const ulonglong2* xr = (const ulonglong2*)(g_x + (size_t)j * 384);
        ulonglong2 x0 = xr[lane];
        ulonglong2 x1 = xr[32 + lane];
        ulonglong2 x2 = xr[64 + lane];
        ulonglong2 u0, u1, u2;
        if (HAS_MU) {
            const ulonglong2* mr = (const ulonglong2*)(g_mu + (size_t)j * 384);
            u0 = mr[lane];
            u1 = mr[32 + lane];
            u2 = mr[64 + lane];
        }

        u64 w0x = h2f2(f0.x), w0y = h2f2(f0.y);
        u64 w1x = h2f2(f1.x), w1y = h2f2(f1.y);
        u64 w2x = h2f2(f2.x), w2y = h2f2(f2.y);

        mq0 = fma2v(w0x, x0.x, mq0);
        mq1 = fma2v(w0y, x0.y, mq1);
        u64 vR0 = mul2v(w1x, x1.x), vR1 = mul2v(w1y, x1.y);
        u64 vM0 = mul2v(w2x, x2.x), vM1 = mul2v(w2y, x2.y);
        u64 dxp = pk2(d4.x, d4.x), dyp = pk2(d4.y, d4.y), dzp = pk2(d4.z, d4.z);
        if (HAS_MU) {
            m0a = fma2v(vR0, dxp, fma2v(vM0, u0.x, m0a));
            m0b = fma2v(vR1, dxp, fma2v(vM1, u0.y, m0b));
            m1a = fma2v(vR0, dyp, fma2v(vM0, u1.x, m1a));
            m1b = fma2v(vR1, dyp, fma2v(vM1, u1.y, m1b));
            m2a = fma2v(vR0, dzp, fma2v(vM0, u2.x, m2a));
            m2b = fma2v(vR1, dzp, fma2v(vM1, u2.y, m2b));
        } else {
            m0a = fma2v(vR0, dxp, m0a);
            m0b = fma2v(vR1, dxp, m0b);
            m1a = fma2v(vR0, dyp, m1a);
            m1b = fma2v(vR1, dyp, m1b);
            m2a = fma2v(vR0, dzp, m2a);
            m2b = fma2v(vR1, dzp, m2b);
        }
        j = jn; d4 = dn;
    }

    // odd warp publishes partials to smem
    ulonglong2* sb = (ulonglong2*)&sm[a][0];
    if (half == 1) {
        ulonglong2 t;
        t.x = mq0; t.y = mq1; sb[lane]      = t;
        t.x = m0a; t.y = m0b; sb[32 + lane] = t;
        t.x = m1a; t.y = m1b; sb[64 + lane] = t;
        t.x = m2a; t.y = m2b; sb[96 + lane] = t;
    }
    __syncthreads();

    if (half == 0) {
        const u64 one = pk2(1.0f, 1.0f);
        ulonglong2 p;
        p = sb[lane];      mq0 = fma2v(p.x, one, mq0); mq1 = fma2v(p.y, one, mq1);
        p = sb[32 + lane]; m0a = fma2v(p.x, one, m0a); m0b = fma2v(p.y, one, m0b);
        p = sb[64 + lane]; m1a = fma2v(p.x, one, m1a); m1b = fma2v(p.y, one, m1b);
        p = sb[96 + lane]; m2a = fma2v(p.x, one, m2a); m2b = fma2v(p.y, one, m2b);

        ulonglong2 o;
        o.x = mq0; o.y = mq1;
        ((ulonglong2*)(g_dq + (size_t)i * NB))[lane] = o;
        ulonglong2* dmu = (ulonglong2*)(g_dmu + (size_t)i * 3 * NB);
        o.x = m0a; o.y = m0b; dmu[lane]      = o;
        o.x = m1a; o.y = m1b; dmu[32 + lane] = o;
        o.x = m2a; o.y = m2b; dmu[64 + lane] = o;
    }
}

// ---------------- per-atom update (f32x2 packed atom pairs) ------------------
__global__ void __launch_bounds__(128) k_atoms_update(
        const float* __restrict__ mixW,
        const float* __restrict__ c1W, const float* __restrict__ c1b,
        const float* __restrict__ c2W, const float* __restrict__ c2b,
        int it, int last, float* __restrict__ mu_out) {
    __shared__ __align__(16) float mus[NB][3][PU];     // [k][d][a]
    __shared__ __align__(16) float ctxs[2 * NB][PU];   // [k][a]
    __shared__ __align__(16) float hs[NB][PU];         // [k][a]
    int t  = threadIdx.x;
    int a0 = blockIdx.x * TU;

    float qreg[TU];
    #pragma unroll
    for (int a = 0; a < TU; a++) {
        size_t g = (size_t)(a0 + a);
        qreg[a] = g_q[g * NB + t] + g_dq[g * NB + t];
        ctxs[t][a] = qreg[a];
        #pragma unroll
        for (int d = 0; d < 3; d++)
            mus[t][d][a] = g_mu[g * 3 * NB + d * NB + t] + g_dmu[g * 3 * NB + d * NB + t];
    }
    __syncthreads();

    const float* MW = mixW + (size_t)it * NB * 2 * NB;
    u64 v2[TU / 2][3], w2[TU / 2][3];
    #pragma unroll
    for (int p = 0; p < TU / 2; p++)
        #pragma unroll
        for (int d = 0; d < 3; d++) { v2[p][d] = 0; w2[p][d] = 0; }
    for (int k = 0; k < NB; k++) {
        float wv = MW[k * 256 + t];
        float ww = MW[k * 256 + NB + t];
        u64 wvp = pk2(wv, wv), wwp = pk2(ww, ww);
        #pragma unroll
        for (int d = 0; d < 3; d++) {
            const ulonglong2* m2 = (const ulonglong2*)&mus[k][d][0];
            ulonglong2 ua = m2[0];
            ulonglong2 ub = m2[1];
            v2[0][d] = fma2v(ua.x, wvp, v2[0][d]);
            v2[1][d] = fma2v(ua.y, wvp, v2[1][d]);
            v2[2][d] = fma2v(ub.x, wvp, v2[2][d]);
            v2[3][d] = fma2v(ub.y, wvp, v2[3][d]);
            w2[0][d] = fma2v(ua.x, wwp, w2[0][d]);
            w2[1][d] = fma2v(ua.y, wwp, w2[1][d]);
            w2[2][d] = fma2v(ub.x, wwp, w2[2][d]);
            w2[3][d] = fma2v(ub.y, wwp, w2[3][d]);
        }
    }
    float v[TU][3], w[TU][3];
    #pragma unroll
    for (int p = 0; p < TU / 2; p++)
        #pragma unroll
        for (int d = 0; d < 3; d++) {
            float2 fv = upk2(v2[p][d]);
            float2 fw = upk2(w2[p][d]);
            v[2 * p][d] = fv.x; v[2 * p + 1][d] = fv.y;
            w[2 * p][d] = fw.x; w[2 * p + 1][d] = fw.y;
        }
    float s[TU];
    #pragma unroll
    for (int a = 0; a < TU; a++) {
        float n2 = v[a][0]*v[a][0] + v[a][1]*v[a][1] + v[a][2]*v[a][2];
        float vn = sqrtf(n2 + EPSV);
        s[a] = v[a][0]*w[a][0] + v[a][1]*w[a][1] + v[a][2]*w[a][2];
        ctxs[NB + t][a] = vn;
    }
    __syncthreads();

    const float* W1 = c1W + (size_t)it * 2 * NB * NB;
    float b1 = c1b[it * NB + t];
    u64 acc[TU / 2];
    u64 b1p = pk2(b1, b1);
    #pragma unroll
    for (int p = 0; p < TU / 2; p++) acc[p] = b1p;
    for (int k = 0; k < 2 * NB; k++) {
        float ww1 = W1[k * NB + t];
        u64 wp = pk2(ww1, ww1);
        const ulonglong2* c2p = (const ulonglong2*)&ctxs[k][0];
        ulonglong2 ca = c2p[0], cb = c2p[1];
        acc[0] = fma2v(ca.x, wp, acc[0]);
        acc[1] = fma2v(ca.y, wp, acc[1]);
        acc[2] = fma2v(cb.x, wp, acc[2]);
        acc[3] = fma2v(cb.y, wp, acc[3]);
    }
    #pragma unroll
    for (int p = 0; p < TU / 2; p++) {
        float2 f = upk2(acc[p]);
        hs[t][2 * p]     = silu_f(f.x);
        hs[t][2 * p + 1] = silu_f(f.y);
    }
    __syncthreads();

    const float* W2 = c2W + (size_t)it * NB * 3 * NB;
    float b20 = c2b[it * 3 * NB + t];
    float b21 = c2b[it * 3 * NB + NB + t];
    float b22 = c2b[it * 3 * NB + 2 * NB + t];
    u64 aq2[TU / 2], am2[TU / 2], aqm2[TU / 2];
    u64 b20p = pk2(b20, b20), b21p = pk2(b21, b21), b22p = pk2(b22, b22);
    #pragma unroll
    for (int p = 0; p < TU / 2; p++) { aq2[p] = b20p; am2[p] = b21p; aqm2[p] = b22p; }
    for (int k = 0; k < NB; k++) {
        float w0 = W2[k * 384 + t];
        float w1 = W2[k * 384 + NB + t];
        float w2w = W2[k * 384 + 2 * NB + t];
        u64 w0p = pk2(w0, w0), w1p = pk2(w1, w1), w2p = pk2(w2w, w2w);
        const ulonglong2* h2 = (const ulonglong2*)&hs[k][0];
        ulonglong2 ha = h2[0], hb = h2[1];
        aq2[0]  = fma2v(ha.x, w0p, aq2[0]);
        aq2[1]  = fma2v(ha.y, w0p, aq2[1]);
        aq2[2]  = fma2v(hb.x, w0p, aq2[2]);
        aq2[3]  = fma2v(hb.y, w0p, aq2[3]);
        am2[0]  = fma2v(ha.x, w1p, am2[0]);
        am2[1]  = fma2v(ha.y, w1p, am2[1]);
        am2[2]  = fma2v(hb.x, w1p, am2[2]);
        am2[3]  = fma2v(hb.y, w1p, am2[3]);
        aqm2[0] = fma2v(ha.x, w2p, aqm2[0]);
        aqm2[1] = fma2v(ha.y, w2p, aqm2[1]);
        aqm2[2] = fma2v(hb.x, w2p, aqm2[2]);
        aqm2[3] = fma2v(hb.y, w2p, aqm2[3]);
    }
    float aq[TU], am[TU], aqm[TU];
    #pragma unroll
    for (int p = 0; p < TU / 2; p++) {
        float2 f0 = upk2(aq2[p]);
        float2 f1 = upk2(am2[p]);
        float2 f2 = upk2(aqm2[p]);
        aq[2 * p] = f0.x;  aq[2 * p + 1] = f0.y;
        am[2 * p] = f1.x;  am[2 * p + 1] = f1.y;
        aqm[2 * p] = f2.x; aqm[2 * p + 1] = f2.y;
    }
    #pragma unroll
    for (int a = 0; a < TU; a++) {
        size_t g = (size_t)(a0 + a);
        g_q[g * NB + t] = qreg[a] + aq[a] + aqm[a] * s[a];
        #pragma unroll
        for (int d = 0; d < 3; d++) {
            float val = mus[t][d][a] + am[a] * w[a][d];
            g_mu[g * 3 * NB + d * NB + t] = val;
            if (last) mu_out[g * 3 * NB + d * NB + t] = val;
        }
    }
}

// ---------------- output head ----------------
__global__ void __launch_bounds__(128) k_head(
        const float* __restrict__ o1W, const float* __restrict__ o1b,
        const float* __restrict__ o2W, const float* __restrict__ o2b,
        const float* __restrict__ o3W, const float* __restrict__ o3b,
        const int* __restrict__ idx_m, float* __restrict__ y) {
    __shared__ float qs[TH][NB];
    __shared__ float h1[TH][NB];
    __shared__ float h2[TH][NB];
    int t  = threadIdx.x;
    int a0 = blockIdx.x * TH;
    #pragma unroll
    for (int a = 0; a < TH; a++) qs[a][t] = g_q[(size_t)(a0 + a) * NB + t];
    __syncthreads();

    float acc[TH];
    float b = o1b[t];
    #pragma unroll
    for (int a = 0; a < TH; a++) acc[a] = b;
    for (int k = 0; k < NB; k++) {
        float w = o1W[k * NB + t];
        #pragma unroll
        for (int a = 0; a < TH; a++) acc[a] += qs[a][k] * w;
    }
    #pragma unroll
    for (int a = 0; a < TH; a++) h1[a][t] = silu_f(acc[a]);
    __syncthreads();

    b = o2b[t];
    #pragma unroll
    for (int a = 0; a < TH; a++) acc[a] = b;
    for (int k = 0; k < NB; k++) {
        float w = o2W[k * NB + t];
        #pragma unroll
        for (int a = 0; a < TH; a++) acc[a] += h1[a][k] * w;
    }
    #pragma unroll
    for (int a = 0; a < TH; a++) h2[a][t] = silu_f(acc[a]);
    __syncthreads();

    if (t < TH) {
        float sum = o3b[0];
        for (int k = 0; k < NB; k++) sum += h2[t][k] * o3W[k];
        atomicAdd(&y[idx_m[a0 + t]], sum);
    }
}

// ---------------- launch ----------------
extern "C" void kernel_launch(void* const* d_in, const int* in_sizes, int n_in,
                              void* d_out, int out_size) {
    const float* positions = (const float*)d_in[0];
    const float* emb  = (const float*)d_in[1];
    const float* fW   = (const float*)d_in[2];
    const float* fb   = (const float*)d_in[3];
    const float* ic1W = (const float*)d_in[4];
    const float* ic1b = (const float*)d_in[5];
    const float* ic2W = (const float*)d_in[6];
    const float* ic2b = (const float*)d_in[7];
    const float* mixW = (const float*)d_in[8];
    const float* c1W  = (const float*)d_in[9];
    const float* c1b  = (const float*)d_in[10];
    const float* c2W  = (const float*)d_in[11];
    const float* c2b  = (const float*)d_in[12];
    const float* o1W  = (const float*)d_in[13];
    const float* o1b  = (const float*)d_in[14];
    const float* o2W  = (const float*)d_in[15];
    const float* o2b  = (const float*)d_in[16];
    const float* o3W  = (const float*)d_in[17];
    const float* o3b  = (const float*)d_in[18];
    const int* z      = (const int*)d_in[19];
    const int* idx_i  = (const int*)d_in[20];
    const int* idx_j  = (const int*)d_in[21];
    const int* idx_m  = (const int*)d_in[22];
    float* out = (float*)d_out;   // layout: y[64], then mu[10000*3*128]

    k_init_edges<<<(N_EDGES + 255) / 256, 256>>>(positions, idx_i, idx_j);
    k_zero_cnt<<<(N_ATOMS + 255) / 256, 256>>>();
    k_hist<<<(N_EDGES + 255) / 256, 256>>>(idx_i);
    k_scan<<<1, 1024>>>();
    k_fill<<<(N_EDGES + 255) / 256, 256>>>(idx_i, idx_j);
    k_filters<<<N_EDGES / EB, 128>>>(fW, fb);
    k_init_atoms<<<N_ATOMS, 128>>>(emb, z, out);

    for (int it = 0; it < NI; it++) {
        k_atoms_x<<<N_ATOMS / TX, 128>>>(ic1W, ic1b, ic2W, ic2b, it);
        if (it == 0) k_gather<0><<<N_ATOMS / 4, 256>>>(it);
        else         k_gather<1><<<N_ATOMS / 4, 256>>>(it);
        k_atoms_update<<<N_ATOMS / TU, 128>>>(mixW, c1W, c1b, c2W, c2b,
                                              it, it == NI - 1, out + BATCH);
    }

    k_head<<<N_ATOMS / TH, 128>>>(o1W, o1b, o2W, o2b, o3W, o3b, idx_m, out);
}

// round 15
// speedup vs baseline: 2.6488x; 1.0391x over previous
#include <cuda_runtime.h>
#include <cuda_fp16.h>
#include <math.h>

#define N_ATOMS 10000
#define N_EDGES 150000
#define NB 128
#define NI 3
#define NF (NI * 3 * NB)     // 1152 filter cols
#define N_RBF 20
#define CUTOFF 5.0f
#define EPSV 1e-8f
#define BATCH 64
#define EBF 64               // edges per filter block (col-split layout)
#define TX 16                // atoms per block, k_atoms_x
#define PX 20                // padded row for TX
#define TU 8                 // atoms per block, k_atoms_update
#define PU 12                // padded row for TU
#define TH 8                 // atoms per block, k_head

typedef unsigned long long u64;

// ---------------- device scratch (static, no allocation) ----------------
__device__ float  g_q   [N_ATOMS * NB];
__device__ __align__(16) float g_mu [N_ATOMS * 3 * NB];
__device__ __align__(16) float g_x  [N_ATOMS * 3 * NB];
__device__ float  g_dq  [N_ATOMS * NB];
__device__ float  g_dmu [N_ATOMS * 3 * NB];
__device__ float  g_phif[N_EDGES * N_RBF];
__device__ float  g_fc  [N_EDGES];
__device__ float4 g_dir4[N_EDGES];
__device__ __align__(16) __half g_filt[(size_t)N_EDGES * NF]; // filters fp16, CSR-slot order
// CSR by destination atom (idx_i)
__device__ int    g_cnt [N_ATOMS];
__device__ int    g_ofs [N_ATOMS + 1];
__device__ int    g_cur [N_ATOMS];
__device__ int    g_slot[N_EDGES];
__device__ int    g_pj  [N_EDGES];
__device__ float4 g_pdir[N_EDGES];

// ---------------- packed f32x2 helpers (FFMA2 path, sm_103a) ----------------
__device__ __forceinline__ u64 pk2(float lo, float hi) {
    u64 r; asm("mov.b64 %0, {%1, %2};" : "=l"(r) : "f"(lo), "f"(hi)); return r;
}
__device__ __forceinline__ float2 upk2(u64 v) {
    float2 f; asm("mov.b64 {%0, %1}, %2;" : "=f"(f.x), "=f"(f.y) : "l"(v)); return f;
}
__device__ __forceinline__ u64 fma2v(u64 a, u64 b, u64 c) {
    u64 d; asm("fma.rn.f32x2 %0, %1, %2, %3;" : "=l"(d) : "l"(a), "l"(b), "l"(c)); return d;
}
__device__ __forceinline__ u64 mul2v(u64 a, u64 b) {
    u64 d; asm("mul.rn.f32x2 %0, %1, %2;" : "=l"(d) : "l"(a), "l"(b)); return d;
}
// half2 (as uint) -> packed f32x2
__device__ __forceinline__ u64 h2f2(unsigned h) {
    float2 f = __half22float2(*reinterpret_cast<__half2*>(&h));
    return pk2(f.x, f.y);
}

__device__ __forceinline__ float silu_f(float v) {
    return v / (1.0f + expf(-v));
}

// ---------------- edge geometry precompute ----------------
__global__ void k_init_edges(const float* __restrict__ pos,
                             const int* __restrict__ idx_i,
                             const int* __restrict__ idx_j) {
    int e = blockIdx.x * blockDim.x + threadIdx.x;
    if (e >= N_EDGES) return;
    int i = idx_i[e], j = idx_j[e];
    float rx = pos[j * 3 + 0] - pos[i * 3 + 0];
    float ry = pos[j * 3 + 1] - pos[i * 3 + 1];
    float rz = pos[j * 3 + 2] - pos[i * 3 + 2];
    float d  = sqrtf(rx * rx + ry * ry + rz * rz);
    float inv = 1.0f / d;
    g_dir4[e] = make_float4(rx * inv, ry * inv, rz * inv, 0.0f);
    float fc = (d < CUTOFF) ? 0.5f * (cosf(d * (float)M_PI / CUTOFF) + 1.0f) : 0.0f;
    g_fc[e] = fc;
    const float width = CUTOFF / (float)(N_RBF - 1);
    const float coeff = -0.5f / (width * width);
    #pragma unroll
    for (int r = 0; r < N_RBF; r++) {
        float dd = d - (float)r * width;
        g_phif[e * N_RBF + r] = expf(coeff * dd * dd) * fc;
    }
}

// ---------------- CSR build ----------------
__global__ void k_zero_cnt() {
    int a = blockIdx.x * blockDim.x + threadIdx.x;
    if (a < N_ATOMS) g_cnt[a] = 0;
}
__global__ void k_hist(const int* __restrict__ idx_i) {
    int e = blockIdx.x * blockDim.x + threadIdx.x;
    if (e < N_EDGES) atomicAdd(&g_cnt[idx_i[e]], 1);
}
__global__ void __launch_bounds__(1024) k_scan() {
    __shared__ int partial[1024];
    int t = threadIdx.x;
    int base = t * 10;
    int local[10];
    int s = 0;
    #pragma unroll
    for (int k = 0; k < 10; k++) {
        int idx = base + k;
        int c = (idx < N_ATOMS) ? g_cnt[idx] : 0;
        local[k] = s;
        s += c;
    }
    partial[t] = s;
    __syncthreads();
    for (int off = 1; off < 1024; off <<= 1) {
        int v = partial[t];
        int u = (t >= off) ? partial[t - off] : 0;
        __syncthreads();
        partial[t] = v + u;
        __syncthreads();
    }
    int pre = (t > 0) ? partial[t - 1] : 0;
    #pragma unroll
    for (int k = 0; k < 10; k++) {
        int idx = base + k;
        if (idx < N_ATOMS) {
            int o = pre + local[k];
            g_ofs[idx] = o;
            g_cur[idx] = o;
        }
    }
    if (t == 1023) g_ofs[N_ATOMS] = partial[1023];
}
__global__ void k_fill(const int* __restrict__ idx_i,
                       const int* __restrict__ idx_j) {
    int e = blockIdx.x * blockDim.x + threadIdx.x;
    if (e < N_EDGES) {
        int pos = atomicAdd(&g_cur[idx_i[e]], 1);
        g_slot[e] = pos;
        g_pj[pos] = idx_j[e];
        g_pdir[pos] = g_dir4[e];
    }
}

// ---------------- dense filter precompute, column-split layout ---------------
// grid = (ceil(N_EDGES/EBF), 9). Each block handles ONE 128-col group and
// EBF=64 edges in chunks of 8, so fW is read once per (block.y, 64 edges):
// fW L2 traffic drops 8x vs the per-block-all-columns form, with only
// wc[20]+acc[4] live per thread (no spills).
__global__ void __launch_bounds__(128) k_filters(const float* __restrict__ fW,
                                                 const float* __restrict__ fb) {
    __shared__ __align__(16) float ps[N_RBF][EBF];   // [r][edge]
    __shared__ float fcs[EBF];
    __shared__ int   slots[EBF];
    int e0 = blockIdx.x * EBF;
    int t  = threadIdx.x;
    int c  = blockIdx.y * 128 + t;     // column in [0, 1152)

    for (int idx = t; idx < EBF * N_RBF; idx += 128) {
        int a = idx % EBF, r = idx / EBF;
        int e = e0 + a;
        ps[r][a] = (e < N_EDGES) ? g_phif[(size_t)e * N_RBF + r] : 0.0f;
    }
    if (t < EBF) {
        int e = e0 + t;
        fcs[t]   = (e < N_EDGES) ? g_fc[e] : 0.0f;
        slots[t] = (e < N_EDGES) ? g_slot[e] : 0;
    }
    __syncthreads();

    float wc[N_RBF];
    #pragma unroll
    for (int r = 0; r < N_RBF; r++) wc[r] = fW[r * NF + c];
    float bias = fb[c];
    u64 bp = pk2(bias, bias);

    int nval = N_EDGES - e0;
    if (nval > EBF) nval = EBF;

    #pragma unroll 1
    for (int ch = 0; ch < EBF / 8; ch++) {
        int abase = ch * 8;
        u64 acc[4];
        #pragma unroll
        for (int p = 0; p < 4; p++)
            acc[p] = mul2v(pk2(fcs[abase + 2 * p], fcs[abase + 2 * p + 1]), bp);
        #pragma unroll
        for (int r = 0; r < N_RBF; r++) {
            u64 wp = pk2(wc[r], wc[r]);
            const u64* pr = (const u64*)&ps[r][abase];
            #pragma unroll
            for (int p = 0; p < 4; p++) acc[p] = fma2v(pr[p], wp, acc[p]);
        }
        #pragma unroll
        for (int p = 0; p < 4; p++) {
            float2 f = upk2(acc[p]);
            int a0i = abase + 2 * p;
            if (a0i < nval)
                g_filt[(size_t)slots[a0i] * NF + c]     = __float2half_rn(f.x);
            if (a0i + 1 < nval)
                g_filt[(size_t)slots[a0i + 1] * NF + c] = __float2half_rn(f.y);
        }
    }
}

// ---------------- atom init ----------------
__global__ void k_init_atoms(const float* __restrict__ emb,
                             const int* __restrict__ z,
                             float* __restrict__ y_out) {
    int a = blockIdx.x;
    int t = threadIdx.x;
    g_q[a * NB + t] = emb[z[a] * NB + t];
    #pragma unroll
    for (int d = 0; d < 3; d++)
        g_mu[a * 3 * NB + d * NB + t] = 0.0f;
    if (a == 0 && t < BATCH) y_out[t] = 0.0f;
}

// ---------------- per-atom input MLP (f32x2 packed atom pairs) ---------------
__global__ void __launch_bounds__(128) k_atoms_x(
        const float* __restrict__ ic1W, const float* __restrict__ ic1b,
        const float* __restrict__ ic2W, const float* __restrict__ ic2b,
        int it) {
    __shared__ __align__(16) float qs[NB][PX];
    __shared__ __align__(16) float hs[NB][PX];
    int t  = threadIdx.x;
    int a0 = blockIdx.x * TX;

    #pragma unroll
    for (int a = 0; a < TX; a++)
        qs[t][a] = g_q[(size_t)(a0 + a) * NB + t];
    __syncthreads();

    const float* W1 = ic1W + (size_t)it * NB * NB;
    float b1 = ic1b[it * NB + t];
    u64 acc[TX / 2];
    u64 b1p = pk2(b1, b1);
    #pragma unroll
    for (int p = 0; p < TX / 2; p++) acc[p] = b1p;
    for (int k = 0; k < NB; k++) {
        float w = W1[k * NB + t];
        u64 wp = pk2(w, w);
        const ulonglong2* q2 = (const ulonglong2*)&qs[k][0];
        #pragma unroll
        for (int p4 = 0; p4 < TX / 4; p4++) {
            ulonglong2 u = q2[p4];
            acc[2 * p4]     = fma2v(u.x, wp, acc[2 * p4]);
            acc[2 * p4 + 1] = fma2v(u.y, wp, acc[2 * p4 + 1]);
        }
    }
    #pragma unroll
    for (int p = 0; p < TX / 2; p++) {
        float2 f = upk2(acc[p]);
        hs[t][2 * p]     = silu_f(f.x);
        hs[t][2 * p + 1] = silu_f(f.y);
    }
    __syncthreads();

    const float* W2 = ic2W + (size_t)it * NB * 3 * NB;
    float b20 = ic2b[it * 3 * NB + t];
    float b21 = ic2b[it * 3 * NB + NB + t];
    float b22 = ic2b[it * 3 * NB + 2 * NB + t];
    u64 c0[TX / 2], c1[TX / 2], c2[TX / 2];
    u64 b20p = pk2(b20, b20), b21p = pk2(b21, b21), b22p = pk2(b22, b22);
    #pragma unroll
    for (int p = 0; p < TX / 2; p++) { c0[p] = b20p; c1[p] = b21p; c2[p] = b22p; }
    for (int k = 0; k < NB; k++) {
        float w0 = W2[k * 384 + t];
        float w1 = W2[k * 384 + NB + t];
        float w2 = W2[k * 384 + 2 * NB + t];
        u64 w0p = pk2(w0, w0), w1p = pk2(w1, w1), w2p = pk2(w2, w2);
        const ulonglong2* h2 = (const ulonglong2*)&hs[k][0];
        #pragma unroll
        for (int p4 = 0; p4 < TX / 4; p4++) {
            ulonglong2 u = h2[p4];
            c0[2 * p4]     = fma2v(u.x, w0p, c0[2 * p4]);
            c0[2 * p4 + 1] = fma2v(u.y, w0p, c0[2 * p4 + 1]);
            c1[2 * p4]     = fma2v(u.x, w1p, c1[2 * p4]);
            c1[2 * p4 + 1] = fma2v(u.y, w1p, c1[2 * p4 + 1]);
            c2[2 * p4]     = fma2v(u.x, w2p, c2[2 * p4]);
            c2[2 * p4 + 1] = fma2v(u.y, w2p, c2[2 * p4 + 1]);
        }
    }
    #pragma unroll
    for (int p = 0; p < TX / 2; p++) {
        float2 f0 = upk2(c0[p]);
        float2 f1 = upk2(c1[p]);
        float2 f2 = upk2(c2[p]);
        size_t ga = (size_t)(a0 + 2 * p) * 384;
        size_t gb = (size_t)(a0 + 2 * p + 1) * 384;
        g_x[ga + t] = f0.x;           g_x[gb + t] = f0.y;
        g_x[ga + NB + t] = f1.x;      g_x[gb + NB + t] = f1.y;
        g_x[ga + 2 * NB + t] = f2.x;  g_x[gb + 2 * NB + t] = f2.y;
    }
}

// ---------------- edge gather: TWO warps per destination atom ----------------
template <int HAS_MU>
__global__ void __launch_bounds__(256) k_gather(int it) {
    __shared__ __align__(16) float sm[4][4 * NB];   // 4 atoms x (dq,m0,m1,m2) x 128
    int warp = threadIdx.x >> 5;
    int lane = threadIdx.x & 31;
    int a    = warp >> 1;          // atom slot 0..3
    int half = warp & 1;
    int i = blockIdx.x * 4 + a;
    int beg0 = g_ofs[i], end0 = g_ofs[i + 1];
    int len  = end0 - beg0;
    int mid  = beg0 + ((len + 1) >> 1);
    int beg  = half ? mid : beg0;
    int end  = half ? end0 : mid;

    u64 mq0 = 0, mq1 = 0;
    u64 m0a = 0, m0b = 0, m1a = 0, m1b = 0, m2a = 0, m2b = 0;

    const int itofs = it * 384;   // in half units
    int j = 0; float4 d4 = make_float4(0,0,0,0);
    if (beg < end) { j = __ldg(g_pj + beg); d4 = g_pdir[beg]; }

    for (int k = beg; k < end; k++) {
        int jn = 0; float4 dn = d4;
        if (k + 1 < end) { jn = __ldg(g_pj + k + 1); dn = g_pdir[k + 1]; }

        const uint2* fe = (const uint2*)(g_filt + (size_t)k * NF + itofs);
        uint2 f0 = fe[lane];
        uint2 f1 = fe[32 + lane];
        uint2 f2 = fe[64 + lane];
        const ulonglong2* xr = (const ulonglong2*)(g_x + (size_t)j * 384);
        ulonglong2 x0 = xr[lane];
        ulonglong2 x1 = xr[32 + lane];
        ulonglong2 x2 = xr[64 + lane];
        ulonglong2 u0, u1, u2;
        if (HAS_MU) {
            const ulonglong2* mr = (const ulonglong2*)(g_mu + (size_t)j * 384);
            u0 = mr[lane];
            u1 = mr[32 + lane];
            u2 = mr[64 + lane];
        }

        u64 w0x = h2f2(f0.x), w0y = h2f2(f0.y);
        u64 w1x = h2f2(f1.x), w1y = h2f2(f1.y);
        u64 w2x = h2f2(f2.x), w2y = h2f2(f2.y);

        mq0 = fma2v(w0x, x0.x, mq0);
        mq1 = fma2v(w0y, x0.y, mq1);
        u64 vR0 = mul2v(w1x, x1.x), vR1 = mul2v(w1y, x1.y);
        u64 vM0 = mul2v(w2x, x2.x), vM1 = mul2v(w2y, x2.y);
        u64 dxp = pk2(d4.x, d4.x), dyp = pk2(d4.y, d4.y), dzp = pk2(d4.z, d4.z);
        if (HAS_MU) {
            m0a = fma2v(vR0, dxp, fma2v(vM0, u0.x, m0a));
            m0b = fma2v(vR1, dxp, fma2v(vM1, u0.y, m0b));
            m1a = fma2v(vR0, dyp, fma2v(vM0, u1.x, m1a));
            m1b = fma2v(vR1, dyp, fma2v(vM1, u1.y, m1b));
            m2a = fma2v(vR0, dzp, fma2v(vM0, u2.x, m2a));
            m2b = fma2v(vR1, dzp, fma2v(vM1, u2.y, m2b));
        } else {
            m0a = fma2v(vR0, dxp, m0a);
            m0b = fma2v(vR1, dxp, m0b);
            m1a = fma2v(vR0, dyp, m1a);
            m1b = fma2v(vR1, dyp, m1b);
            m2a = fma2v(vR0, dzp, m2a);
            m2b = fma2v(vR1, dzp, m2b);
        }
        j = jn; d4 = dn;
    }

    // odd warp publishes partials to smem
    ulonglong2* sb = (ulonglong2*)&sm[a][0];
    if (half == 1) {
        ulonglong2 t;
        t.x = mq0; t.y = mq1; sb[lane]      = t;
        t.x = m0a; t.y = m0b; sb[32 + lane] = t;
        t.x = m1a; t.y = m1b; sb[64 + lane] = t;
        t.x = m2a; t.y = m2b; sb[96 + lane] = t;
    }
    __syncthreads();

    if (half == 0) {
        const u64 one = pk2(1.0f, 1.0f);
        ulonglong2 p;
        p = sb[lane];      mq0 = fma2v(p.x, one, mq0); mq1 = fma2v(p.y, one, mq1);
        p = sb[32 + lane]; m0a = fma2v(p.x, one, m0a); m0b = fma2v(p.y, one, m0b);
        p = sb[64 + lane]; m1a = fma2v(p.x, one, m1a); m1b = fma2v(p.y, one, m1b);
        p = sb[96 + lane]; m2a = fma2v(p.x, one, m2a); m2b = fma2v(p.y, one, m2b);

        ulonglong2 o;
        o.x = mq0; o.y = mq1;
        ((ulonglong2*)(g_dq + (size_t)i * NB))[lane] = o;
        ulonglong2* dmu = (ulonglong2*)(g_dmu + (size_t)i * 3 * NB);
        o.x = m0a; o.y = m0b; dmu[lane]      = o;
        o.x = m1a; o.y = m1b; dmu[32 + lane] = o;
        o.x = m2a; o.y = m2b; dmu[64 + lane] = o;
    }
}

// ---------------- per-atom update (f32x2 packed atom pairs) ------------------
__global__ void __launch_bounds__(128) k_atoms_update(
        const float* __restrict__ mixW,
        const float* __restrict__ c1W, const float* __restrict__ c1b,
        const float* __restrict__ c2W, const float* __restrict__ c2b,
        int it, int last, float* __restrict__ mu_out) {
    __shared__ __align__(16) float mus[NB][3][PU];     // [k][d][a]
    __shared__ __align__(16) float ctxs[2 * NB][PU];   // [k][a]
    __shared__ __align__(16) float hs[NB][PU];         // [k][a]
    int t  = threadIdx.x;
    int a0 = blockIdx.x * TU;

    float qreg[TU];
    #pragma unroll
    for (int a = 0; a < TU; a++) {
        size_t g = (size_t)(a0 + a);
        qreg[a] = g_q[g * NB + t] + g_dq[g * NB + t];
        ctxs[t][a] = qreg[a];
        #pragma unroll
        for (int d = 0; d < 3; d++)
            mus[t][d][a] = g_mu[g * 3 * NB + d * NB + t] + g_dmu[g * 3 * NB + d * NB + t];
    }
    __syncthreads();

    const float* MW = mixW + (size_t)it * NB * 2 * NB;
    u64 v2[TU / 2][3], w2[TU / 2][3];
    #pragma unroll
    for (int p = 0; p < TU / 2; p++)
        #pragma unroll
        for (int d = 0; d < 3; d++) { v2[p][d] = 0; w2[p][d] = 0; }
    for (int k = 0; k < NB; k++) {
        float wv = MW[k * 256 + t];
        float ww = MW[k * 256 + NB + t];
        u64 wvp = pk2(wv, wv), wwp = pk2(ww, ww);
        #pragma unroll
        for (int d = 0; d < 3; d++) {
            const ulonglong2* m2 = (const ulonglong2*)&mus[k][d][0];
            ulonglong2 ua = m2[0];
            ulonglong2 ub = m2[1];
            v2[0][d] = fma2v(ua.x, wvp, v2[0][d]);
            v2[1][d] = fma2v(ua.y, wvp, v2[1][d]);
            v2[2][d] = fma2v(ub.x, wvp, v2[2][d]);
            v2[3][d] = fma2v(ub.y, wvp, v2[3][d]);
            w2[0][d] = fma2v(ua.x, wwp, w2[0][d]);
            w2[1][d] = fma2v(ua.y, wwp, w2[1][d]);
            w2[2][d] = fma2v(ub.x, wwp, w2[2][d]);
            w2[3][d] = fma2v(ub.y, wwp, w2[3][d]);
        }
    }
    float v[TU][3], w[TU][3];
    #pragma unroll
    for (int p = 0; p < TU / 2; p++)
        #pragma unroll
        for (int d = 0; d < 3; d++) {
            float2 fv = upk2(v2[p][d]);
            float2 fw = upk2(w2[p][d]);
            v[2 * p][d] = fv.x; v[2 * p + 1][d] = fv.y;
            w[2 * p][d] = fw.x; w[2 * p + 1][d] = fw.y;
        }
    float s[TU];
    #pragma unroll
    for (int a = 0; a < TU; a++) {
        float n2 = v[a][0]*v[a][0] + v[a][1]*v[a][1] + v[a][2]*v[a][2];
        float vn = sqrtf(n2 + EPSV);
        s[a] = v[a][0]*w[a][0] + v[a][1]*w[a][1] + v[a][2]*w[a][2];
        ctxs[NB + t][a] = vn;
    }
    __syncthreads();

    const float* W1 = c1W + (size_t)it * 2 * NB * NB;
    float b1 = c1b[it * NB + t];
    u64 acc[TU / 2];
    u64 b1p = pk2(b1, b1);
    #pragma unroll
    for (int p = 0; p < TU / 2; p++) acc[p] = b1p;
    for (int k = 0; k < 2 * NB; k++) {
        float ww1 = W1[k * NB + t];
        u64 wp = pk2(ww1, ww1);
        const ulonglong2* c2p = (const ulonglong2*)&ctxs[k][0];
        ulonglong2 ca = c2p[0], cb = c2p[1];
        acc[0] = fma2v(ca.x, wp, acc[0]);
        acc[1] = fma2v(ca.y, wp, acc[1]);
        acc[2] = fma2v(cb.x, wp, acc[2]);
        acc[3] = fma2v(cb.y, wp, acc[3]);
    }
    #pragma unroll
    for (int p = 0; p < TU / 2; p++) {
        float2 f = upk2(acc[p]);
        hs[t][2 * p]     = silu_f(f.x);
        hs[t][2 * p + 1] = silu_f(f.y);
    }
    __syncthreads();

    const float* W2 = c2W + (size_t)it * NB * 3 * NB;
    float b20 = c2b[it * 3 * NB + t];
    float b21 = c2b[it * 3 * NB + NB + t];
    float b22 = c2b[it * 3 * NB + 2 * NB + t];
    u64 aq2[TU / 2], am2[TU / 2], aqm2[TU / 2];
    u64 b20p = pk2(b20, b20), b21p = pk2(b21, b21), b22p = pk2(b22, b22);
    #pragma unroll
    for (int p = 0; p < TU / 2; p++) { aq2[p] = b20p; am2[p] = b21p; aqm2[p] = b22p; }
    for (int k = 0; k < NB; k++) {
        float w0 = W2[k * 384 + t];
        float w1 = W2[k * 384 + NB + t];
        float w2w = W2[k * 384 + 2 * NB + t];
        u64 w0p = pk2(w0, w0), w1p = pk2(w1, w1), w2p = pk2(w2w, w2w);
        const ulonglong2* h2 = (const ulonglong2*)&hs[k][0];
        ulonglong2 ha = h2[0], hb = h2[1];
        aq2[0]  = fma2v(ha.x, w0p, aq2[0]);
        aq2[1]  = fma2v(ha.y, w0p, aq2[1]);
        aq2[2]  = fma2v(hb.x, w0p, aq2[2]);
        aq2[3]  = fma2v(hb.y, w0p, aq2[3]);
        am2[0]  = fma2v(ha.x, w1p, am2[0]);
        am2[1]  = fma2v(ha.y, w1p, am2[1]);
        am2[2]  = fma2v(hb.x, w1p, am2[2]);
        am2[3]  = fma2v(hb.y, w1p, am2[3]);
        aqm2[0] = fma2v(ha.x, w2p, aqm2[0]);
        aqm2[1] = fma2v(ha.y, w2p, aqm2[1]);
        aqm2[2] = fma2v(hb.x, w2p, aqm2[2]);
        aqm2[3] = fma2v(hb.y, w2p, aqm2[3]);
    }
    float aq[TU], am[TU], aqm[TU];
    #pragma unroll
    for (int p = 0; p < TU / 2; p++) {
        float2 f0 = upk2(aq2[p]);
        float2 f1 = upk2(am2[p]);
        float2 f2 = upk2(aqm2[p]);
        aq[2 * p] = f0.x;  aq[2 * p + 1] = f0.y;
        am[2 * p] = f1.x;  am[2 * p + 1] = f1.y;
        aqm[2 * p] = f2.x; aqm[2 * p + 1] = f2.y;
    }
    #pragma unroll
    for (int a = 0; a < TU; a++) {
        size_t g = (size_t)(a0 + a);
        g_q[g * NB + t] = qreg[a] + aq[a] + aqm[a] * s[a];
        #pragma unroll
        for (int d = 0; d < 3; d++) {
            float val = mus[t][d][a] + am[a] * w[a][d];
            g_mu[g * 3 * NB + d * NB + t] = val;
            if (last) mu_out[g * 3 * NB + d * NB + t] = val;
        }
    }
}

// ---------------- output head ----------------
__global__ void __launch_bounds__(128) k_head(
        const float* __restrict__ o1W, const float* __restrict__ o1b,
        const float* __restrict__ o2W, const float* __restrict__ o2b,
        const float* __restrict__ o3W, const float* __restrict__ o3b,
        const int* __restrict__ idx_m, float* __restrict__ y) {
    __shared__ float qs[TH][NB];
    __shared__ float h1[TH][NB];
    __shared__ float h2[TH][NB];
    int t  = threadIdx.x;
    int a0 = blockIdx.x * TH;
    #pragma unroll
    for (int a = 0; a < TH; a++) qs[a][t] = g_q[(size_t)(a0 + a) * NB + t];
    __syncthreads();

    float acc[TH];
    float b = o1b[t];
    #pragma unroll
    for (int a = 0; a < TH; a++) acc[a] = b;
    for (int k = 0; k < NB; k++) {
        float w = o1W[k * NB + t];
        #pragma unroll
        for (int a = 0; a < TH; a++) acc[a] += qs[a][k] * w;
    }
    #pragma unroll
    for (int a = 0; a < TH; a++) h1[a][t] = silu_f(acc[a]);
    __syncthreads();

    b = o2b[t];
    #pragma unroll
    for (int a = 0; a < TH; a++) acc[a] = b;
    for (int k = 0; k < NB; k++) {
        float w = o2W[k * NB + t];
        #pragma unroll
        for (int a = 0; a < TH; a++) acc[a] += h1[a][k] * w;
    }
    #pragma unroll
    for (int a = 0; a < TH; a++) h2[a][t] = silu_f(acc[a]);
    __syncthreads();

    if (t < TH) {
        float sum = o3b[0];
        for (int k = 0; k < NB; k++) sum += h2[t][k] * o3W[k];
        atomicAdd(&y[idx_m[a0 + t]], sum);
    }
}

// ---------------- launch ----------------
extern "C" void kernel_launch(void* const* d_in, const int* in_sizes, int n_in,
                              void* d_out, int out_size) {
    const float* positions = (const float*)d_in[0];
    const float* emb  = (const float*)d_in[1];
    const float* fW   = (const float*)d_in[2];
    const float* fb   = (const float*)d_in[3];
    const float* ic1W = (const float*)d_in[4];
    const float* ic1b = (const float*)d_in[5];
    const float* ic2W = (const float*)d_in[6];
    const float* ic2b = (const float*)d_in[7];
    const float* mixW = (const float*)d_in[8];
    const float* c1W  = (const float*)d_in[9];
    const float* c1b  = (const float*)d_in[10];
    const float* c2W  = (const float*)d_in[11];
    const float* c2b  = (const float*)d_in[12];
    const float* o1W  = (const float*)d_in[13];
    const float* o1b  = (const float*)d_in[14];
    const float* o2W  = (const float*)d_in[15];
    const float* o2b  = (const float*)d_in[16];
    const float* o3W  = (const float*)d_in[17];
    const float* o3b  = (const float*)d_in[18];
    const int* z      = (const int*)d_in[19];
    const int* idx_i  = (const int*)d_in[20];
    const int* idx_j  = (const int*)d_in[21];
    const int* idx_m  = (const int*)d_in[22];
    float* out = (float*)d_out;   // layout: y[64], then mu[10000*3*128]

    k_init_edges<<<(N_EDGES + 255) / 256, 256>>>(positions, idx_i, idx_j);
    k_zero_cnt<<<(N_ATOMS + 255) / 256, 256>>>();
    k_hist<<<(N_EDGES + 255) / 256, 256>>>(idx_i);
    k_scan<<<1, 1024>>>();
    k_fill<<<(N_EDGES + 255) / 256, 256>>>(idx_i, idx_j);
    {
        dim3 fg((N_EDGES + EBF - 1) / EBF, NF / 128);
        k_filters<<<fg, 128>>>(fW, fb);
    }
    k_init_atoms<<<N_ATOMS, 128>>>(emb, z, out);

    for (int it = 0; it < NI; it++) {
        k_atoms_x<<<N_ATOMS / TX, 128>>>(ic1W, ic1b, ic2W, ic2b, it);
        if (it == 0) k_gather<0><<<N_ATOMS / 4, 256>>>(it);
        else         k_gather<1><<<N_ATOMS / 4, 256>>>(it);
        k_atoms_update<<<N_ATOMS / TU, 128>>>(mixW, c1W, c1b, c2W, c2b,
                                              it, it == NI - 1, out + BATCH);
    }

    k_head<<<N_ATOMS / TH, 128>>>(o1W, o1b, o2W, o2b, o3W, o3b, idx_m, out);
}

// round 16
// speedup vs baseline: 2.8044x; 1.0587x over previous
#include <cuda_runtime.h>
#include <cuda_fp16.h>
#include <mma.h>
#include <math.h>

using namespace nvcuda;

#define N_ATOMS 10000
#define N_EDGES 150000
#define NB 128
#define NI 3
#define NF (NI * 3 * NB)     // 1152 filter cols
#define N_RBF 20
#define CUTOFF 5.0f
#define EPSV 1e-8f
#define BATCH 64
#define FEB 64               // edges per wmma filter block
#define BSP 136              // padded B smem row stride (halfs)
#define TX 16                // atoms per block, k_atoms_x
#define PX 20                // padded row for TX
#define TU 8                 // atoms per block, k_atoms_update
#define PU 12                // padded row for TU
#define TH 8                 // atoms per block, k_head

typedef unsigned long long u64;

// ---------------- device scratch (static, no allocation) ----------------
__device__ float  g_q   [N_ATOMS * NB];
__device__ __align__(16) float g_mu [N_ATOMS * 3 * NB];
__device__ __align__(16) float g_x  [N_ATOMS * 3 * NB];
__device__ float  g_dq  [N_ATOMS * NB];
__device__ float  g_dmu [N_ATOMS * 3 * NB];
__device__ __align__(16) __half g_phif_h[(size_t)N_EDGES * 32];  // A: [e][32] fp16
__device__ __align__(16) __half g_B[32 * NF];                    // B: [32][1152] fp16
__device__ float4 g_dir4[N_EDGES];
__device__ __align__(16) __half g_filt[(size_t)N_EDGES * NF]; // filters fp16, CSR-slot order
// CSR by destination atom (idx_i)
__device__ int    g_cnt [N_ATOMS];
__device__ int    g_ofs [N_ATOMS + 1];
__device__ int    g_cur [N_ATOMS];
__device__ int    g_slot[N_EDGES];
__device__ int    g_pj  [N_EDGES];
__device__ float4 g_pdir[N_EDGES];

// ---------------- packed f32x2 helpers (FFMA2 path, sm_103a) ----------------
__device__ __forceinline__ u64 pk2(float lo, float hi) {
    u64 r; asm("mov.b64 %0, {%1, %2};" : "=l"(r) : "f"(lo), "f"(hi)); return r;
}
__device__ __forceinline__ float2 upk2(u64 v) {
    float2 f; asm("mov.b64 {%0, %1}, %2;" : "=f"(f.x), "=f"(f.y) : "l"(v)); return f;
}
__device__ __forceinline__ u64 fma2v(u64 a, u64 b, u64 c) {
    u64 d; asm("fma.rn.f32x2 %0, %1, %2, %3;" : "=l"(d) : "l"(a), "l"(b), "l"(c)); return d;
}
__device__ __forceinline__ u64 mul2v(u64 a, u64 b) {
    u64 d; asm("mul.rn.f32x2 %0, %1, %2;" : "=l"(d) : "l"(a), "l"(b)); return d;
}
// half2 (as uint) -> packed f32x2
__device__ __forceinline__ u64 h2f2(unsigned h) {
    float2 f = __half22float2(*reinterpret_cast<__half2*>(&h));
    return pk2(f.x, f.y);
}

__device__ __forceinline__ float silu_f(float v) {
    return v / (1.0f + expf(-v));
}

// ---------------- edge geometry precompute (A rows in fp16) -----------------
__global__ void k_init_edges(const float* __restrict__ pos,
                             const int* __restrict__ idx_i,
                             const int* __restrict__ idx_j) {
    int e = blockIdx.x * blockDim.x + threadIdx.x;
    if (e >= N_EDGES) return;
    int i = idx_i[e], j = idx_j[e];
    float rx = pos[j * 3 + 0] - pos[i * 3 + 0];
    float ry = pos[j * 3 + 1] - pos[i * 3 + 1];
    float rz = pos[j * 3 + 2] - pos[i * 3 + 2];
    float d  = sqrtf(rx * rx + ry * ry + rz * rz);
    float inv = 1.0f / d;
    g_dir4[e] = make_float4(rx * inv, ry * inv, rz * inv, 0.0f);
    float fc = (d < CUTOFF) ? 0.5f * (cosf(d * (float)M_PI / CUTOFF) + 1.0f) : 0.0f;
    const float width = CUTOFF / (float)(N_RBF - 1);
    const float coeff = -0.5f / (width * width);
    __half* row = g_phif_h + (size_t)e * 32;
    #pragma unroll
    for (int r = 0; r < N_RBF; r++) {
        float dd = d - (float)r * width;
        row[r] = __float2half_rn(expf(coeff * dd * dd) * fc);
    }
    row[20] = __float2half_rn(fc);
    #pragma unroll
    for (int r = 21; r < 32; r++) row[r] = __float2half_rn(0.0f);
}

// ---------------- B matrix build: [32 x 1152] fp16 --------------------------
__global__ void k_makeB(const float* __restrict__ fW,
                        const float* __restrict__ fb) {
    int i = blockIdx.x * blockDim.x + threadIdx.x;
    if (i >= 32 * NF) return;
    int r = i / NF, c = i % NF;
    float v = (r < N_RBF) ? fW[r * NF + c] : ((r == 20) ? fb[c] : 0.0f);
    g_B[i] = __float2half_rn(v);
}

// ---------------- CSR build ----------------
__global__ void k_zero_cnt() {
    int a = blockIdx.x * blockDim.x + threadIdx.x;
    if (a < N_ATOMS) g_cnt[a] = 0;
}
__global__ void k_hist(const int* __restrict__ idx_i) {
    int e = blockIdx.x * blockDim.x + threadIdx.x;
    if (e < N_EDGES) atomicAdd(&g_cnt[idx_i[e]], 1);
}
__global__ void __launch_bounds__(1024) k_scan() {
    __shared__ int partial[1024];
    int t = threadIdx.x;
    int base = t * 10;
    int local[10];
    int s = 0;
    #pragma unroll
    for (int k = 0; k < 10; k++) {
        int idx = base + k;
        int c = (idx < N_ATOMS) ? g_cnt[idx] : 0;
        local[k] = s;
        s += c;
    }
    partial[t] = s;
    __syncthreads();
    for (int off = 1; off < 1024; off <<= 1) {
        int v = partial[t];
        int u = (t >= off) ? partial[t - off] : 0;
        __syncthreads();
        partial[t] = v + u;
        __syncthreads();
    }
    int pre = (t > 0) ? partial[t - 1] : 0;
    #pragma unroll
    for (int k = 0; k < 10; k++) {
        int idx = base + k;
        if (idx < N_ATOMS) {
            int o = pre + local[k];
            g_ofs[idx] = o;
            g_cur[idx] = o;
        }
    }
    if (t == 1023) g_ofs[N_ATOMS] = partial[1023];
}
__global__ void k_fill(const int* __restrict__ idx_i,
                       const int* __restrict__ idx_j) {
    int e = blockIdx.x * blockDim.x + threadIdx.x;
    if (e < N_EDGES) {
        int pos = atomicAdd(&g_cur[idx_i[e]], 1);
        g_slot[e] = pos;
        g_pj[pos] = idx_j[e];
        g_pdir[pos] = g_dir4[e];
    }
}

// ---------------- filter GEMM on tensor cores (wmma fp16 -> fp32) -----------
// grid = (ceil(N_EDGES/FEB), 9). Block: 64 edges x 128 cols.
// filt = A[64x32] @ B[32x128] with A = [phi*fc | fc | 0], B = [fW ; fb ; 0].
__global__ void __launch_bounds__(128) k_filters_wmma() {
    __shared__ __align__(16) __half As[FEB][32];       // 4 KB
    __shared__ __align__(16) __half Bs[32][BSP];       // 8.5 KB
    __shared__ __align__(16) float  Cs[FEB][128];      // 32 KB
    __shared__ int slots[FEB];
    int e0 = blockIdx.x * FEB;
    int t  = threadIdx.x;
    int c0 = blockIdx.y * 128;

    // A: 64 rows x 32 halfs = 256 uint4 loads
    for (int idx = t; idx < FEB * 4; idx += 128) {
        int row = idx >> 2, part = idx & 3;
        int e = e0 + row;
        uint4 v = make_uint4(0, 0, 0, 0);
        if (e < N_EDGES)
            v = ((const uint4*)(g_phif_h + (size_t)e * 32))[part];
        ((uint4*)&As[row][0])[part] = v;
    }
    // B: 32 rows x 128 halfs = 512 uint4 loads
    for (int idx = t; idx < 32 * 16; idx += 128) {
        int r = idx >> 4, pc = (idx & 15) * 8;
        *(uint4*)&Bs[r][pc] = *(const uint4*)&g_B[r * NF + c0 + pc];
    }
    for (int idx = t; idx < FEB; idx += 128) {
        int e = e0 + idx;
        slots[idx] = (e < N_EDGES) ? g_slot[e] : -1;
    }
    __syncthreads();

    int warp = t >> 5;   // m-tile
    wmma::fragment<wmma::accumulator, 16, 16, 16, float> cf[8];
    #pragma unroll
    for (int n = 0; n < 8; n++) wmma::fill_fragment(cf[n], 0.0f);
    #pragma unroll
    for (int k = 0; k < 2; k++) {
        wmma::fragment<wmma::matrix_a, 16, 16, 16, __half, wmma::row_major> af;
        wmma::load_matrix_sync(af, &As[warp * 16][k * 16], 32);
        #pragma unroll
        for (int n = 0; n < 8; n++) {
            wmma::fragment<wmma::matrix_b, 16, 16, 16, __half, wmma::row_major> bf;
            wmma::load_matrix_sync(bf, &Bs[k * 16][n * 16], BSP);
            wmma::mma_sync(cf[n], af, bf, cf[n]);
        }
    }
    #pragma unroll
    for (int n = 0; n < 8; n++)
        wmma::store_matrix_sync(&Cs[warp * 16][n * 16], cf[n], 128, wmma::mem_row_major);
    __syncthreads();

    // scatter rows to CSR slots (128 threads cover one row's 128 cols)
    #pragma unroll 4
    for (int r = 0; r < FEB; r++) {
        int s = slots[r];
        if (s >= 0)
            g_filt[(size_t)s * NF + c0 + t] = __float2half_rn(Cs[r][t]);
    }
}

// ---------------- atom init ----------------
__global__ void k_init_atoms(const float* __restrict__ emb,
                             const int* __restrict__ z,
                             float* __restrict__ y_out) {
    int a = blockIdx.x;
    int t = threadIdx.x;
    g_q[a * NB + t] = emb[z[a] * NB + t];
    #pragma unroll
    for (int d = 0; d < 3; d++)
        g_mu[a * 3 * NB + d * NB + t] = 0.0f;
    if (a == 0 && t < BATCH) y_out[t] = 0.0f;
}

// ---------------- per-atom input MLP (f32x2 packed atom pairs) ---------------
__global__ void __launch_bounds__(128) k_atoms_x(
        const float* __restrict__ ic1W, const float* __restrict__ ic1b,
        const float* __restrict__ ic2W, const float* __restrict__ ic2b,
        int it) {
    __shared__ __align__(16) float qs[NB][PX];
    __shared__ __align__(16) float hs[NB][PX];
    int t  = threadIdx.x;
    int a0 = blockIdx.x * TX;

    #pragma unroll
    for (int a = 0; a < TX; a++)
        qs[t][a] = g_q[(size_t)(a0 + a) * NB + t];
    __syncthreads();

    const float* W1 = ic1W + (size_t)it * NB * NB;
    float b1 = ic1b[it * NB + t];
    u64 acc[TX / 2];
    u64 b1p = pk2(b1, b1);
    #pragma unroll
    for (int p = 0; p < TX / 2; p++) acc[p] = b1p;
    for (int k = 0; k < NB; k++) {
        float w = W1[k * NB + t];
        u64 wp = pk2(w, w);
        const ulonglong2* q2 = (const ulonglong2*)&qs[k][0];
        #pragma unroll
        for (int p4 = 0; p4 < TX / 4; p4++) {
            ulonglong2 u = q2[p4];
            acc[2 * p4]     = fma2v(u.x, wp, acc[2 * p4]);
            acc[2 * p4 + 1] = fma2v(u.y, wp, acc[2 * p4 + 1]);
        }
    }
    #pragma unroll
    for (int p = 0; p < TX / 2; p++) {
        float2 f = upk2(acc[p]);
        hs[t][2 * p]     = silu_f(f.x);
        hs[t][2 * p + 1] = silu_f(f.y);
    }
    __syncthreads();

    const float* W2 = ic2W + (size_t)it * NB * 3 * NB;
    float b20 = ic2b[it * 3 * NB + t];
    float b21 = ic2b[it * 3 * NB + NB + t];
    float b22 = ic2b[it * 3 * NB + 2 * NB + t];
    u64 c0[TX / 2], c1[TX / 2], c2[TX / 2];
    u64 b20p = pk2(b20, b20), b21p = pk2(b21, b21), b22p = pk2(b22, b22);
    #pragma unroll
    for (int p = 0; p < TX / 2; p++) { c0[p] = b20p; c1[p] = b21p; c2[p] = b22p; }
    for (int k = 0; k < NB; k++) {
        float w0 = W2[k * 384 + t];
        float w1 = W2[k * 384 + NB + t];
        float w2 = W2[k * 384 + 2 * NB + t];
        u64 w0p = pk2(w0, w0), w1p = pk2(w1, w1), w2p = pk2(w2, w2);
        const ulonglong2* h2 = (const ulonglong2*)&hs[k][0];
        #pragma unroll
        for (int p4 = 0; p4 < TX / 4; p4++) {
            ulonglong2 u = h2[p4];
            c0[2 * p4]     = fma2v(u.x, w0p, c0[2 * p4]);
            c0[2 * p4 + 1] = fma2v(u.y, w0p, c0[2 * p4 + 1]);
            c1[2 * p4]     = fma2v(u.x, w1p, c1[2 * p4]);
            c1[2 * p4 + 1] = fma2v(u.y, w1p, c1[2 * p4 + 1]);
            c2[2 * p4]     = fma2v(u.x, w2p, c2[2 * p4]);
            c2[2 * p4 + 1] = fma2v(u.y, w2p, c2[2 * p4 + 1]);
        }
    }
    #pragma unroll
    for (int p = 0; p < TX / 2; p++) {
        float2 f0 = upk2(c0[p]);
        float2 f1 = upk2(c1[p]);
        float2 f2 = upk2(c2[p]);
        size_t ga = (size_t)(a0 + 2 * p) * 384;
        size_t gb = (size_t)(a0 + 2 * p + 1) * 384;
        g_x[ga + t] = f0.x;           g_x[gb + t] = f0.y;
        g_x[ga + NB + t] = f1.x;      g_x[gb + NB + t] = f1.y;
        g_x[ga + 2 * NB + t] = f2.x;  g_x[gb + 2 * NB + t] = f2.y;
    }
}

// ---------------- edge gather: TWO warps per destination atom ----------------
template <int HAS_MU>
__global__ void __launch_bounds__(256) k_gather(int it) {
    __shared__ __align__(16) float sm[4][4 * NB];   // 4 atoms x (dq,m0,m1,m2) x 128
    int warp = threadIdx.x >> 5;
    int lane = threadIdx.x & 31;
    int a    = warp >> 1;          // atom slot 0..3
    int half = warp & 1;
    int i = blockIdx.x * 4 + a;
    int beg0 = g_ofs[i], end0 = g_ofs[i + 1];
    int len  = end0 - beg0;
    int mid  = beg0 + ((len + 1) >> 1);
    int beg  = half ? mid : beg0;
    int end  = half ? end0 : mid;

    u64 mq0 = 0, mq1 = 0;
    u64 m0a = 0, m0b = 0, m1a = 0, m1b = 0, m2a = 0, m2b = 0;

    const int itofs = it * 384;   // in half units
    int j = 0; float4 d4 = make_float4(0,0,0,0);
    if (beg < end) { j = __ldg(g_pj + beg); d4 = g_pdir[beg]; }

    for (int k = beg; k < end; k++) {
        int jn = 0; float4 dn = d4;
        if (k + 1 < end) { jn = __ldg(g_pj + k + 1); dn = g_pdir[k + 1]; }

        const uint2* fe = (const uint2*)(g_filt + (size_t)k * NF + itofs);
        uint2 f0 = fe[lane];
        uint2 f1 = fe[32 + lane];
        uint2 f2 = fe[64 + lane];
        const ulonglong2* xr = (const ulonglong2*)(g_x + (size_t)j * 384);
        ulonglong2 x0 = xr[lane];
        ulonglong2 x1 = xr[32 + lane];
        ulonglong2 x2 = xr[64 + lane];
        ulonglong2 u0, u1, u2;
        if (HAS_MU) {
            const ulonglong2* mr = (const ulonglong2*)(g_mu + (size_t)j * 384);
            u0 = mr[lane];
            u1 = mr[32 + lane];
            u2 = mr[64 + lane];
        }

        u64 w0x = h2f2(f0.x), w0y = h2f2(f0.y);
        u64 w1x = h2f2(f1.x), w1y = h2f2(f1.y);
        u64 w2x = h2f2(f2.x), w2y = h2f2(f2.y);

        mq0 = fma2v(w0x, x0.x, mq0);
        mq1 = fma2v(w0y, x0.y, mq1);
        u64 vR0 = mul2v(w1x, x1.x), vR1 = mul2v(w1y, x1.y);
        u64 vM0 = mul2v(w2x, x2.x), vM1 = mul2v(w2y, x2.y);
        u64 dxp = pk2(d4.x, d4.x), dyp = pk2(d4.y, d4.y), dzp = pk2(d4.z, d4.z);
        if (HAS_MU) {
            m0a = fma2v(vR0, dxp, fma2v(vM0, u0.x, m0a));
            m0b = fma2v(vR1, dxp, fma2v(vM1, u0.y, m0b));
            m1a = fma2v(vR0, dyp, fma2v(vM0, u1.x, m1a));
            m1b = fma2v(vR1, dyp, fma2v(vM1, u1.y, m1b));
            m2a = fma2v(vR0, dzp, fma2v(vM0, u2.x, m2a));
            m2b = fma2v(vR1, dzp, fma2v(vM1, u2.y, m2b));
        } else {
            m0a = fma2v(vR0, dxp, m0a);
            m0b = fma2v(vR1, dxp, m0b);
            m1a = fma2v(vR0, dyp, m1a);
            m1b = fma2v(vR1, dyp, m1b);
            m2a = fma2v(vR0, dzp, m2a);
            m2b = fma2v(vR1, dzp, m2b);
        }
        j = jn; d4 = dn;
    }

    // odd warp publishes partials to smem
    ulonglong2* sb = (ulonglong2*)&sm[a][0];
    if (half == 1) {
        ulonglong2 t;
        t.x = mq0; t.y = mq1; sb[lane]      = t;
        t.x = m0a; t.y = m0b; sb[32 + lane] = t;
        t.x = m1a; t.y = m1b; sb[64 + lane] = t;
        t.x = m2a; t.y = m2b; sb[96 + lane] = t;
    }
    __syncthreads();

    if (half == 0) {
        const u64 one = pk2(1.0f, 1.0f);
        ulonglong2 p;
        p = sb[lane];      mq0 = fma2v(p.x, one, mq0); mq1 = fma2v(p.y, one, mq1);
        p = sb[32 + lane]; m0a = fma2v(p.x, one, m0a); m0b = fma2v(p.y, one, m0b);
        p = sb[64 + lane]; m1a = fma2v(p.x, one, m1a); m1b = fma2v(p.y, one, m1b);
        p = sb[96 + lane]; m2a = fma2v(p.x, one, m2a); m2b = fma2v(p.y, one, m2b);

        ulonglong2 o;
        o.x = mq0; o.y = mq1;
        ((ulonglong2*)(g_dq + (size_t)i * NB))[lane] = o;
        ulonglong2* dmu = (ulonglong2*)(g_dmu + (size_t)i * 3 * NB);
        o.x = m0a; o.y = m0b; dmu[lane]      = o;
        o.x = m1a; o.y = m1b; dmu[32 + lane] = o;
        o.x = m2a; o.y = m2b; dmu[64 + lane] = o;
    }
}

// ---------------- per-atom update (f32x2 packed atom pairs) ------------------
__global__ void __launch_bounds__(128) k_atoms_update(
        const float* __restrict__ mixW,
        const float* __restrict__ c1W, const float* __restrict__ c1b,
        const float* __restrict__ c2W, const float* __restrict__ c2b,
        int it, int last, float* __restrict__ mu_out) {
    __shared__ __align__(16) float mus[NB][3][PU];     // [k][d][a]
    __shared__ __align__(16) float ctxs[2 * NB][PU];   // [k][a]
    __shared__ __align__(16) float hs[NB][PU];         // [k][a]
    int t  = threadIdx.x;
    int a0 = blockIdx.x * TU;

    float qreg[TU];
    #pragma unroll
    for (int a = 0; a < TU; a++) {
        size_t g = (size_t)(a0 + a);
        qreg[a] = g_q[g * NB + t] + g_dq[g * NB + t];
        ctxs[t][a] = qreg[a];
        #pragma unroll
        for (int d = 0; d < 3; d++)
            mus[t][d][a] = g_mu[g * 3 * NB + d * NB + t] + g_dmu[g * 3 * NB + d * NB + t];
    }
    __syncthreads();

    const float* MW = mixW + (size_t)it * NB * 2 * NB;
    u64 v2[TU / 2][3], w2[TU / 2][3];
    #pragma unroll
    for (int p = 0; p < TU / 2; p++)
        #pragma unroll
        for (int d = 0; d < 3; d++) { v2[p][d] = 0; w2[p][d] = 0; }
    for (int k = 0; k < NB; k++) {
        float wv = MW[k * 256 + t];
        float ww = MW[k * 256 + NB + t];
        u64 wvp = pk2(wv, wv), wwp = pk2(ww, ww);
        #pragma unroll
        for (int d = 0; d < 3; d++) {
            const ulonglong2* m2 = (const ulonglong2*)&mus[k][d][0];
            ulonglong2 ua = m2[0];
            ulonglong2 ub = m2[1];
            v2[0][d] = fma2v(ua.x, wvp, v2[0][d]);
            v2[1][d] = fma2v(ua.y, wvp, v2[1][d]);
            v2[2][d] = fma2v(ub.x, wvp, v2[2][d]);
            v2[3][d] = fma2v(ub.y, wvp, v2[3][d]);
            w2[0][d] = fma2v(ua.x, wwp, w2[0][d]);
            w2[1][d] = fma2v(ua.y, wwp, w2[1][d]);
            w2[2][d] = fma2v(ub.x, wwp, w2[2][d]);
            w2[3][d] = fma2v(ub.y, wwp, w2[3][d]);
        }
    }
    float v[TU][3], w[TU][3];
    #pragma unroll
    for (int p = 0; p < TU / 2; p++)
        #pragma unroll
        for (int d = 0; d < 3; d++) {
            float2 fv = upk2(v2[p][d]);
            float2 fw = upk2(w2[p][d]);
            v[2 * p][d] = fv.x; v[2 * p + 1][d] = fv.y;
            w[2 * p][d] = fw.x; w[2 * p + 1][d] = fw.y;
        }
    float s[TU];
    #pragma unroll
    for (int a = 0; a < TU; a++) {
        float n2 = v[a][0]*v[a][0] + v[a][1]*v[a][1] + v[a][2]*v[a][2];
        float vn = sqrtf(n2 + EPSV);
        s[a] = v[a][0]*w[a][0] + v[a][1]*w[a][1] + v[a][2]*w[a][2];
        ctxs[NB + t][a] = vn;
    }
    __syncthreads();

    const float* W1 = c1W + (size_t)it * 2 * NB * NB;
    float b1 = c1b[it * NB + t];
    u64 acc[TU / 2];
    u64 b1p = pk2(b1, b1);
    #pragma unroll
    for (int p = 0; p < TU / 2; p++) acc[p] = b1p;
    for (int k = 0; k < 2 * NB; k++) {
        float ww1 = W1[k * NB + t];
        u64 wp = pk2(ww1, ww1);
        const ulonglong2* c2p = (const ulonglong2*)&ctxs[k][0];
        ulonglong2 ca = c2p[0], cb = c2p[1];
        acc[0] = fma2v(ca.x, wp, acc[0]);
        acc[1] = fma2v(ca.y, wp, acc[1]);
        acc[2] = fma2v(cb.x, wp, acc[2]);
        acc[3] = fma2v(cb.y, wp, acc[3]);
    }
    #pragma unroll
    for (int p = 0; p < TU / 2; p++) {
        float2 f = upk2(acc[p]);
        hs[t][2 * p]     = silu_f(f.x);
        hs[t][2 * p + 1] = silu_f(f.y);
    }
    __syncthreads();

    const float* W2 = c2W + (size_t)it * NB * 3 * NB;
    float b20 = c2b[it * 3 * NB + t];
    float b21 = c2b[it * 3 * NB + NB + t];
    float b22 = c2b[it * 3 * NB + 2 * NB + t];
    u64 aq2[TU / 2], am2[TU / 2], aqm2[TU / 2];
    u64 b20p = pk2(b20, b20), b21p = pk2(b21, b21), b22p = pk2(b22, b22);
    #pragma unroll
    for (int p = 0; p < TU / 2; p++) { aq2[p] = b20p; am2[p] = b21p; aqm2[p] = b22p; }
    for (int k = 0; k < NB; k++) {
        float w0 = W2[k * 384 + t];
        float w1 = W2[k * 384 + NB + t];
        float w2w = W2[k * 384 + 2 * NB + t];
        u64 w0p = pk2(w0, w0), w1p = pk2(w1, w1), w2p = pk2(w2w, w2w);
        const ulonglong2* h2 = (const ulonglong2*)&hs[k][0];
        ulonglong2 ha = h2[0], hb = h2[1];
        aq2[0]  = fma2v(ha.x, w0p, aq2[0]);
        aq2[1]  = fma2v(ha.y, w0p, aq2[1]);
        aq2[2]  = fma2v(hb.x, w0p, aq2[2]);
        aq2[3]  = fma2v(hb.y, w0p, aq2[3]);
        am2[0]  = fma2v(ha.x, w1p, am2[0]);
        am2[1]  = fma2v(ha.y, w1p, am2[1]);
        am2[2]  = fma2v(hb.x, w1p, am2[2]);
        am2[3]  = fma2v(hb.y, w1p, am2[3]);
        aqm2[0] = fma2v(ha.x, w2p, aqm2[0]);
        aqm2[1] = fma2v(ha.y, w2p, aqm2[1]);
        aqm2[2] = fma2v(hb.x, w2p, aqm2[2]);
        aqm2[3] = fma2v(hb.y, w2p, aqm2[3]);
    }
    float aq[TU], am[TU], aqm[TU];
    #pragma unroll
    for (int p = 0; p < TU / 2; p++) {
        float2 f0 = upk2(aq2[p]);
        float2 f1 = upk2(am2[p]);
        float2 f2 = upk2(aqm2[p]);
        aq[2 * p] = f0.x;  aq[2 * p + 1] = f0.y;
        am[2 * p] = f1.x;  am[2 * p + 1] = f1.y;
        aqm[2 * p] = f2.x; aqm[2 * p + 1] = f2.y;
    }
    #pragma unroll
    for (int a = 0; a < TU; a++) {
        size_t g = (size_t)(a0 + a);
        g_q[g * NB + t] = qreg[a] + aq[a] + aqm[a] * s[a];
        #pragma unroll
        for (int d = 0; d < 3; d++) {
            float val = mus[t][d][a] + am[a] * w[a][d];
            g_mu[g * 3 * NB + d * NB + t] = val;
            if (last) mu_out[g * 3 * NB + d * NB + t] = val;
        }
    }
}

// ---------------- output head ----------------
__global__ void __launch_bounds__(128) k_head(
        const float* __restrict__ o1W, const float* __restrict__ o1b,
        const float* __restrict__ o2W, const float* __restrict__ o2b,
        const float* __restrict__ o3W, const float* __restrict__ o3b,
        const int* __restrict__ idx_m, float* __restrict__ y) {
    __shared__ float qs[TH][NB];
    __shared__ float h1[TH][NB];
    __shared__ float h2[TH][NB];
    int t  = threadIdx.x;
    int a0 = blockIdx.x * TH;
    #pragma unroll
    for (int a = 0; a < TH; a++) qs[a][t] = g_q[(size_t)(a0 + a) * NB + t];
    __syncthreads();

    float acc[TH];
    float b = o1b[t];
    #pragma unroll
    for (int a = 0; a < TH; a++) acc[a] = b;
    for (int k = 0; k < NB; k++) {
        float w = o1W[k * NB + t];
        #pragma unroll
        for (int a = 0; a < TH; a++) acc[a] += qs[a][k] * w;
    }
    #pragma unroll
    for (int a = 0; a < TH; a++) h1[a][t] = silu_f(acc[a]);
    __syncthreads();

    b = o2b[t];
    #pragma unroll
    for (int a = 0; a < TH; a++) acc[a] = b;
    for (int k = 0; k < NB; k++) {
        float w = o2W[k * NB + t];
        #pragma unroll
        for (int a = 0; a < TH; a++) acc[a] += h1[a][k] * w;
    }
    #pragma unroll
    for (int a = 0; a < TH; a++) h2[a][t] = silu_f(acc[a]);
    __syncthreads();

    if (t < TH) {
        float sum = o3b[0];
        for (int k = 0; k < NB; k++) sum += h2[t][k] * o3W[k];
        atomicAdd(&y[idx_m[a0 + t]], sum);
    }
}

// ---------------- launch ----------------
extern "C" void kernel_launch(void* const* d_in, const int* in_sizes, int n_in,
                              void* d_out, int out_size) {
    const float* positions = (const float*)d_in[0];
    const float* emb  = (const float*)d_in[1];
    const float* fW   = (const float*)d_in[2];
    const float* fb   = (const float*)d_in[3];
    const float* ic1W = (const float*)d_in[4];
    const float* ic1b = (const float*)d_in[5];
    const float* ic2W = (const float*)d_in[6];
    const float* ic2b = (const float*)d_in[7];
    const float* mixW = (const float*)d_in[8];
    const float* c1W  = (const float*)d_in[9];
    const float* c1b  = (const float*)d_in[10];
    const float* c2W  = (const float*)d_in[11];
    const float* c2b  = (const float*)d_in[12];
    const float* o1W  = (const float*)d_in[13];
    const float* o1b  = (const float*)d_in[14];
    const float* o2W  = (const float*)d_in[15];
    const float* o2b  = (const float*)d_in[16];
    const float* o3W  = (const float*)d_in[17];
    const float* o3b  = (const float*)d_in[18];
    const int* z      = (const int*)d_in[19];
    const int* idx_i  = (const int*)d_in[20];
    const int* idx_j  = (const int*)d_in[21];
    const int* idx_m  = (const int*)d_in[22];
    float* out = (float*)d_out;   // layout: y[64], then mu[10000*3*128]

    k_init_edges<<<(N_EDGES + 255) / 256, 256>>>(positions, idx_i, idx_j);
    k_makeB<<<(32 * NF + 255) / 256, 256>>>(fW, fb);
    k_zero_cnt<<<(N_ATOMS + 255) / 256, 256>>>();
    k_hist<<<(N_EDGES + 255) / 256, 256>>>(idx_i);
    k_scan<<<1, 1024>>>();
    k_fill<<<(N_EDGES + 255) / 256, 256>>>(idx_i, idx_j);
    {
        dim3 fg((N_EDGES + FEB - 1) / FEB, NF / 128);
        k_filters_wmma<<<fg, 128>>>();
    }
    k_init_atoms<<<N_ATOMS, 128>>>(emb, z, out);

    for (int it = 0; it < NI; it++) {
        k_atoms_x<<<N_ATOMS / TX, 128>>>(ic1W, ic1b, ic2W, ic2b, it);
        if (it == 0) k_gather<0><<<N_ATOMS / 4, 256>>>(it);
        else         k_gather<1><<<N_ATOMS / 4, 256>>>(it);
        k_atoms_update<<<N_ATOMS / TU, 128>>>(mixW, c1W, c1b, c2W, c2b,
                                              it, it == NI - 1, out + BATCH);
    }

    k_head<<<N_ATOMS / TH, 128>>>(o1W, o1b, o2W, o2b, o3W, o3b, idx_m, out);
}

// round 17
// speedup vs baseline: 2.8100x; 1.0020x over previous
#include <cuda_runtime.h>
#include <cuda_fp16.h>
#include <mma.h>
#include <math.h>

using namespace nvcuda;

#define N_ATOMS 10000
#define N_EDGES 150000
#define NB 128
#define NI 3
#define NF (NI * 3 * NB)     // 1152 filter cols
#define N_RBF 20
#define CUTOFF 5.0f
#define EPSV 1e-8f
#define BATCH 64
#define FEB 64               // edges per wmma filter block
#define BSP 136              // padded B smem row stride (halfs)
#define TX 16                // atoms per block, k_atoms_x (one wmma m-tile)
#define PX 20                // padded row for TX
#define TU 8                 // atoms per block, k_atoms_update
#define PU 12                // padded row for TU
#define TH 8                 // atoms per block, k_head

typedef unsigned long long u64;

// ---------------- device scratch (static, no allocation) ----------------
__device__ float  g_q   [N_ATOMS * NB];
__device__ __align__(16) float g_mu [N_ATOMS * 3 * NB];
__device__ __align__(16) float g_x  [N_ATOMS * 3 * NB];
__device__ float  g_dq  [N_ATOMS * NB];
__device__ float  g_dmu [N_ATOMS * 3 * NB];
__device__ __align__(16) __half g_phif_h[(size_t)N_EDGES * 32];  // A: [e][32] fp16
__device__ __align__(16) __half g_B[32 * NF];                    // B: [32][1152] fp16
__device__ __align__(16) __half g_w2h[NI * NB * 3 * NB];         // ic2W fp16 mirror
__device__ __align__(16) float  g_bias2x[NI * 16 * 384];         // bias rows for wmma C init
__device__ float4 g_dir4[N_EDGES];
__device__ __align__(16) __half g_filt[(size_t)N_EDGES * NF]; // filters fp16, CSR-slot order
// CSR by destination atom (idx_i)
__device__ int    g_cnt [N_ATOMS];
__device__ int    g_ofs [N_ATOMS + 1];
__device__ int    g_cur [N_ATOMS];
__device__ int    g_slot[N_EDGES];
__device__ int    g_pj  [N_EDGES];
__device__ float4 g_pdir[N_EDGES];

// ---------------- packed f32x2 helpers (FFMA2 path, sm_103a) ----------------
__device__ __forceinline__ u64 pk2(float lo, float hi) {
    u64 r; asm("mov.b64 %0, {%1, %2};" : "=l"(r) : "f"(lo), "f"(hi)); return r;
}
__device__ __forceinline__ float2 upk2(u64 v) {
    float2 f; asm("mov.b64 {%0, %1}, %2;" : "=f"(f.x), "=f"(f.y) : "l"(v)); return f;
}
__device__ __forceinline__ u64 fma2v(u64 a, u64 b, u64 c) {
    u64 d; asm("fma.rn.f32x2 %0, %1, %2, %3;" : "=l"(d) : "l"(a), "l"(b), "l"(c)); return d;
}
__device__ __forceinline__ u64 mul2v(u64 a, u64 b) {
    u64 d; asm("mul.rn.f32x2 %0, %1, %2;" : "=l"(d) : "l"(a), "l"(b)); return d;
}
// half2 (as uint) -> packed f32x2
__device__ __forceinline__ u64 h2f2(unsigned h) {
    float2 f = __half22float2(*reinterpret_cast<__half2*>(&h));
    return pk2(f.x, f.y);
}

__device__ __forceinline__ float silu_f(float v) {
    return v / (1.0f + expf(-v));
}

// ---------------- edge geometry precompute (A rows in fp16) -----------------
__global__ void k_init_edges(const float* __restrict__ pos,
                             const int* __restrict__ idx_i,
                             const int* __restrict__ idx_j) {
    int e = blockIdx.x * blockDim.x + threadIdx.x;
    if (e >= N_EDGES) return;
    int i = idx_i[e], j = idx_j[e];
    float rx = pos[j * 3 + 0] - pos[i * 3 + 0];
    float ry = pos[j * 3 + 1] - pos[i * 3 + 1];
    float rz = pos[j * 3 + 2] - pos[i * 3 + 2];
    float d  = sqrtf(rx * rx + ry * ry + rz * rz);
    float inv = 1.0f / d;
    g_dir4[e] = make_float4(rx * inv, ry * inv, rz * inv, 0.0f);
    float fc = (d < CUTOFF) ? 0.5f * (cosf(d * (float)M_PI / CUTOFF) + 1.0f) : 0.0f;
    const float width = CUTOFF / (float)(N_RBF - 1);
    const float coeff = -0.5f / (width * width);
    __half* row = g_phif_h + (size_t)e * 32;
    #pragma unroll
    for (int r = 0; r < N_RBF; r++) {
        float dd = d - (float)r * width;
        row[r] = __float2half_rn(expf(coeff * dd * dd) * fc);
    }
    row[20] = __float2half_rn(fc);
    #pragma unroll
    for (int r = 21; r < 32; r++) row[r] = __float2half_rn(0.0f);
}

// ---------------- B matrix build: [32 x 1152] fp16 --------------------------
__global__ void k_makeB(const float* __restrict__ fW,
                        const float* __restrict__ fb) {
    int i = blockIdx.x * blockDim.x + threadIdx.x;
    if (i >= 32 * NF) return;
    int r = i / NF, c = i % NF;
    float v = (r < N_RBF) ? fW[r * NF + c] : ((r == 20) ? fb[c] : 0.0f);
    g_B[i] = __float2half_rn(v);
}

// ---------------- ic2W fp16 mirror + bias blocks ----------------------------
__global__ void k_cvtW2(const float* __restrict__ ic2W,
                        const float* __restrict__ ic2b) {
    int i = blockIdx.x * blockDim.x + threadIdx.x;
    if (i < NI * NB * 3 * NB)
        g_w2h[i] = __float2half_rn(ic2W[i]);
    if (i < NI * 16 * 384) {
        int it = i / (16 * 384);
        int c  = i % 384;
        g_bias2x[i] = ic2b[it * 384 + c];
    }
}

// ---------------- CSR build ----------------
__global__ void k_zero_cnt() {
    int a = blockIdx.x * blockDim.x + threadIdx.x;
    if (a < N_ATOMS) g_cnt[a] = 0;
}
__global__ void k_hist(const int* __restrict__ idx_i) {
    int e = blockIdx.x * blockDim.x + threadIdx.x;
    if (e < N_EDGES) atomicAdd(&g_cnt[idx_i[e]], 1);
}
__global__ void __launch_bounds__(1024) k_scan() {
    __shared__ int partial[1024];
    int t = threadIdx.x;
    int base = t * 10;
    int local[10];
    int s = 0;
    #pragma unroll
    for (int k = 0; k < 10; k++) {
        int idx = base + k;
        int c = (idx < N_ATOMS) ? g_cnt[idx] : 0;
        local[k] = s;
        s += c;
    }
    partial[t] = s;
    __syncthreads();
    for (int off = 1; off < 1024; off <<= 1) {
        int v = partial[t];
        int u = (t >= off) ? partial[t - off] : 0;
        __syncthreads();
        partial[t] = v + u;
        __syncthreads();
    }
    int pre = (t > 0) ? partial[t - 1] : 0;
    #pragma unroll
    for (int k = 0; k < 10; k++) {
        int idx = base + k;
        if (idx < N_ATOMS) {
            int o = pre + local[k];
            g_ofs[idx] = o;
            g_cur[idx] = o;
        }
    }
    if (t == 1023) g_ofs[N_ATOMS] = partial[1023];
}
__global__ void k_fill(const int* __restrict__ idx_i,
                       const int* __restrict__ idx_j) {
    int e = blockIdx.x * blockDim.x + threadIdx.x;
    if (e < N_EDGES) {
        int pos = atomicAdd(&g_cur[idx_i[e]], 1);
        g_slot[e] = pos;
        g_pj[pos] = idx_j[e];
        g_pdir[pos] = g_dir4[e];
    }
}

// ---------------- filter GEMM on tensor cores (wmma fp16 -> fp32) -----------
__global__ void __launch_bounds__(128) k_filters_wmma() {
    __shared__ __align__(16) __half As[FEB][32];
    __shared__ __align__(16) __half Bs[32][BSP];
    __shared__ __align__(16) float  Cs[FEB][128];
    __shared__ int slots[FEB];
    int e0 = blockIdx.x * FEB;
    int t  = threadIdx.x;
    int c0 = blockIdx.y * 128;

    for (int idx = t; idx < FEB * 4; idx += 128) {
        int row = idx >> 2, part = idx & 3;
        int e = e0 + row;
        uint4 v = make_uint4(0, 0, 0, 0);
        if (e < N_EDGES)
            v = ((const uint4*)(g_phif_h + (size_t)e * 32))[part];
        ((uint4*)&As[row][0])[part] = v;
    }
    for (int idx = t; idx < 32 * 16; idx += 128) {
        int r = idx >> 4, pc = (idx & 15) * 8;
        *(uint4*)&Bs[r][pc] = *(const uint4*)&g_B[r * NF + c0 + pc];
    }
    for (int idx = t; idx < FEB; idx += 128) {
        int e = e0 + idx;
        slots[idx] = (e < N_EDGES) ? g_slot[e] : -1;
    }
    __syncthreads();

    int warp = t >> 5;
    wmma::fragment<wmma::accumulator, 16, 16, 16, float> cf[8];
    #pragma unroll
    for (int n = 0; n < 8; n++) wmma::fill_fragment(cf[n], 0.0f);
    #pragma unroll
    for (int k = 0; k < 2; k++) {
        wmma::fragment<wmma::matrix_a, 16, 16, 16, __half, wmma::row_major> af;
        wmma::load_matrix_sync(af, &As[warp * 16][k * 16], 32);
        #pragma unroll
        for (int n = 0; n < 8; n++) {
            wmma::fragment<wmma::matrix_b, 16, 16, 16, __half, wmma::row_major> bf;
            wmma::load_matrix_sync(bf, &Bs[k * 16][n * 16], BSP);
            wmma::mma_sync(cf[n], af, bf, cf[n]);
        }
    }
    #pragma unroll
    for (int n = 0; n < 8; n++)
        wmma::store_matrix_sync(&Cs[warp * 16][n * 16], cf[n], 128, wmma::mem_row_major);
    __syncthreads();

    #pragma unroll 4
    for (int r = 0; r < FEB; r++) {
        int s = slots[r];
        if (s >= 0)
            g_filt[(size_t)s * NF + c0 + t] = __float2half_rn(Cs[r][t]);
    }
}

// ---------------- atom init ----------------
__global__ void k_init_atoms(const float* __restrict__ emb,
                             const int* __restrict__ z,
                             float* __restrict__ y_out) {
    int a = blockIdx.x;
    int t = threadIdx.x;
    g_q[a * NB + t] = emb[z[a] * NB + t];
    #pragma unroll
    for (int d = 0; d < 3; d++)
        g_mu[a * 3 * NB + d * NB + t] = 0.0f;
    if (a == 0 && t < BATCH) y_out[t] = 0.0f;
}

// ---------------- per-atom input MLP: GEMM1 FFMA2 + GEMM2 wmma ---------------
__global__ void __launch_bounds__(128) k_atoms_x(
        const float* __restrict__ ic1W, const float* __restrict__ ic1b,
        int it) {
    __shared__ __align__(16) float  qs[NB][PX];
    __shared__ __align__(16) __half Hs[16][136];   // silu(h) fp16, [atom][k]
    int t  = threadIdx.x;
    int a0 = blockIdx.x * TX;

    #pragma unroll
    for (int a = 0; a < TX; a++)
        qs[t][a] = g_q[(size_t)(a0 + a) * NB + t];
    __syncthreads();

    const float* W1 = ic1W + (size_t)it * NB * NB;
    float b1 = ic1b[it * NB + t];
    u64 acc[TX / 2];
    u64 b1p = pk2(b1, b1);
    #pragma unroll
    for (int p = 0; p < TX / 2; p++) acc[p] = b1p;
    for (int k = 0; k < NB; k++) {
        float w = W1[k * NB + t];
        u64 wp = pk2(w, w);
        const ulonglong2* q2 = (const ulonglong2*)&qs[k][0];
        #pragma unroll
        for (int p4 = 0; p4 < TX / 4; p4++) {
            ulonglong2 u = q2[p4];
            acc[2 * p4]     = fma2v(u.x, wp, acc[2 * p4]);
            acc[2 * p4 + 1] = fma2v(u.y, wp, acc[2 * p4 + 1]);
        }
    }
    #pragma unroll
    for (int p = 0; p < TX / 2; p++) {
        float2 f = upk2(acc[p]);
        Hs[2 * p][t]     = __float2half_rn(silu_f(f.x));
        Hs[2 * p + 1][t] = __float2half_rn(silu_f(f.y));
    }
    __syncthreads();

    // GEMM2 on tensor cores: X[16x384] = Hs[16x128] @ W2h[128x384] + bias
    int warp = t >> 5;
    const __half* W2h = g_w2h + (size_t)it * NB * 384;
    const float*  Bx  = g_bias2x + (size_t)it * 16 * 384;
    float* xout = g_x + (size_t)a0 * 384;

    wmma::fragment<wmma::accumulator, 16, 16, 16, float> cf[6];
    #pragma unroll
    for (int i = 0; i < 6; i++) {
        int n = warp * 6 + i;
        wmma::load_matrix_sync(cf[i], Bx + n * 16, 384, wmma::mem_row_major);
    }
    #pragma unroll
    for (int k = 0; k < 8; k++) {
        wmma::fragment<wmma::matrix_a, 16, 16, 16, __half, wmma::row_major> af;
        wmma::load_matrix_sync(af, &Hs[0][k * 16], 136);
        #pragma unroll
        for (int i = 0; i < 6; i++) {
            int n = warp * 6 + i;
            wmma::fragment<wmma::matrix_b, 16, 16, 16, __half, wmma::row_major> bf;
            wmma::load_matrix_sync(bf, W2h + (k * 16) * 384 + n * 16, 384);
            wmma::mma_sync(cf[i], af, bf, cf[i]);
        }
    }
    #pragma unroll
    for (int i = 0; i < 6; i++) {
        int n = warp * 6 + i;
        wmma::store_matrix_sync(xout + n * 16, cf[i], 384, wmma::mem_row_major);
    }
}

// ---------------- edge gather: TWO warps per destination atom ----------------
template <int HAS_MU>
__global__ void __launch_bounds__(256) k_gather(int it) {
    __shared__ __align__(16) float sm[4][4 * NB];
    int warp = threadIdx.x >> 5;
    int lane = threadIdx.x & 31;
    int a    = warp >> 1;
    int half = warp & 1;
    int i = blockIdx.x * 4 + a;
    int beg0 = g_ofs[i], end0 = g_ofs[i + 1];
    int len  = end0 - beg0;
    int mid  = beg0 + ((len + 1) >> 1);
    int beg  = half ? mid : beg0;
    int end  = half ? end0 : mid;

    u64 mq0 = 0, mq1 = 0;
    u64 m0a = 0, m0b = 0, m1a = 0, m1b = 0, m2a = 0, m2b = 0;

    const int itofs = it * 384;
    int j = 0; float4 d4 = make_float4(0,0,0,0);
    if (beg < end) { j = __ldg(g_pj + beg); d4 = g_pdir[beg]; }

    for (int k = beg; k < end; k++) {
        int jn = 0; float4 dn = d4;
        if (k + 1 < end) { jn = __ldg(g_pj + k + 1); dn = g_pdir[k + 1]; }

        const uint2* fe = (const uint2*)(g_filt + (size_t)k * NF + itofs);
        uint2 f0 = fe[lane];
        uint2 f1 = fe[32 + lane];
        uint2 f2 = fe[64 + lane];
        const ulonglong2* xr = (const ulonglong2*)(g_x + (size_t)j * 384);
        ulonglong2 x0 = xr[lane];
        ulonglong2 x1 = xr[32 + lane];
        ulonglong2 x2 = xr[64 + lane];
        ulonglong2 u0, u1, u2;
        if (HAS_MU) {
            const ulonglong2* mr = (const ulonglong2*)(g_mu + (size_t)j * 384);
            u0 = mr[lane];
            u1 = mr[32 + lane];
            u2 = mr[64 + lane];
        }

        u64 w0x = h2f2(f0.x), w0y = h2f2(f0.y);
        u64 w1x = h2f2(f1.x), w1y = h2f2(f1.y);
        u64 w2x = h2f2(f2.x), w2y = h2f2(f2.y);

        mq0 = fma2v(w0x, x0.x, mq0);
        mq1 = fma2v(w0y, x0.y, mq1);
        u64 vR0 = mul2v(w1x, x1.x), vR1 = mul2v(w1y, x1.y);
        u64 vM0 = mul2v(w2x, x2.x), vM1 = mul2v(w2y, x2.y);
        u64 dxp = pk2(d4.x, d4.x), dyp = pk2(d4.y, d4.y), dzp = pk2(d4.z, d4.z);
        if (HAS_MU) {
            m0a = fma2v(vR0, dxp, fma2v(vM0, u0.x, m0a));
            m0b = fma2v(vR1, dxp, fma2v(vM1, u0.y, m0b));
            m1a = fma2v(vR0, dyp, fma2v(vM0, u1.x, m1a));
            m1b = fma2v(vR1, dyp, fma2v(vM1, u1.y, m1b));
            m2a = fma2v(vR0, dzp, fma2v(vM0, u2.x, m2a));
            m2b = fma2v(vR1, dzp, fma2v(vM1, u2.y, m2b));
        } else {
            m0a = fma2v(vR0, dxp, m0a);
            m0b = fma2v(vR1, dxp, m0b);
            m1a = fma2v(vR0, dyp, m1a);
            m1b = fma2v(vR1, dyp, m1b);
            m2a = fma2v(vR0, dzp, m2a);
            m2b = fma2v(vR1, dzp, m2b);
        }
        j = jn; d4 = dn;
    }

    ulonglong2* sb = (ulonglong2*)&sm[a][0];
    if (half == 1) {
        ulonglong2 t;
        t.x = mq0; t.y = mq1; sb[lane]      = t;
        t.x = m0a; t.y = m0b; sb[32 + lane] = t;
        t.x = m1a; t.y = m1b; sb[64 + lane] = t;
        t.x = m2a; t.y = m2b; sb[96 + lane] = t;
    }
    __syncthreads();

    if (half == 0) {
        const u64 one = pk2(1.0f, 1.0f);
        ulonglong2 p;
        p = sb[lane];      mq0 = fma2v(p.x, one, mq0); mq1 = fma2v(p.y, one, mq1);
        p = sb[32 + lane]; m0a = fma2v(p.x, one, m0a); m0b = fma2v(p.y, one, m0b);
        p = sb[64 + lane]; m1a = fma2v(p.x, one, m1a); m1b = fma2v(p.y, one, m1b);
        p = sb[96 + lane]; m2a = fma2v(p.x, one, m2a); m2b = fma2v(p.y, one, m2b);

        ulonglong2 o;
        o.x = mq0; o.y = mq1;
        ((ulonglong2*)(g_dq + (size_t)i * NB))[lane] = o;
        ulonglong2* dmu = (ulonglong2*)(g_dmu + (size_t)i * 3 * NB);
        o.x = m0a; o.y = m0b; dmu[lane]      = o;
        o.x = m1a; o.y = m1b; dmu[32 + lane] = o;
        o.x = m2a; o.y = m2b; dmu[64 + lane] = o;
    }
}

// ---------------- per-atom update (f32x2 packed atom pairs) ------------------
__global__ void __launch_bounds__(128) k_atoms_update(
        const float* __restrict__ mixW,
        const float* __restrict__ c1W, const float* __restrict__ c1b,
        const float* __restrict__ c2W, const float* __restrict__ c2b,
        int it, int last, float* __restrict__ mu_out) {
    __shared__ __align__(16) float mus[NB][3][PU];
    __shared__ __align__(16) float ctxs[2 * NB][PU];
    __shared__ __align__(16) float hs[NB][PU];
    int t  = threadIdx.x;
    int a0 = blockIdx.x * TU;

    float qreg[TU];
    #pragma unroll
    for (int a = 0; a < TU; a++) {
        size_t g = (size_t)(a0 + a);
        qreg[a] = g_q[g * NB + t] + g_dq[g * NB + t];
        ctxs[t][a] = qreg[a];
        #pragma unroll
        for (int d = 0; d < 3; d++)
            mus[t][d][a] = g_mu[g * 3 * NB + d * NB + t] + g_dmu[g * 3 * NB + d * NB + t];
    }
    __syncthreads();

    const float* MW = mixW + (size_t)it * NB * 2 * NB;
    u64 v2[TU / 2][3], w2[TU / 2][3];
    #pragma unroll
    for (int p = 0; p < TU / 2; p++)
        #pragma unroll
        for (int d = 0; d < 3; d++) { v2[p][d] = 0; w2[p][d] = 0; }
    for (int k = 0; k < NB; k++) {
        float wv = MW[k * 256 + t];
        float ww = MW[k * 256 + NB + t];
        u64 wvp = pk2(wv, wv), wwp = pk2(ww, ww);
        #pragma unroll
        for (int d = 0; d < 3; d++) {
            const ulonglong2* m2 = (const ulonglong2*)&mus[k][d][0];
            ulonglong2 ua = m2[0];
            ulonglong2 ub = m2[1];
            v2[0][d] = fma2v(ua.x, wvp, v2[0][d]);
            v2[1][d] = fma2v(ua.y, wvp, v2[1][d]);
            v2[2][d] = fma2v(ub.x, wvp, v2[2][d]);
            v2[3][d] = fma2v(ub.y, wvp, v2[3][d]);
            w2[0][d] = fma2v(ua.x, wwp, w2[0][d]);
            w2[1][d] = fma2v(ua.y, wwp, w2[1][d]);
            w2[2][d] = fma2v(ub.x, wwp, w2[2][d]);
            w2[3][d] = fma2v(ub.y, wwp, w2[3][d]);
        }
    }
    float v[TU][3], w[TU][3];
    #pragma unroll
    for (int p = 0; p < TU / 2; p++)
        #pragma unroll
        for (int d = 0; d < 3; d++) {
            float2 fv = upk2(v2[p][d]);
            float2 fw = upk2(w2[p][d]);
            v[2 * p][d] = fv.x; v[2 * p + 1][d] = fv.y;
            w[2 * p][d] = fw.x; w[2 * p + 1][d] = fw.y;
        }
    float s[TU];
    #pragma unroll
    for (int a = 0; a < TU; a++) {
        float n2 = v[a][0]*v[a][0] + v[a][1]*v[a][1] + v[a][2]*v[a][2];
        float vn = sqrtf(n2 + EPSV);
        s[a] = v[a][0]*w[a][0] + v[a][1]*w[a][1] + v[a][2]*w[a][2];
        ctxs[NB + t][a] = vn;
    }
    __syncthreads();

    const float* W1 = c1W + (size_t)it * 2 * NB * NB;
    float b1 = c1b[it * NB + t];
    u64 acc[TU / 2];
    u64 b1p = pk2(b1, b1);
    #pragma unroll
    for (int p = 0; p < TU / 2; p++) acc[p] = b1p;
    for (int k = 0; k < 2 * NB; k++) {
        float ww1 = W1[k * NB + t];
        u64 wp = pk2(ww1, ww1);
        const ulonglong2* c2p = (const ulonglong2*)&ctxs[k][0];
        ulonglong2 ca = c2p[0], cb = c2p[1];
        acc[0] = fma2v(ca.x, wp, acc[0]);
        acc[1] = fma2v(ca.y, wp, acc[1]);
        acc[2] = fma2v(cb.x, wp, acc[2]);
        acc[3] = fma2v(cb.y, wp, acc[3]);
    }
    #pragma unroll
    for (int p = 0; p < TU / 2; p++) {
        float2 f = upk2(acc[p]);
        hs[t][2 * p]     = silu_f(f.x);
        hs[t][2 * p + 1] = silu_f(f.y);
    }
    __syncthreads();

    const float* W2 = c2W + (size_t)it * NB * 3 * NB;
    float b20 = c2b[it * 3 * NB + t];
    float b21 = c2b[it * 3 * NB + NB + t];
    float b22 = c2b[it * 3 * NB + 2 * NB + t];
    u64 aq2[TU / 2], am2[TU / 2], aqm2[TU / 2];
    u64 b20p = pk2(b20, b20), b21p = pk2(b21, b21), b22p = pk2(b22, b22);
    #pragma unroll
    for (int p = 0; p < TU / 2; p++) { aq2[p] = b20p; am2[p] = b21p; aqm2[p] = b22p; }
    for (int k = 0; k < NB; k++) {
        float w0 = W2[k * 384 + t];
        float w1 = W2[k * 384 + NB + t];
        float w2w = W2[k * 384 + 2 * NB + t];
        u64 w0p = pk2(w0, w0), w1p = pk2(w1, w1), w2p = pk2(w2w, w2w);
        const ulonglong2* h2 = (const ulonglong2*)&hs[k][0];
        ulonglong2 ha = h2[0], hb = h2[1];
        aq2[0]  = fma2v(ha.x, w0p, aq2[0]);
        aq2[1]  = fma2v(ha.y, w0p, aq2[1]);
        aq2[2]  = fma2v(hb.x, w0p, aq2[2]);
        aq2[3]  = fma2v(hb.y, w0p, aq2[3]);
        am2[0]  = fma2v(ha.x, w1p, am2[0]);
        am2[1]  = fma2v(ha.y, w1p, am2[1]);
        am2[2]  = fma2v(hb.x, w1p, am2[2]);
        am2[3]  = fma2v(hb.y, w1p, am2[3]);
        aqm2[0] = fma2v(ha.x, w2p, aqm2[0]);
        aqm2[1] = fma2v(ha.y, w2p, aqm2[1]);
        aqm2[2] = fma2v(hb.x, w2p, aqm2[2]);
        aqm2[3] = fma2v(hb.y, w2p, aqm2[3]);
    }
    float aq[TU], am[TU], aqm[TU];
    #pragma unroll
    for (int p = 0; p < TU / 2; p++) {
        float2 f0 = upk2(aq2[p]);
        float2 f1 = upk2(am2[p]);
        float2 f2 = upk2(aqm2[p]);
        aq[2 * p] = f0.x;  aq[2 * p + 1] = f0.y;
        am[2 * p] = f1.x;  am[2 * p + 1] = f1.y;
        aqm[2 * p] = f2.x; aqm[2 * p + 1] = f2.y;
    }
    #pragma unroll
    for (int a = 0; a < TU; a++) {
        size_t g = (size_t)(a0 + a);
        g_q[g * NB + t] = qreg[a] + aq[a] + aqm[a] * s[a];
        #pragma unroll
        for (int d = 0; d < 3; d++) {
            float val = mus[t][d][a] + am[a] * w[a][d];
            g_mu[g * 3 * NB + d * NB + t] = val;
            if (last) mu_out[g * 3 * NB + d * NB + t] = val;
        }
    }
}

// ---------------- output head ----------------
__global__ void __launch_bounds__(128) k_head(
        const float* __restrict__ o1W, const float* __restrict__ o1b,
        const float* __restrict__ o2W, const float* __restrict__ o2b,
        const float* __restrict__ o3W, const float* __restrict__ o3b,
        const int* __restrict__ idx_m, float* __restrict__ y) {
    __shared__ float qs[TH][NB];
    __shared__ float h1[TH][NB];
    __shared__ float h2[TH][NB];
    int t  = threadIdx.x;
    int a0 = blockIdx.x * TH;
    #pragma unroll
    for (int a = 0; a < TH; a++) qs[a][t] = g_q[(size_t)(a0 + a) * NB + t];
    __syncthreads();

    float acc[TH];
    float b = o1b[t];
    #pragma unroll
    for (int a = 0; a < TH; a++) acc[a] = b;
    for (int k = 0; k < NB; k++) {
        float w = o1W[k * NB + t];
        #pragma unroll
        for (int a = 0; a < TH; a++) acc[a] += qs[a][k] * w;
    }
    #pragma unroll
    for (int a = 0; a < TH; a++) h1[a][t] = silu_f(acc[a]);
    __syncthreads();

    b = o2b[t];
    #pragma unroll
    for (int a = 0; a < TH; a++) acc[a] = b;
    for (int k = 0; k < NB; k++) {
        float w = o2W[k * NB + t];
        #pragma unroll
        for (int a = 0; a < TH; a++) acc[a] += h1[a][k] * w;
    }
    #pragma unroll
    for (int a = 0; a < TH; a++) h2[a][t] = silu_f(acc[a]);
    __syncthreads();

    if (t < TH) {
        float sum = o3b[0];
        for (int k = 0; k < NB; k++) sum += h2[t][k] * o3W[k];
        atomicAdd(&y[idx_m[a0 + t]], sum);
    }
}

// ---------------- launch ----------------
extern "C" void kernel_launch(void* const* d_in, const int* in_sizes, int n_in,
                              void* d_out, int out_size) {
    const float* positions = (const float*)d_in[0];
    const float* emb  = (const float*)d_in[1];
    const float* fW   = (const float*)d_in[2];
    const float* fb   = (const float*)d_in[3];
    const float* ic1W = (const float*)d_in[4];
    const float* ic1b = (const float*)d_in[5];
    const float* ic2W = (const float*)d_in[6];
    const float* ic2b = (const float*)d_in[7];
    const float* mixW = (const float*)d_in[8];
    const float* c1W  = (const float*)d_in[9];
    const float* c1b  = (const float*)d_in[10];
    const float* c2W  = (const float*)d_in[11];
    const float* c2b  = (const float*)d_in[12];
    const float* o1W  = (const float*)d_in[13];
    const float* o1b  = (const float*)d_in[14];
    const float* o2W  = (const float*)d_in[15];
    const float* o2b  = (const float*)d_in[16];
    const float* o3W  = (const float*)d_in[17];
    const float* o3b  = (const float*)d_in[18];
    const int* z      = (const int*)d_in[19];
    const int* idx_i  = (const int*)d_in[20];
    const int* idx_j  = (const int*)d_in[21];
    const int* idx_m  = (const int*)d_in[22];
    float* out = (float*)d_out;   // layout: y[64], then mu[10000*3*128]

    k_init_edges<<<(N_EDGES + 255) / 256, 256>>>(positions, idx_i, idx_j);
    k_makeB<<<(32 * NF + 255) / 256, 256>>>(fW, fb);
    k_cvtW2<<<(NI * NB * 3 * NB + 255) / 256, 256>>>(ic2W, ic2b);
    k_zero_cnt<<<(N_ATOMS + 255) / 256, 256>>>();
    k_hist<<<(N_EDGES + 255) / 256, 256>>>(idx_i);
    k_scan<<<1, 1024>>>();
    k_fill<<<(N_EDGES + 255) / 256, 256>>>(idx_i, idx_j);
    {
        dim3 fg((N_EDGES + FEB - 1) / FEB, NF / 128);
        k_filters_wmma<<<fg, 128>>>();
    }
    k_init_atoms<<<N_ATOMS, 128>>>(emb, z, out);

    for (int it = 0; it < NI; it++) {
        k_atoms_x<<<N_ATOMS / TX, 128>>>(ic1W, ic1b, it);
        if (it == 0) k_gather<0><<<N_ATOMS / 4, 256>>>(it);
        else         k_gather<1><<<N_ATOMS / 4, 256>>>(it);
        k_atoms_update<<<N_ATOMS / TU, 128>>>(mixW, c1W, c1b, c2W, c2b,
                                              it, it == NI - 1, out + BATCH);
    }

    k_head<<<N_ATOMS / TH, 128>>>(o1W, o1b, o2W, o2b, o3W, o3b, idx_m, out);
}